// round 7
// baseline (speedup 1.0000x reference)
#include <cuda_runtime.h>
#include <cuda_bf16.h>
#include <math.h>
#include <stdint.h>

#define D_MODEL 2048
#define N_HEADS 32
#define N_KV    8
#define HD      64
#define SEQ     2048
#define BATCH   2
#define NTOK    (BATCH*SEQ)      /* 4096 */
#define QDIM    (N_HEADS*HD)     /* 2048 */
#define KVDIM   (N_KV*HD)        /* 512  */
#define QKVDIM  (QDIM + 2*KVDIM) /* 3072 */
#define ROPE_BASE 500000.0
#define SCALE_L2E 0.1803368801111204f   /* 0.125 * log2(e) */

/* ---------------- static device scratch ---------------- */
__device__ float g_cos[SEQ*(HD/2)];
__device__ float g_sin[SEQ*(HD/2)];

__device__ __nv_bfloat16 g_xhi [NTOK*D_MODEL];
__device__ __nv_bfloat16 g_xlo [NTOK*D_MODEL];
__device__ __nv_bfloat16 g_wbhi[QKVDIM*D_MODEL];   /* packed Wq|Wk|Wv, [N,K] */
__device__ __nv_bfloat16 g_wblo[QKVDIM*D_MODEL];
__device__ __nv_bfloat16 g_wohi[D_MODEL*QDIM];
__device__ __nv_bfloat16 g_wolo[D_MODEL*QDIM];
__device__ __nv_bfloat16 g_aohi[NTOK*QDIM];
__device__ __nv_bfloat16 g_aolo[NTOK*QDIM];

/* attention operands (written by QKV-GEMM epilogue, rope applied) */
__device__ __nv_bfloat16 g_qhi[NTOK*QDIM];
__device__ __nv_bfloat16 g_qlo[NTOK*QDIM];
__device__ __nv_bfloat16 g_khi[NTOK*KVDIM];
__device__ __nv_bfloat16 g_klo[NTOK*KVDIM];
__device__ __nv_bfloat16 g_vhi[NTOK*KVDIM];
__device__ __nv_bfloat16 g_vlo[NTOK*KVDIM];

/* ---------------- PTX helpers ---------------- */
__device__ __forceinline__ uint32_t smem_u32(const void* p) {
    uint32_t a;
    asm("{ .reg .u64 t; cvta.to.shared.u64 t, %1; cvt.u32.u64 %0, t; }" : "=r"(a) : "l"(p));
    return a;
}
__device__ __forceinline__ void cp16(uint32_t saddr, const void* g) {
    asm volatile("cp.async.cg.shared.global [%0], [%1], 16;" :: "r"(saddr), "l"(g));
}
__device__ __forceinline__ void cp_commit() { asm volatile("cp.async.commit_group;" ::: "memory"); }
__device__ __forceinline__ void cp_wait0()  { asm volatile("cp.async.wait_group 0;"  ::: "memory"); }
__device__ __forceinline__ void cp_wait1()  { asm volatile("cp.async.wait_group 1;"  ::: "memory"); }

__device__ __forceinline__ void ldmx4(uint32_t* r, uint32_t addr) {
    asm volatile("ldmatrix.sync.aligned.m8n8.x4.shared.b16 {%0,%1,%2,%3}, [%4];"
                 : "=r"(r[0]), "=r"(r[1]), "=r"(r[2]), "=r"(r[3]) : "r"(addr));
}
__device__ __forceinline__ void ldmx4t(uint32_t* r, uint32_t addr) {
    asm volatile("ldmatrix.sync.aligned.m8n8.x4.trans.shared.b16 {%0,%1,%2,%3}, [%4];"
                 : "=r"(r[0]), "=r"(r[1]), "=r"(r[2]), "=r"(r[3]) : "r"(addr));
}
__device__ __forceinline__ void mma16816(float* d, const uint32_t* a, const uint32_t* b) {
    asm volatile(
        "mma.sync.aligned.m16n8k16.row.col.f32.bf16.bf16.f32 "
        "{%0,%1,%2,%3}, {%4,%5,%6,%7}, {%8,%9}, {%0,%1,%2,%3};"
        : "+f"(d[0]), "+f"(d[1]), "+f"(d[2]), "+f"(d[3])
        : "r"(a[0]), "r"(a[1]), "r"(a[2]), "r"(a[3]), "r"(b[0]), "r"(b[1]));
}
__device__ __forceinline__ float ex2(float x) {
    float y; asm("ex2.approx.f32 %0, %1;" : "=f"(y) : "f"(x)); return y;
}
__device__ __forceinline__ uint32_t pk(float a, float b) {
    __nv_bfloat162 t = __float22bfloat162_rn(make_float2(a, b));
    return *(uint32_t*)&t;
}
__device__ __forceinline__ float b2f(float v) {
    return __bfloat162float(__float2bfloat16(v));
}

/* ---------------- split kernels ---------------- */
__global__ __launch_bounds__(256) void split_kernel(const float* __restrict__ src,
                                                    __nv_bfloat16* __restrict__ hi,
                                                    __nv_bfloat16* __restrict__ lo,
                                                    int n4) {
    int i = blockIdx.x * blockDim.x + threadIdx.x;
    if (i >= n4) return;
    float4 v = ((const float4*)src)[i];
    __nv_bfloat16 h[4], l[4];
    float vv[4] = {v.x, v.y, v.z, v.w};
#pragma unroll
    for (int j = 0; j < 4; j++) {
        h[j] = __float2bfloat16(vv[j]);
        l[j] = __float2bfloat16(vv[j] - __bfloat162float(h[j]));
    }
    ((uint2*)hi)[i] = *(uint2*)h;
    ((uint2*)lo)[i] = *(uint2*)l;
}

__global__ __launch_bounds__(256) void tsplit_kernel(const float* __restrict__ W,
                                                     __nv_bfloat16* __restrict__ hi,
                                                     __nv_bfloat16* __restrict__ lo,
                                                     int K, int N, int nOff) {
    __shared__ float t[32][33];
    int n0 = blockIdx.x * 32, k0 = blockIdx.y * 32;
    int tx = threadIdx.x, ty = threadIdx.y;
#pragma unroll
    for (int i = 0; i < 32; i += 8)
        t[ty + i][tx] = W[(size_t)(k0 + ty + i) * N + n0 + tx];
    __syncthreads();
#pragma unroll
    for (int i = 0; i < 32; i += 8) {
        float v = t[tx][ty + i];
        __nv_bfloat16 h = __float2bfloat16(v);
        float r = v - __bfloat162float(h);
        size_t o = (size_t)(nOff + n0 + ty + i) * K + k0 + tx;
        hi[o] = h;
        lo[o] = __float2bfloat16(r);
    }
}

/* ---------------- RoPE table ---------------- */
__global__ void rope_table_kernel() {
    int i = blockIdx.x * blockDim.x + threadIdx.x;
    if (i >= SEQ * (HD/2)) return;
    int t = i / (HD/2);
    int j = i % (HD/2);
    double inv = pow((double)ROPE_BASE, -(double)(2*j) / (double)HD);
    double ang = (double)t * inv;
    g_cos[i] = (float)cos(ang);
    g_sin[i] = (float)sin(ang);
}

/* ---------------- shared GEMM mainloop macro ---------------- */
#define TILE_B   10240            /* 128 rows * 80 B */
#define STAGE_B  (4*TILE_B)
#define GEMM_SMEM (2*STAGE_B)

#define GEMM_MAIN(Ahi, Alo, Bhi, Blo, Kdim)                                       \
    extern __shared__ char smem[];                                                \
    uint32_t sb = smem_u32(smem);                                                 \
    int tid = threadIdx.x, lane = tid & 31, wid = tid >> 5;                       \
    int wm = wid & 1, wn = wid >> 1;                                              \
    int bm = blockIdx.y * 128, bn = blockIdx.x * 128;                             \
    int lr = tid >> 2;                                                            \
    int lc = tid & 3;                                                             \
    const __nv_bfloat16* gA1 = (Ahi) + (size_t)(bm + lr) * (Kdim) + lc * 8;       \
    const __nv_bfloat16* gA2 = (Alo) + (size_t)(bm + lr) * (Kdim) + lc * 8;       \
    const __nv_bfloat16* gB1 = (Bhi) + (size_t)(bn + lr) * (Kdim) + lc * 8;       \
    const __nv_bfloat16* gB2 = (Blo) + (size_t)(bn + lr) * (Kdim) + lc * 8;       \
    size_t rstep = (size_t)32 * (Kdim);                                           \
    uint32_t soff = lr * 80 + lc * 16;                                            \
    float acc[4][8][4];                                                           \
    _Pragma("unroll")                                                             \
    for (int i = 0; i < 4; i++)                                                   \
        _Pragma("unroll")                                                         \
        for (int j = 0; j < 8; j++)                                               \
            _Pragma("unroll")                                                     \
            for (int t = 0; t < 4; t++) acc[i][j][t] = 0.f;                       \
    int nkt = (Kdim) >> 5;                                                        \
    {                                                                             \
        _Pragma("unroll")                                                         \
        for (int r = 0; r < 4; r++) {                                             \
            uint32_t so = sb + soff + r * 2560;                                   \
            cp16(so,              gA1 + r * rstep);                               \
            cp16(so + TILE_B,     gA2 + r * rstep);                               \
            cp16(so + 2*TILE_B,   gB1 + r * rstep);                               \
            cp16(so + 3*TILE_B,   gB2 + r * rstep);                               \
        }                                                                         \
    }                                                                             \
    cp_commit(); cp_wait0(); __syncthreads();                                     \
    uint32_t aBase = 2 * ((uint32_t)(wm * 64 + (lane & 15)) * 40 + ((lane >> 4) << 3)); \
    uint32_t bBase = 2 * ((uint32_t)(wn * 64 + (lane & 7) + ((lane >> 4) << 3)) * 40 + (lane & 8)); \
    for (int kt = 0; kt < nkt; kt++) {                                            \
        if (kt + 1 < nkt) {                                                       \
            int koff = (kt + 1) << 5;                                             \
            uint32_t st = sb + ((kt + 1) & 1) * STAGE_B;                          \
            _Pragma("unroll")                                                     \
            for (int r = 0; r < 4; r++) {                                         \
                uint32_t so = st + soff + r * 2560;                               \
                cp16(so,              gA1 + r * rstep + koff);                    \
                cp16(so + TILE_B,     gA2 + r * rstep + koff);                    \
                cp16(so + 2*TILE_B,   gB1 + r * rstep + koff);                    \
                cp16(so + 3*TILE_B,   gB2 + r * rstep + koff);                    \
            }                                                                     \
        }                                                                         \
        cp_commit();                                                              \
        uint32_t base = sb + (kt & 1) * STAGE_B;                                  \
        _Pragma("unroll")                                                         \
        for (int kb = 0; kb < 32; kb += 16) {                                     \
            uint32_t ah[4][4], al[4][4], bh[4][4], bl[4][4];                      \
            _Pragma("unroll")                                                     \
            for (int mt = 0; mt < 4; mt++) {                                      \
                uint32_t o = aBase + 2 * (mt * 16 * 40 + kb);                     \
                ldmx4(ah[mt], base + o);                                          \
                ldmx4(al[mt], base + TILE_B + o);                                 \
            }                                                                     \
            _Pragma("unroll")                                                     \
            for (int g = 0; g < 4; g++) {                                         \
                uint32_t o = bBase + 2 * (g * 16 * 40 + kb);                      \
                ldmx4(bh[g], base + 2*TILE_B + o);                                \
                ldmx4(bl[g], base + 3*TILE_B + o);                                \
            }                                                                     \
            _Pragma("unroll")                                                     \
            for (int mt = 0; mt < 4; mt++)                                        \
                _Pragma("unroll")                                                 \
                for (int nt = 0; nt < 8; nt++) {                                  \
                    const uint32_t* fh = &bh[nt >> 1][(nt & 1) * 2];              \
                    const uint32_t* fl = &bl[nt >> 1][(nt & 1) * 2];              \
                    mma16816(acc[mt][nt], ah[mt], fh);                            \
                    mma16816(acc[mt][nt], ah[mt], fl);                            \
                    mma16816(acc[mt][nt], al[mt], fh);                            \
                }                                                                 \
        }                                                                         \
        cp_wait0();                                                               \
        __syncthreads();                                                          \
    }

/* ---------------- generic GEMM (Wo projection) ---------------- */
__global__ __launch_bounds__(128, 2)
void hmma_gemm(const __nv_bfloat16* __restrict__ Ahi, const __nv_bfloat16* __restrict__ Alo,
               const __nv_bfloat16* __restrict__ Bhi, const __nv_bfloat16* __restrict__ Blo,
               float* __restrict__ C, int N, int K) {
    GEMM_MAIN(Ahi, Alo, Bhi, Blo, K)
    int er = lane >> 2, ec = (lane & 3) * 2;
#pragma unroll
    for (int mt = 0; mt < 4; mt++)
#pragma unroll
        for (int nt = 0; nt < 8; nt++) {
            int row = bm + wm * 64 + mt * 16 + er;
            int col = bn + wn * 64 + nt * 8 + ec;
            *(float2*)(C + (size_t)row * N + col) =
                make_float2(acc[mt][nt][0], acc[mt][nt][1]);
            *(float2*)(C + (size_t)(row + 8) * N + col) =
                make_float2(acc[mt][nt][2], acc[mt][nt][3]);
        }
}

/* ---------------- QKV GEMM with fused RoPE + hi/lo split epilogue ------- */
__global__ __launch_bounds__(128, 2)
void hmma_gemm_qkv() {
    GEMM_MAIN(g_xhi, g_xlo, g_wbhi, g_wblo, D_MODEL)
    int er = lane >> 2, ec = (lane & 3) * 2;
    int head = (bn + wn * 64) >> 6;           /* 0..47 */
    if (head < N_HEADS + N_KV) {
        /* q or k: rope in registers */
        bool isq = head < N_HEADS;
        float scl = isq ? SCALE_L2E : 1.0f;
        __nv_bfloat16* hi = isq ? g_qhi : g_khi;
        __nv_bfloat16* lo = isq ? g_qlo : g_klo;
        int dim  = isq ? QDIM : KVDIM;
        int hcol = (isq ? head : head - N_HEADS) * HD;
#pragma unroll
        for (int mt = 0; mt < 4; mt++) {
            int row = bm + wm * 64 + mt * 16 + er;
#pragma unroll
            for (int hr = 0; hr < 2; hr++) {
                int tok = row + hr * 8;
                int s = tok & (SEQ - 1);
                int e0 = hr * 2;
#pragma unroll
                for (int nt = 0; nt < 4; nt++) {
                    int j = nt * 8 + ec;
                    float c0 = g_cos[s*32 + j],   c1 = g_cos[s*32 + j + 1];
                    float n0 = g_sin[s*32 + j],   n1 = g_sin[s*32 + j + 1];
                    float x1a = acc[mt][nt][e0],     x1b = acc[mt][nt][e0+1];
                    float x2a = acc[mt][nt+4][e0],   x2b = acc[mt][nt+4][e0+1];
                    float r1a = (x1a*c0 - x2a*n0) * scl, r1b = (x1b*c1 - x2b*n1) * scl;
                    float r2a = (x2a*c0 + x1a*n0) * scl, r2b = (x2b*c1 + x1b*n1) * scl;
                    size_t o1 = (size_t)tok * dim + hcol + j;
                    *(uint32_t*)(hi + o1)      = pk(r1a, r1b);
                    *(uint32_t*)(lo + o1)      = pk(r1a - b2f(r1a), r1b - b2f(r1b));
                    *(uint32_t*)(hi + o1 + 32) = pk(r2a, r2b);
                    *(uint32_t*)(lo + o1 + 32) = pk(r2a - b2f(r2a), r2b - b2f(r2b));
                }
            }
        }
    } else {
        /* v: plain split */
        int hcol = (head - N_HEADS - N_KV) * HD;
#pragma unroll
        for (int mt = 0; mt < 4; mt++) {
            int row = bm + wm * 64 + mt * 16 + er;
#pragma unroll
            for (int nt = 0; nt < 8; nt++) {
                int jj = nt * 8 + ec;
                size_t o0 = (size_t)row * KVDIM + hcol + jj;
                size_t o1 = (size_t)(row + 8) * KVDIM + hcol + jj;
                float v0 = acc[mt][nt][0], v1 = acc[mt][nt][1];
                float v2 = acc[mt][nt][2], v3 = acc[mt][nt][3];
                *(uint32_t*)(g_vhi + o0) = pk(v0, v1);
                *(uint32_t*)(g_vlo + o0) = pk(v0 - b2f(v0), v1 - b2f(v1));
                *(uint32_t*)(g_vhi + o1) = pk(v2, v3);
                *(uint32_t*)(g_vlo + o1) = pk(v2 - b2f(v2), v3 - b2f(v3));
            }
        }
    }
}

/* ---------------- HMMA flash attention, 128-row q blocks ----------------
 * 8 warps, each owns 16 q rows x full 64 kv cols. Double-buffered KV.
 */
#define AST 36864           /* stage: KH 9216 | KL | VH | VL */
#define ATTN_SMEM (2*AST)

__global__ __launch_bounds__(256)
void attn_kernel(const int* __restrict__ cu) {
    extern __shared__ char smem[];
    uint32_t sb = smem_u32(smem);
    int qb = blockIdx.x, h = blockIdx.y, b = blockIdx.z;
    int kvh = h >> 2;
    int tid = threadIdx.x, lane = tid & 31, wq = tid >> 5;
    int mq = lane >> 3, r = lane & 7;

    int b0 = min(max(cu[b*4+0], 0), SEQ);
    int b1 = min(max(cu[b*4+1], 0), SEQ);
    int b2 = min(max(cu[b*4+2], 0), SEQ);
    int b3 = min(max(cu[b*4+3], 0), SEQ);

    int p0 = qb * 128;
    int s_start = 0;
    if (b0 <= p0) s_start = b0;
    if (b1 <= p0) s_start = max(s_start, b1);
    if (b2 <= p0) s_start = max(s_start, b2);
    if (b3 <= p0) s_start = max(s_start, b3);
    int kb0 = s_start >> 6;
    int kbmax = 2*qb + 1;

    /* ---- stage Q (128 x 64 hi/lo) into stage0, extract fragments ---- */
#pragma unroll
    for (int i = 0; i < 8; i++) {
        int idx = tid + i * 256;          /* 0..2047 */
        int arr = idx >> 10;
        int rem = idx & 1023;
        int row = rem >> 3, c = rem & 7;
        cp16(sb + arr*18432 + row*144 + c*16,
             (arr ? g_qlo : g_qhi) + (size_t)(b*SEQ + p0 + row) * QDIM + h*HD + c*8);
    }
    cp_commit(); cp_wait0(); __syncthreads();

    uint32_t qh[4][4], ql[4][4];
#pragma unroll
    for (int kt = 0; kt < 4; kt++) {
        uint32_t off = (uint32_t)(wq*16 + (lane & 15)) * 144 + (kt*16 + ((lane >> 4) << 3)) * 2;
        ldmx4(qh[kt], sb + off);
        ldmx4(ql[kt], sb + 18432 + off);
    }
    __syncthreads();   /* all warps done reading Q smem */

    int qp0 = p0 + wq*16 + (lane >> 2);
    int qp1 = qp0 + 8;
    int qsg0 = (b0 <= qp0) + (b1 <= qp0) + (b2 <= qp0) + (b3 <= qp0);
    int qsg1 = (b0 <= qp1) + (b1 <= qp1) + (b2 <= qp1) + (b3 <= qp1);

    float m0 = -INFINITY, m1 = -INFINITY, l0 = 0.f, l1 = 0.f;
    float o[8][4];
#pragma unroll
    for (int nd = 0; nd < 8; nd++)
#pragma unroll
        for (int j = 0; j < 4; j++) o[nd][j] = 0.f;

    int colb = (lane & 3) * 2;

#define LOADKV(stb, kb_)                                                          \
    do {                                                                          \
        _Pragma("unroll")                                                         \
        for (int i_ = 0; i_ < 8; i_++) {                                          \
            int idx_ = tid + i_ * 256;                                            \
            int arr_ = idx_ >> 9;                                                 \
            int rem_ = idx_ & 511;                                                \
            int row_ = rem_ >> 3, c_ = rem_ & 7;                                  \
            const __nv_bfloat16* src_ = (arr_ == 0) ? g_khi : (arr_ == 1) ? g_klo \
                                      : (arr_ == 2) ? g_vhi : g_vlo;              \
            cp16((stb) + arr_*9216 + row_*144 + c_*16,                            \
                 src_ + (size_t)(b*SEQ + (kb_)*64 + row_) * KVDIM + kvh*HD + c_*8);\
        }                                                                         \
    } while (0)

    LOADKV(sb + (kb0 & 1) * AST, kb0);
    cp_commit();

    for (int kb = kb0; kb <= kbmax; kb++) {
        if (kb < kbmax) {
            LOADKV(sb + ((kb + 1) & 1) * AST, kb + 1);
            cp_commit();
            cp_wait1();
        } else {
            cp_wait0();
        }
        __syncthreads();
        uint32_t st = sb + (kb & 1) * AST;

        /* ---- scores S = Q K^T ---- */
        float s[8][4];
#pragma unroll
        for (int nt = 0; nt < 8; nt++)
#pragma unroll
            for (int j = 0; j < 4; j++) s[nt][j] = 0.f;

#pragma unroll
        for (int kt = 0; kt < 4; kt++) {
            uint32_t khf[4][4], klf[4][4];
#pragma unroll
            for (int np = 0; np < 4; np++) {
                uint32_t off = (uint32_t)(np*16 + ((mq & 2) ? 8 : 0) + r) * 144
                             + (kt*16 + ((mq & 1) ? 8 : 0)) * 2;
                ldmx4(khf[np], st + off);
                ldmx4(klf[np], st + 9216 + off);
            }
#pragma unroll
            for (int nt = 0; nt < 8; nt++) {
                const uint32_t* fh = &khf[nt >> 1][(nt & 1) * 2];
                const uint32_t* fl = &klf[nt >> 1][(nt & 1) * 2];
                mma16816(s[nt], qh[kt], fh);
                mma16816(s[nt], qh[kt], fl);
                mma16816(s[nt], ql[kt], fh);
            }
        }

        /* ---- mask ---- */
#pragma unroll
        for (int nt = 0; nt < 8; nt++)
#pragma unroll
            for (int e = 0; e < 2; e++) {
                int kp = kb*64 + nt*8 + colb + e;
                int sk = (b0 <= kp) + (b1 <= kp) + (b2 <= kp) + (b3 <= kp);
                if (kp > qp0 || sk != qsg0) s[nt][e]     = -INFINITY;
                if (kp > qp1 || sk != qsg1) s[nt][2 + e] = -INFINITY;
            }

        /* ---- online softmax (base-2) ---- */
        float rm0 = -INFINITY, rm1 = -INFINITY;
#pragma unroll
        for (int nt = 0; nt < 8; nt++) {
            rm0 = fmaxf(rm0, fmaxf(s[nt][0], s[nt][1]));
            rm1 = fmaxf(rm1, fmaxf(s[nt][2], s[nt][3]));
        }
        rm0 = fmaxf(rm0, __shfl_xor_sync(0xffffffffu, rm0, 1));
        rm0 = fmaxf(rm0, __shfl_xor_sync(0xffffffffu, rm0, 2));
        rm1 = fmaxf(rm1, __shfl_xor_sync(0xffffffffu, rm1, 1));
        rm1 = fmaxf(rm1, __shfl_xor_sync(0xffffffffu, rm1, 2));
        float mn0 = fmaxf(m0, rm0), mn1 = fmaxf(m1, rm1);
        bool lv0 = mn0 > -INFINITY, lv1 = mn1 > -INFINITY;
        float sc0 = lv0 ? ((m0 > -INFINITY) ? ex2(m0 - mn0) : 0.f) : 1.f;
        float sc1 = lv1 ? ((m1 > -INFINITY) ? ex2(m1 - mn1) : 0.f) : 1.f;

        float rs0 = 0.f, rs1 = 0.f;
#pragma unroll
        for (int nt = 0; nt < 8; nt++) {
#pragma unroll
            for (int e = 0; e < 2; e++) {
                float v0 = lv0 ? ex2(s[nt][e]     - mn0) : 0.f;
                float v1 = lv1 ? ex2(s[nt][2 + e] - mn1) : 0.f;
                s[nt][e] = v0;     rs0 += v0;
                s[nt][2+e] = v1;   rs1 += v1;
            }
        }
        rs0 += __shfl_xor_sync(0xffffffffu, rs0, 1);
        rs0 += __shfl_xor_sync(0xffffffffu, rs0, 2);
        rs1 += __shfl_xor_sync(0xffffffffu, rs1, 1);
        rs1 += __shfl_xor_sync(0xffffffffu, rs1, 2);
        l0 = l0 * sc0 + rs0;  m0 = mn0;
        l1 = l1 * sc1 + rs1;  m1 = mn1;
#pragma unroll
        for (int nd = 0; nd < 8; nd++) {
            o[nd][0] *= sc0; o[nd][1] *= sc0;
            o[nd][2] *= sc1; o[nd][3] *= sc1;
        }

        /* ---- O += P V ---- */
#pragma unroll
        for (int kt2 = 0; kt2 < 4; kt2++) {
            float* sA = s[2*kt2];
            float* sB = s[2*kt2 + 1];
            uint32_t pah[4] = { pk(sA[0], sA[1]), pk(sA[2], sA[3]),
                                pk(sB[0], sB[1]), pk(sB[2], sB[3]) };
            uint32_t pal[4] = { pk(sA[0]-b2f(sA[0]), sA[1]-b2f(sA[1])),
                                pk(sA[2]-b2f(sA[2]), sA[3]-b2f(sA[3])),
                                pk(sB[0]-b2f(sB[0]), sB[1]-b2f(sB[1])),
                                pk(sB[2]-b2f(sB[2]), sB[3]-b2f(sB[3])) };
#pragma unroll
            for (int ndp = 0; ndp < 4; ndp++) {
                uint32_t off = (uint32_t)(kt2*16 + ((mq & 1) ? 8 : 0) + r) * 144
                             + (ndp*16 + ((mq & 2) ? 8 : 0)) * 2;
                uint32_t vh4[4], vl4[4];
                ldmx4t(vh4, st + 18432 + off);
                ldmx4t(vl4, st + 27648 + off);
#pragma unroll
                for (int q2 = 0; q2 < 2; q2++) {
                    int nd = ndp*2 + q2;
                    mma16816(o[nd], pah, &vh4[q2*2]);
                    mma16816(o[nd], pah, &vl4[q2*2]);
                    mma16816(o[nd], pal, &vh4[q2*2]);
                }
            }
        }
        __syncthreads();   /* stage consumed before next-next overwrite */
    }
#undef LOADKV

    /* ---- epilogue: normalize, write hi/lo bf16 ---- */
    float inv0 = 1.f / l0, inv1 = 1.f / l1;
    size_t r0g = (size_t)(b*SEQ + qp0) * QDIM + h*HD;
    size_t r1g = (size_t)(b*SEQ + qp1) * QDIM + h*HD;
#pragma unroll
    for (int nd = 0; nd < 8; nd++) {
        float v0 = o[nd][0]*inv0, v1 = o[nd][1]*inv0;
        float v2 = o[nd][2]*inv1, v3 = o[nd][3]*inv1;
        *(uint32_t*)(g_aohi + r0g + nd*8 + colb) = pk(v0, v1);
        *(uint32_t*)(g_aolo + r0g + nd*8 + colb) = pk(v0 - b2f(v0), v1 - b2f(v1));
        *(uint32_t*)(g_aohi + r1g + nd*8 + colb) = pk(v2, v3);
        *(uint32_t*)(g_aolo + r1g + nd*8 + colb) = pk(v2 - b2f(v2), v3 - b2f(v3));
    }
}

/* ------------------------------------------------------------------ */
extern "C" void kernel_launch(void* const* d_in, const int* in_sizes, int n_in,
                              void* d_out, int out_size) {
    const float* x  = (const float*)d_in[0];
    const int*   cu = (const int*)  d_in[1];
    const float* Wq = (const float*)d_in[2];
    const float* Wk = (const float*)d_in[3];
    const float* Wv = (const float*)d_in[4];
    const float* Wo = (const float*)d_in[5];
    float* out = (float*)d_out;

    __nv_bfloat16 *xhi, *xlo, *wbhi, *wblo, *wohi, *wolo, *aohi, *aolo;
    cudaGetSymbolAddress((void**)&xhi, g_xhi);   cudaGetSymbolAddress((void**)&xlo, g_xlo);
    cudaGetSymbolAddress((void**)&wbhi, g_wbhi); cudaGetSymbolAddress((void**)&wblo, g_wblo);
    cudaGetSymbolAddress((void**)&wohi, g_wohi); cudaGetSymbolAddress((void**)&wolo, g_wolo);
    cudaGetSymbolAddress((void**)&aohi, g_aohi); cudaGetSymbolAddress((void**)&aolo, g_aolo);

    cudaFuncSetAttribute(attn_kernel,
                         cudaFuncAttributeMaxDynamicSharedMemorySize, ATTN_SMEM);
    cudaFuncSetAttribute(hmma_gemm,
                         cudaFuncAttributeMaxDynamicSharedMemorySize, GEMM_SMEM);
    cudaFuncSetAttribute(hmma_gemm_qkv,
                         cudaFuncAttributeMaxDynamicSharedMemorySize, GEMM_SMEM);

    /* prep */
    rope_table_kernel<<<(SEQ*(HD/2) + 255)/256, 256>>>();
    split_kernel<<<(NTOK*D_MODEL/4 + 255)/256, 256>>>(x, xhi, xlo, NTOK*D_MODEL/4);
    tsplit_kernel<<<dim3(QDIM /32, D_MODEL/32), dim3(32,8)>>>(Wq, wbhi, wblo, D_MODEL, QDIM,  0);
    tsplit_kernel<<<dim3(KVDIM/32, D_MODEL/32), dim3(32,8)>>>(Wk, wbhi, wblo, D_MODEL, KVDIM, QDIM);
    tsplit_kernel<<<dim3(KVDIM/32, D_MODEL/32), dim3(32,8)>>>(Wv, wbhi, wblo, D_MODEL, KVDIM, QDIM+KVDIM);
    tsplit_kernel<<<dim3(D_MODEL/32, QDIM/32), dim3(32,8)>>>(Wo, wohi, wolo, QDIM, D_MODEL, 0);

    /* merged QKV projection with fused rope+split epilogue */
    hmma_gemm_qkv<<<dim3(QKVDIM/128, NTOK/128), 128, GEMM_SMEM>>>();

    /* attention */
    attn_kernel<<<dim3(SEQ/128, N_HEADS, BATCH), 256, ATTN_SMEM>>>(cu);

    /* output projection */
    hmma_gemm<<<dim3(D_MODEL/128, NTOK/128), 128, GEMM_SMEM>>>(aohi, aolo, wohi, wolo, out,
                                                               D_MODEL, QDIM);
}

// round 8
// speedup vs baseline: 1.0442x; 1.0442x over previous
#include <cuda_runtime.h>
#include <cuda_bf16.h>
#include <math.h>
#include <stdint.h>

#define D_MODEL 2048
#define N_HEADS 32
#define N_KV    8
#define HD      64
#define SEQ     2048
#define BATCH   2
#define NTOK    (BATCH*SEQ)      /* 4096 */
#define QDIM    (N_HEADS*HD)     /* 2048 */
#define KVDIM   (N_KV*HD)        /* 512  */
#define QKVDIM  (QDIM + 2*KVDIM) /* 3072 */
#define ROPE_BASE 500000.0
#define SCALE_L2E 0.1803368801111204f   /* 0.125 * log2(e) */

/* ---------------- static device scratch ---------------- */
__device__ float g_cos[SEQ*(HD/2)];
__device__ float g_sin[SEQ*(HD/2)];

__device__ __nv_bfloat16 g_xhi [NTOK*D_MODEL];
__device__ __nv_bfloat16 g_xlo [NTOK*D_MODEL];
__device__ __nv_bfloat16 g_wbhi[QKVDIM*D_MODEL];   /* packed Wq|Wk|Wv, [N,K] */
__device__ __nv_bfloat16 g_wblo[QKVDIM*D_MODEL];
__device__ __nv_bfloat16 g_wohi[D_MODEL*QDIM];
__device__ __nv_bfloat16 g_wolo[D_MODEL*QDIM];
__device__ __nv_bfloat16 g_aohi[NTOK*QDIM];
__device__ __nv_bfloat16 g_aolo[NTOK*QDIM];

/* attention operands (written by QKV-GEMM epilogue, rope applied) */
__device__ __nv_bfloat16 g_qhi[NTOK*QDIM];
__device__ __nv_bfloat16 g_qlo[NTOK*QDIM];
__device__ __nv_bfloat16 g_khi[NTOK*KVDIM];
__device__ __nv_bfloat16 g_klo[NTOK*KVDIM];
__device__ __nv_bfloat16 g_vhi[NTOK*KVDIM];
__device__ __nv_bfloat16 g_vlo[NTOK*KVDIM];

/* ---------------- PTX helpers ---------------- */
__device__ __forceinline__ uint32_t smem_u32(const void* p) {
    uint32_t a;
    asm("{ .reg .u64 t; cvta.to.shared.u64 t, %1; cvt.u32.u64 %0, t; }" : "=r"(a) : "l"(p));
    return a;
}
__device__ __forceinline__ void cp16(uint32_t saddr, const void* g) {
    asm volatile("cp.async.cg.shared.global [%0], [%1], 16;" :: "r"(saddr), "l"(g));
}
__device__ __forceinline__ void cp_commit() { asm volatile("cp.async.commit_group;" ::: "memory"); }
__device__ __forceinline__ void cp_wait0()  { asm volatile("cp.async.wait_group 0;"  ::: "memory"); }

__device__ __forceinline__ void ldmx4(uint32_t* r, uint32_t addr) {
    asm volatile("ldmatrix.sync.aligned.m8n8.x4.shared.b16 {%0,%1,%2,%3}, [%4];"
                 : "=r"(r[0]), "=r"(r[1]), "=r"(r[2]), "=r"(r[3]) : "r"(addr));
}
__device__ __forceinline__ void ldmx4t(uint32_t* r, uint32_t addr) {
    asm volatile("ldmatrix.sync.aligned.m8n8.x4.trans.shared.b16 {%0,%1,%2,%3}, [%4];"
                 : "=r"(r[0]), "=r"(r[1]), "=r"(r[2]), "=r"(r[3]) : "r"(addr));
}
__device__ __forceinline__ void mma16816(float* d, const uint32_t* a, const uint32_t* b) {
    asm volatile(
        "mma.sync.aligned.m16n8k16.row.col.f32.bf16.bf16.f32 "
        "{%0,%1,%2,%3}, {%4,%5,%6,%7}, {%8,%9}, {%0,%1,%2,%3};"
        : "+f"(d[0]), "+f"(d[1]), "+f"(d[2]), "+f"(d[3])
        : "r"(a[0]), "r"(a[1]), "r"(a[2]), "r"(a[3]), "r"(b[0]), "r"(b[1]));
}
__device__ __forceinline__ float ex2(float x) {
    float y; asm("ex2.approx.f32 %0, %1;" : "=f"(y) : "f"(x)); return y;
}
__device__ __forceinline__ uint32_t pk(float a, float b) {
    __nv_bfloat162 t = __float22bfloat162_rn(make_float2(a, b));
    return *(uint32_t*)&t;
}
__device__ __forceinline__ float b2f(float v) {
    return __bfloat162float(__float2bfloat16(v));
}

/* ---------------- split kernels ---------------- */
__global__ __launch_bounds__(256) void split_kernel(const float* __restrict__ src,
                                                    __nv_bfloat16* __restrict__ hi,
                                                    __nv_bfloat16* __restrict__ lo,
                                                    int n4) {
    int i = blockIdx.x * blockDim.x + threadIdx.x;
    if (i >= n4) return;
    float4 v = ((const float4*)src)[i];
    __nv_bfloat16 h[4], l[4];
    float vv[4] = {v.x, v.y, v.z, v.w};
#pragma unroll
    for (int j = 0; j < 4; j++) {
        h[j] = __float2bfloat16(vv[j]);
        l[j] = __float2bfloat16(vv[j] - __bfloat162float(h[j]));
    }
    ((uint2*)hi)[i] = *(uint2*)h;
    ((uint2*)lo)[i] = *(uint2*)l;
}

__global__ __launch_bounds__(256) void tsplit_kernel(const float* __restrict__ W,
                                                     __nv_bfloat16* __restrict__ hi,
                                                     __nv_bfloat16* __restrict__ lo,
                                                     int K, int N, int nOff) {
    __shared__ float t[32][33];
    int n0 = blockIdx.x * 32, k0 = blockIdx.y * 32;
    int tx = threadIdx.x, ty = threadIdx.y;
#pragma unroll
    for (int i = 0; i < 32; i += 8)
        t[ty + i][tx] = W[(size_t)(k0 + ty + i) * N + n0 + tx];
    __syncthreads();
#pragma unroll
    for (int i = 0; i < 32; i += 8) {
        float v = t[tx][ty + i];
        __nv_bfloat16 h = __float2bfloat16(v);
        float r = v - __bfloat162float(h);
        size_t o = (size_t)(nOff + n0 + ty + i) * K + k0 + tx;
        hi[o] = h;
        lo[o] = __float2bfloat16(r);
    }
}

/* ---------------- RoPE table ---------------- */
__global__ void rope_table_kernel() {
    int i = blockIdx.x * blockDim.x + threadIdx.x;
    if (i >= SEQ * (HD/2)) return;
    int t = i / (HD/2);
    int j = i % (HD/2);
    double inv = pow((double)ROPE_BASE, -(double)(2*j) / (double)HD);
    double ang = (double)t * inv;
    g_cos[i] = (float)cos(ang);
    g_sin[i] = (float)sin(ang);
}

/* ---------------- shared GEMM mainloop macro ---------------- */
#define TILE_B   10240            /* 128 rows * 80 B */
#define STAGE_B  (4*TILE_B)
#define GEMM_SMEM (2*STAGE_B)

#define GEMM_MAIN(Ahi, Alo, Bhi, Blo, Kdim)                                       \
    extern __shared__ char smem[];                                                \
    uint32_t sb = smem_u32(smem);                                                 \
    int tid = threadIdx.x, lane = tid & 31, wid = tid >> 5;                       \
    int wm = wid & 1, wn = wid >> 1;                                              \
    int bm = blockIdx.y * 128, bn = blockIdx.x * 128;                             \
    int lr = tid >> 2;                                                            \
    int lc = tid & 3;                                                             \
    const __nv_bfloat16* gA1 = (Ahi) + (size_t)(bm + lr) * (Kdim) + lc * 8;       \
    const __nv_bfloat16* gA2 = (Alo) + (size_t)(bm + lr) * (Kdim) + lc * 8;       \
    const __nv_bfloat16* gB1 = (Bhi) + (size_t)(bn + lr) * (Kdim) + lc * 8;       \
    const __nv_bfloat16* gB2 = (Blo) + (size_t)(bn + lr) * (Kdim) + lc * 8;       \
    size_t rstep = (size_t)32 * (Kdim);                                           \
    uint32_t soff = lr * 80 + lc * 16;                                            \
    float acc[4][8][4];                                                           \
    _Pragma("unroll")                                                             \
    for (int i = 0; i < 4; i++)                                                   \
        _Pragma("unroll")                                                         \
        for (int j = 0; j < 8; j++)                                               \
            _Pragma("unroll")                                                     \
            for (int t = 0; t < 4; t++) acc[i][j][t] = 0.f;                       \
    int nkt = (Kdim) >> 5;                                                        \
    {                                                                             \
        _Pragma("unroll")                                                         \
        for (int r = 0; r < 4; r++) {                                             \
            uint32_t so = sb + soff + r * 2560;                                   \
            cp16(so,              gA1 + r * rstep);                               \
            cp16(so + TILE_B,     gA2 + r * rstep);                               \
            cp16(so + 2*TILE_B,   gB1 + r * rstep);                               \
            cp16(so + 3*TILE_B,   gB2 + r * rstep);                               \
        }                                                                         \
    }                                                                             \
    cp_commit(); cp_wait0(); __syncthreads();                                     \
    uint32_t aBase = 2 * ((uint32_t)(wm * 64 + (lane & 15)) * 40 + ((lane >> 4) << 3)); \
    uint32_t bBase = 2 * ((uint32_t)(wn * 64 + (lane & 7) + ((lane >> 4) << 3)) * 40 + (lane & 8)); \
    for (int kt = 0; kt < nkt; kt++) {                                            \
        if (kt + 1 < nkt) {                                                       \
            int koff = (kt + 1) << 5;                                             \
            uint32_t st = sb + ((kt + 1) & 1) * STAGE_B;                          \
            _Pragma("unroll")                                                     \
            for (int r = 0; r < 4; r++) {                                         \
                uint32_t so = st + soff + r * 2560;                               \
                cp16(so,              gA1 + r * rstep + koff);                    \
                cp16(so + TILE_B,     gA2 + r * rstep + koff);                    \
                cp16(so + 2*TILE_B,   gB1 + r * rstep + koff);                    \
                cp16(so + 3*TILE_B,   gB2 + r * rstep + koff);                    \
            }                                                                     \
        }                                                                         \
        cp_commit();                                                              \
        uint32_t base = sb + (kt & 1) * STAGE_B;                                  \
        _Pragma("unroll")                                                         \
        for (int kb = 0; kb < 32; kb += 16) {                                     \
            uint32_t ah[4][4], al[4][4], bh[4][4], bl[4][4];                      \
            _Pragma("unroll")                                                     \
            for (int mt = 0; mt < 4; mt++) {                                      \
                uint32_t o = aBase + 2 * (mt * 16 * 40 + kb);                     \
                ldmx4(ah[mt], base + o);                                          \
                ldmx4(al[mt], base + TILE_B + o);                                 \
            }                                                                     \
            _Pragma("unroll")                                                     \
            for (int g = 0; g < 4; g++) {                                         \
                uint32_t o = bBase + 2 * (g * 16 * 40 + kb);                      \
                ldmx4(bh[g], base + 2*TILE_B + o);                                \
                ldmx4(bl[g], base + 3*TILE_B + o);                                \
            }                                                                     \
            _Pragma("unroll")                                                     \
            for (int mt = 0; mt < 4; mt++)                                        \
                _Pragma("unroll")                                                 \
                for (int nt = 0; nt < 8; nt++) {                                  \
                    const uint32_t* fh = &bh[nt >> 1][(nt & 1) * 2];              \
                    const uint32_t* fl = &bl[nt >> 1][(nt & 1) * 2];              \
                    mma16816(acc[mt][nt], ah[mt], fh);                            \
                    mma16816(acc[mt][nt], ah[mt], fl);                            \
                    mma16816(acc[mt][nt], al[mt], fh);                            \
                }                                                                 \
        }                                                                         \
        cp_wait0();                                                               \
        __syncthreads();                                                          \
    }

/* ---------------- generic GEMM (Wo projection) ---------------- */
__global__ __launch_bounds__(128, 2)
void hmma_gemm(const __nv_bfloat16* __restrict__ Ahi, const __nv_bfloat16* __restrict__ Alo,
               const __nv_bfloat16* __restrict__ Bhi, const __nv_bfloat16* __restrict__ Blo,
               float* __restrict__ C, int N, int K) {
    GEMM_MAIN(Ahi, Alo, Bhi, Blo, K)
    int er = lane >> 2, ec = (lane & 3) * 2;
#pragma unroll
    for (int mt = 0; mt < 4; mt++)
#pragma unroll
        for (int nt = 0; nt < 8; nt++) {
            int row = bm + wm * 64 + mt * 16 + er;
            int col = bn + wn * 64 + nt * 8 + ec;
            *(float2*)(C + (size_t)row * N + col) =
                make_float2(acc[mt][nt][0], acc[mt][nt][1]);
            *(float2*)(C + (size_t)(row + 8) * N + col) =
                make_float2(acc[mt][nt][2], acc[mt][nt][3]);
        }
}

/* ---------------- QKV GEMM with fused RoPE + hi/lo split epilogue ------- */
__global__ __launch_bounds__(128, 2)
void hmma_gemm_qkv() {
    GEMM_MAIN(g_xhi, g_xlo, g_wbhi, g_wblo, D_MODEL)
    int er = lane >> 2, ec = (lane & 3) * 2;
    int head = (bn + wn * 64) >> 6;           /* 0..47 */
    if (head < N_HEADS + N_KV) {
        bool isq = head < N_HEADS;
        float scl = isq ? SCALE_L2E : 1.0f;
        __nv_bfloat16* hi = isq ? g_qhi : g_khi;
        __nv_bfloat16* lo = isq ? g_qlo : g_klo;
        int dim  = isq ? QDIM : KVDIM;
        int hcol = (isq ? head : head - N_HEADS) * HD;
#pragma unroll
        for (int mt = 0; mt < 4; mt++) {
            int row = bm + wm * 64 + mt * 16 + er;
#pragma unroll
            for (int hr = 0; hr < 2; hr++) {
                int tok = row + hr * 8;
                int s = tok & (SEQ - 1);
                int e0 = hr * 2;
#pragma unroll
                for (int nt = 0; nt < 4; nt++) {
                    int j = nt * 8 + ec;
                    float c0 = g_cos[s*32 + j],   c1 = g_cos[s*32 + j + 1];
                    float n0 = g_sin[s*32 + j],   n1 = g_sin[s*32 + j + 1];
                    float x1a = acc[mt][nt][e0],     x1b = acc[mt][nt][e0+1];
                    float x2a = acc[mt][nt+4][e0],   x2b = acc[mt][nt+4][e0+1];
                    float r1a = (x1a*c0 - x2a*n0) * scl, r1b = (x1b*c1 - x2b*n1) * scl;
                    float r2a = (x2a*c0 + x1a*n0) * scl, r2b = (x2b*c1 + x1b*n1) * scl;
                    size_t o1 = (size_t)tok * dim + hcol + j;
                    *(uint32_t*)(hi + o1)      = pk(r1a, r1b);
                    *(uint32_t*)(lo + o1)      = pk(r1a - b2f(r1a), r1b - b2f(r1b));
                    *(uint32_t*)(hi + o1 + 32) = pk(r2a, r2b);
                    *(uint32_t*)(lo + o1 + 32) = pk(r2a - b2f(r2a), r2b - b2f(r2b));
                }
            }
        }
    } else {
        int hcol = (head - N_HEADS - N_KV) * HD;
#pragma unroll
        for (int mt = 0; mt < 4; mt++) {
            int row = bm + wm * 64 + mt * 16 + er;
#pragma unroll
            for (int nt = 0; nt < 8; nt++) {
                int jj = nt * 8 + ec;
                size_t o0 = (size_t)row * KVDIM + hcol + jj;
                size_t o1 = (size_t)(row + 8) * KVDIM + hcol + jj;
                float v0 = acc[mt][nt][0], v1 = acc[mt][nt][1];
                float v2 = acc[mt][nt][2], v3 = acc[mt][nt][3];
                *(uint32_t*)(g_vhi + o0) = pk(v0, v1);
                *(uint32_t*)(g_vlo + o0) = pk(v0 - b2f(v0), v1 - b2f(v1));
                *(uint32_t*)(g_vhi + o1) = pk(v2, v3);
                *(uint32_t*)(g_vlo + o1) = pk(v2 - b2f(v2), v3 - b2f(v3));
            }
        }
    }
}

/* ---------------- HMMA flash attention (R6 proven version) -------------
 * q-block 64, kv-block 64. 8 warps: wq = wid&3 (16 q rows), wk = wid>>2
 * (kv half of 32). smem stage KH|KL|VH|VL, 64 rows x 144B each.
 */
#define AS_KH 0
#define AS_KL 9216
#define AS_VH 18432
#define AS_VL 27648
#define ATTN_SMEM 36864

__global__ __launch_bounds__(256)
void attn_kernel(const int* __restrict__ cu) {
    extern __shared__ char smem[];
    uint32_t sb = smem_u32(smem);
    int qb = blockIdx.x, h = blockIdx.y, b = blockIdx.z;
    int kvh = h >> 2;
    int tid = threadIdx.x, lane = tid & 31, wid = tid >> 5;
    int wq = wid & 3, wk = wid >> 2;

    int b0 = min(max(cu[b*4+0], 0), SEQ);
    int b1 = min(max(cu[b*4+1], 0), SEQ);
    int b2 = min(max(cu[b*4+2], 0), SEQ);
    int b3 = min(max(cu[b*4+3], 0), SEQ);

    int p0 = qb * 64;
    int s_start = 0;
    if (b0 <= p0) s_start = b0;
    if (b1 <= p0) s_start = max(s_start, b1);
    if (b2 <= p0) s_start = max(s_start, b2);
    if (b3 <= p0) s_start = max(s_start, b3);
    int kb0 = s_start >> 6;

#pragma unroll
    for (int i = 0; i < 4; i++) {
        int arr = i >> 1;
        int rem = tid + (i & 1) * 256;
        int row = rem >> 3, c = rem & 7;
        const __nv_bfloat16* src = arr ? g_qlo : g_qhi;
        cp16(sb + arr*9216 + row*144 + c*16,
             src + (size_t)(b*SEQ + p0 + row) * QDIM + h*HD + c*8);
    }
    cp_commit(); cp_wait0(); __syncthreads();

    uint32_t qh[4][4], ql[4][4];
#pragma unroll
    for (int kt = 0; kt < 4; kt++) {
        uint32_t off = (uint32_t)(wq*16 + (lane & 15)) * 144 + (kt*16 + ((lane >> 4) << 3)) * 2;
        ldmx4(qh[kt], sb + off);
        ldmx4(ql[kt], sb + 9216 + off);
    }

    int qp0 = p0 + wq*16 + (lane >> 2);
    int qp1 = qp0 + 8;
    int qsg0 = (b0 <= qp0) + (b1 <= qp0) + (b2 <= qp0) + (b3 <= qp0);
    int qsg1 = (b0 <= qp1) + (b1 <= qp1) + (b2 <= qp1) + (b3 <= qp1);

    float m0 = -INFINITY, m1 = -INFINITY, l0 = 0.f, l1 = 0.f;
    float o[8][4];
#pragma unroll
    for (int nd = 0; nd < 8; nd++)
#pragma unroll
        for (int j = 0; j < 4; j++) o[nd][j] = 0.f;

    int colb = wk*32 + (lane & 3)*2;

    for (int kb = kb0; kb <= qb; kb++) {
        __syncthreads();
#pragma unroll
        for (int i = 0; i < 8; i++) {
            int arr = i >> 1;
            int rem = tid + (i & 1) * 256;
            int row = rem >> 3, c = rem & 7;
            const __nv_bfloat16* src = (arr == 0) ? g_khi : (arr == 1) ? g_klo
                                     : (arr == 2) ? g_vhi : g_vlo;
            cp16(sb + arr*9216 + row*144 + c*16,
                 src + (size_t)(b*SEQ + kb*64 + row) * KVDIM + kvh*HD + c*8);
        }
        cp_commit(); cp_wait0(); __syncthreads();

        float s[4][4];
#pragma unroll
        for (int nt = 0; nt < 4; nt++)
#pragma unroll
            for (int j = 0; j < 4; j++) s[nt][j] = 0.f;

#pragma unroll
        for (int kt = 0; kt < 4; kt++) {
            uint32_t khf[2][4], klf[2][4];
#pragma unroll
            for (int np = 0; np < 2; np++) {
                int mq = lane >> 3, r = lane & 7;
                uint32_t off = (uint32_t)(wk*32 + np*16 + ((mq & 2) ? 8 : 0) + r) * 144
                             + (kt*16 + ((mq & 1) ? 8 : 0)) * 2;
                ldmx4(khf[np], sb + AS_KH + off);
                ldmx4(klf[np], sb + AS_KL + off);
            }
#pragma unroll
            for (int nt = 0; nt < 4; nt++) {
                const uint32_t* fh = &khf[nt >> 1][(nt & 1) * 2];
                const uint32_t* fl = &klf[nt >> 1][(nt & 1) * 2];
                mma16816(s[nt], qh[kt], fh);
                mma16816(s[nt], qh[kt], fl);
                mma16816(s[nt], ql[kt], fh);
            }
        }

#pragma unroll
        for (int nt = 0; nt < 4; nt++)
#pragma unroll
            for (int e = 0; e < 2; e++) {
                int kp = kb*64 + colb + nt*8 + e;
                int sk = (b0 <= kp) + (b1 <= kp) + (b2 <= kp) + (b3 <= kp);
                if (kp > qp0 || sk != qsg0) s[nt][e]     = -INFINITY;
                if (kp > qp1 || sk != qsg1) s[nt][2 + e] = -INFINITY;
            }

        float rm0 = -INFINITY, rm1 = -INFINITY;
#pragma unroll
        for (int nt = 0; nt < 4; nt++) {
            rm0 = fmaxf(rm0, fmaxf(s[nt][0], s[nt][1]));
            rm1 = fmaxf(rm1, fmaxf(s[nt][2], s[nt][3]));
        }
        rm0 = fmaxf(rm0, __shfl_xor_sync(0xffffffffu, rm0, 1));
        rm0 = fmaxf(rm0, __shfl_xor_sync(0xffffffffu, rm0, 2));
        rm1 = fmaxf(rm1, __shfl_xor_sync(0xffffffffu, rm1, 1));
        rm1 = fmaxf(rm1, __shfl_xor_sync(0xffffffffu, rm1, 2));
        float mn0 = fmaxf(m0, rm0), mn1 = fmaxf(m1, rm1);
        bool lv0 = mn0 > -INFINITY, lv1 = mn1 > -INFINITY;
        float sc0 = lv0 ? ((m0 > -INFINITY) ? ex2(m0 - mn0) : 0.f) : 1.f;
        float sc1 = lv1 ? ((m1 > -INFINITY) ? ex2(m1 - mn1) : 0.f) : 1.f;

        float p[4][4], pl[4][4];
        float rs0 = 0.f, rs1 = 0.f;
#pragma unroll
        for (int nt = 0; nt < 4; nt++) {
#pragma unroll
            for (int e = 0; e < 2; e++) {
                float v0 = lv0 ? ex2(s[nt][e]     - mn0) : 0.f;
                float v1 = lv1 ? ex2(s[nt][2 + e] - mn1) : 0.f;
                p[nt][e] = v0;     rs0 += v0;
                p[nt][2+e] = v1;   rs1 += v1;
            }
        }
        rs0 += __shfl_xor_sync(0xffffffffu, rs0, 1);
        rs0 += __shfl_xor_sync(0xffffffffu, rs0, 2);
        rs1 += __shfl_xor_sync(0xffffffffu, rs1, 1);
        rs1 += __shfl_xor_sync(0xffffffffu, rs1, 2);
        l0 = l0 * sc0 + rs0;  m0 = mn0;
        l1 = l1 * sc1 + rs1;  m1 = mn1;
#pragma unroll
        for (int nd = 0; nd < 8; nd++) {
            o[nd][0] *= sc0; o[nd][1] *= sc0;
            o[nd][2] *= sc1; o[nd][3] *= sc1;
        }

#pragma unroll
        for (int nt = 0; nt < 4; nt++)
#pragma unroll
            for (int j = 0; j < 4; j++) {
                float hv = __bfloat162float(__float2bfloat16(p[nt][j]));
                pl[nt][j] = p[nt][j] - hv;
            }

#pragma unroll
        for (int kt2 = 0; kt2 < 2; kt2++) {
            uint32_t pah[4] = { pk(p[2*kt2][0],   p[2*kt2][1]),
                                pk(p[2*kt2][2],   p[2*kt2][3]),
                                pk(p[2*kt2+1][0], p[2*kt2+1][1]),
                                pk(p[2*kt2+1][2], p[2*kt2+1][3]) };
            uint32_t pal[4] = { pk(pl[2*kt2][0],   pl[2*kt2][1]),
                                pk(pl[2*kt2][2],   pl[2*kt2][3]),
                                pk(pl[2*kt2+1][0], pl[2*kt2+1][1]),
                                pk(pl[2*kt2+1][2], pl[2*kt2+1][3]) };
#pragma unroll
            for (int ndp = 0; ndp < 4; ndp++) {
                int mq = lane >> 3, r = lane & 7;
                uint32_t off = (uint32_t)(wk*32 + kt2*16 + ((mq & 1) ? 8 : 0) + r) * 144
                             + (ndp*16 + ((mq & 2) ? 8 : 0)) * 2;
                uint32_t vh4[4], vl4[4];
                ldmx4t(vh4, sb + AS_VH + off);
                ldmx4t(vl4, sb + AS_VL + off);
#pragma unroll
                for (int q2 = 0; q2 < 2; q2++) {
                    int nd = ndp*2 + q2;
                    mma16816(o[nd], pah, &vh4[q2*2]);
                    mma16816(o[nd], pah, &vl4[q2*2]);
                    mma16816(o[nd], pal, &vh4[q2*2]);
                }
            }
        }
    }

    __syncthreads();
    float* Osm = (float*)smem;
    float* msm = (float*)(smem + 17408);
    float* lsm = (float*)(smem + 17664);
    int rl = wq*16 + (lane >> 2);
    int c2 = (lane & 3)*2;
    if (wk == 1) {
#pragma unroll
        for (int nd = 0; nd < 8; nd++) {
            *(float2*)&Osm[rl*68 + nd*8 + c2]     = make_float2(o[nd][0], o[nd][1]);
            *(float2*)&Osm[(rl+8)*68 + nd*8 + c2] = make_float2(o[nd][2], o[nd][3]);
        }
        if ((lane & 3) == 0) {
            msm[rl] = m0; msm[rl+8] = m1;
            lsm[rl] = l0; lsm[rl+8] = l1;
        }
    }
    __syncthreads();
    if (wk == 0) {
        float pm0 = msm[rl], pm1 = msm[rl+8];
        float pl0 = lsm[rl], pl1 = lsm[rl+8];
        float M0 = fmaxf(m0, pm0), M1 = fmaxf(m1, pm1);
        float sa0 = (m0  > -INFINITY) ? ex2(m0  - M0) : 0.f;
        float sb0 = (pm0 > -INFINITY) ? ex2(pm0 - M0) : 0.f;
        float sa1 = (m1  > -INFINITY) ? ex2(m1  - M1) : 0.f;
        float sb1 = (pm1 > -INFINITY) ? ex2(pm1 - M1) : 0.f;
        float inv0 = 1.f / (l0*sa0 + pl0*sb0);
        float inv1 = 1.f / (l1*sa1 + pl1*sb1);
        size_t r0g = (size_t)(b*SEQ + p0 + rl) * QDIM + h*HD;
        size_t r1g = (size_t)(b*SEQ + p0 + rl + 8) * QDIM + h*HD;
#pragma unroll
        for (int nd = 0; nd < 8; nd++) {
            float v0 = (o[nd][0]*sa0 + Osm[rl*68 + nd*8 + c2]*sb0) * inv0;
            float v1 = (o[nd][1]*sa0 + Osm[rl*68 + nd*8 + c2 + 1]*sb0) * inv0;
            float v2 = (o[nd][2]*sa1 + Osm[(rl+8)*68 + nd*8 + c2]*sb1) * inv1;
            float v3 = (o[nd][3]*sa1 + Osm[(rl+8)*68 + nd*8 + c2 + 1]*sb1) * inv1;
            *(uint32_t*)(g_aohi + r0g + nd*8 + c2) = pk(v0, v1);
            *(uint32_t*)(g_aolo + r0g + nd*8 + c2) = pk(v0 - b2f(v0), v1 - b2f(v1));
            *(uint32_t*)(g_aohi + r1g + nd*8 + c2) = pk(v2, v3);
            *(uint32_t*)(g_aolo + r1g + nd*8 + c2) = pk(v2 - b2f(v2), v3 - b2f(v3));
        }
    }
}

/* ------------------------------------------------------------------ */
extern "C" void kernel_launch(void* const* d_in, const int* in_sizes, int n_in,
                              void* d_out, int out_size) {
    const float* x  = (const float*)d_in[0];
    const int*   cu = (const int*)  d_in[1];
    const float* Wq = (const float*)d_in[2];
    const float* Wk = (const float*)d_in[3];
    const float* Wv = (const float*)d_in[4];
    const float* Wo = (const float*)d_in[5];
    float* out = (float*)d_out;

    __nv_bfloat16 *xhi, *xlo, *wbhi, *wblo, *wohi, *wolo, *aohi, *aolo;
    cudaGetSymbolAddress((void**)&xhi, g_xhi);   cudaGetSymbolAddress((void**)&xlo, g_xlo);
    cudaGetSymbolAddress((void**)&wbhi, g_wbhi); cudaGetSymbolAddress((void**)&wblo, g_wblo);
    cudaGetSymbolAddress((void**)&wohi, g_wohi); cudaGetSymbolAddress((void**)&wolo, g_wolo);
    cudaGetSymbolAddress((void**)&aohi, g_aohi); cudaGetSymbolAddress((void**)&aolo, g_aolo);

    cudaFuncSetAttribute(attn_kernel,
                         cudaFuncAttributeMaxDynamicSharedMemorySize, ATTN_SMEM);
    cudaFuncSetAttribute(hmma_gemm,
                         cudaFuncAttributeMaxDynamicSharedMemorySize, GEMM_SMEM);
    cudaFuncSetAttribute(hmma_gemm_qkv,
                         cudaFuncAttributeMaxDynamicSharedMemorySize, GEMM_SMEM);

    /* prep */
    rope_table_kernel<<<(SEQ*(HD/2) + 255)/256, 256>>>();
    split_kernel<<<(NTOK*D_MODEL/4 + 255)/256, 256>>>(x, xhi, xlo, NTOK*D_MODEL/4);
    tsplit_kernel<<<dim3(QDIM /32, D_MODEL/32), dim3(32,8)>>>(Wq, wbhi, wblo, D_MODEL, QDIM,  0);
    tsplit_kernel<<<dim3(KVDIM/32, D_MODEL/32), dim3(32,8)>>>(Wk, wbhi, wblo, D_MODEL, KVDIM, QDIM);
    tsplit_kernel<<<dim3(KVDIM/32, D_MODEL/32), dim3(32,8)>>>(Wv, wbhi, wblo, D_MODEL, KVDIM, QDIM+KVDIM);
    tsplit_kernel<<<dim3(D_MODEL/32, QDIM/32), dim3(32,8)>>>(Wo, wohi, wolo, QDIM, D_MODEL, 0);

    /* merged QKV projection with fused rope+split epilogue */
    hmma_gemm_qkv<<<dim3(QKVDIM/128, NTOK/128), 128, GEMM_SMEM>>>();

    /* attention (R6 64-row version) */
    attn_kernel<<<dim3(SEQ/64, N_HEADS, BATCH), 256, ATTN_SMEM>>>(cu);

    /* output projection */
    hmma_gemm<<<dim3(D_MODEL/128, NTOK/128), 128, GEMM_SMEM>>>(aohi, aolo, wohi, wolo, out,
                                                               D_MODEL, QDIM);
}

// round 9
// speedup vs baseline: 1.0443x; 1.0001x over previous
#include <cuda_runtime.h>
#include <cuda_bf16.h>
#include <math.h>
#include <stdint.h>

#define D_MODEL 2048
#define N_HEADS 32
#define N_KV    8
#define HD      64
#define SEQ     2048
#define BATCH   2
#define NTOK    (BATCH*SEQ)      /* 4096 */
#define QDIM    (N_HEADS*HD)     /* 2048 */
#define KVDIM   (N_KV*HD)        /* 512  */
#define QKVDIM  (QDIM + 2*KVDIM) /* 3072 */
#define ROPE_BASE 500000.0
#define SCALE_L2E 0.1803368801111204f   /* 0.125 * log2(e) */

/* ---------------- static device scratch ---------------- */
__device__ float g_cos[SEQ*(HD/2)];
__device__ float g_sin[SEQ*(HD/2)];

__device__ __nv_bfloat16 g_xhi [NTOK*D_MODEL];
__device__ __nv_bfloat16 g_xlo [NTOK*D_MODEL];
__device__ __nv_bfloat16 g_wbhi[QKVDIM*D_MODEL];   /* packed Wq|Wk|Wv, [N,K] */
__device__ __nv_bfloat16 g_wblo[QKVDIM*D_MODEL];
__device__ __nv_bfloat16 g_wohi[D_MODEL*QDIM];
__device__ __nv_bfloat16 g_wolo[D_MODEL*QDIM];
__device__ __nv_bfloat16 g_aohi[NTOK*QDIM];
__device__ __nv_bfloat16 g_aolo[NTOK*QDIM];

/* attention operands (written by QKV-GEMM epilogue, rope applied) */
__device__ __nv_bfloat16 g_qhi[NTOK*QDIM];
__device__ __nv_bfloat16 g_qlo[NTOK*QDIM];
__device__ __nv_bfloat16 g_khi[NTOK*KVDIM];
__device__ __nv_bfloat16 g_klo[NTOK*KVDIM];
__device__ __nv_bfloat16 g_vhi[NTOK*KVDIM];
__device__ __nv_bfloat16 g_vlo[NTOK*KVDIM];

/* ---------------- PTX helpers ---------------- */
__device__ __forceinline__ uint32_t smem_u32(const void* p) {
    uint32_t a;
    asm("{ .reg .u64 t; cvta.to.shared.u64 t, %1; cvt.u32.u64 %0, t; }" : "=r"(a) : "l"(p));
    return a;
}
__device__ __forceinline__ void cp16(uint32_t saddr, const void* g) {
    asm volatile("cp.async.cg.shared.global [%0], [%1], 16;" :: "r"(saddr), "l"(g));
}
__device__ __forceinline__ void cp_commit() { asm volatile("cp.async.commit_group;" ::: "memory"); }
__device__ __forceinline__ void cp_wait0()  { asm volatile("cp.async.wait_group 0;"  ::: "memory"); }

__device__ __forceinline__ void ldmx4(uint32_t* r, uint32_t addr) {
    asm volatile("ldmatrix.sync.aligned.m8n8.x4.shared.b16 {%0,%1,%2,%3}, [%4];"
                 : "=r"(r[0]), "=r"(r[1]), "=r"(r[2]), "=r"(r[3]) : "r"(addr));
}
__device__ __forceinline__ void ldmx4t(uint32_t* r, uint32_t addr) {
    asm volatile("ldmatrix.sync.aligned.m8n8.x4.trans.shared.b16 {%0,%1,%2,%3}, [%4];"
                 : "=r"(r[0]), "=r"(r[1]), "=r"(r[2]), "=r"(r[3]) : "r"(addr));
}
__device__ __forceinline__ void mma16816(float* d, const uint32_t* a, const uint32_t* b) {
    asm volatile(
        "mma.sync.aligned.m16n8k16.row.col.f32.bf16.bf16.f32 "
        "{%0,%1,%2,%3}, {%4,%5,%6,%7}, {%8,%9}, {%0,%1,%2,%3};"
        : "+f"(d[0]), "+f"(d[1]), "+f"(d[2]), "+f"(d[3])
        : "r"(a[0]), "r"(a[1]), "r"(a[2]), "r"(a[3]), "r"(b[0]), "r"(b[1]));
}
__device__ __forceinline__ float ex2(float x) {
    float y; asm("ex2.approx.f32 %0, %1;" : "=f"(y) : "f"(x)); return y;
}
__device__ __forceinline__ uint32_t pk(float a, float b) {
    __nv_bfloat162 t = __float22bfloat162_rn(make_float2(a, b));
    return *(uint32_t*)&t;
}
__device__ __forceinline__ float b2f(float v) {
    return __bfloat162float(__float2bfloat16(v));
}

/* ---------------- split kernels ---------------- */
__global__ __launch_bounds__(256) void split_kernel(const float* __restrict__ src,
                                                    __nv_bfloat16* __restrict__ hi,
                                                    __nv_bfloat16* __restrict__ lo,
                                                    int n4) {
    int i = blockIdx.x * blockDim.x + threadIdx.x;
    if (i >= n4) return;
    float4 v = ((const float4*)src)[i];
    __nv_bfloat16 h[4], l[4];
    float vv[4] = {v.x, v.y, v.z, v.w};
#pragma unroll
    for (int j = 0; j < 4; j++) {
        h[j] = __float2bfloat16(vv[j]);
        l[j] = __float2bfloat16(vv[j] - __bfloat162float(h[j]));
    }
    ((uint2*)hi)[i] = *(uint2*)h;
    ((uint2*)lo)[i] = *(uint2*)l;
}

__global__ __launch_bounds__(256) void tsplit_kernel(const float* __restrict__ W,
                                                     __nv_bfloat16* __restrict__ hi,
                                                     __nv_bfloat16* __restrict__ lo,
                                                     int K, int N, int nOff) {
    __shared__ float t[32][33];
    int n0 = blockIdx.x * 32, k0 = blockIdx.y * 32;
    int tx = threadIdx.x, ty = threadIdx.y;
#pragma unroll
    for (int i = 0; i < 32; i += 8)
        t[ty + i][tx] = W[(size_t)(k0 + ty + i) * N + n0 + tx];
    __syncthreads();
#pragma unroll
    for (int i = 0; i < 32; i += 8) {
        float v = t[tx][ty + i];
        __nv_bfloat16 h = __float2bfloat16(v);
        float r = v - __bfloat162float(h);
        size_t o = (size_t)(nOff + n0 + ty + i) * K + k0 + tx;
        hi[o] = h;
        lo[o] = __float2bfloat16(r);
    }
}

/* ---------------- RoPE table ---------------- */
__global__ void rope_table_kernel() {
    int i = blockIdx.x * blockDim.x + threadIdx.x;
    if (i >= SEQ * (HD/2)) return;
    int t = i / (HD/2);
    int j = i % (HD/2);
    double inv = pow((double)ROPE_BASE, -(double)(2*j) / (double)HD);
    double ang = (double)t * inv;
    g_cos[i] = (float)cos(ang);
    g_sin[i] = (float)sin(ang);
}

/* ---------------- shared GEMM mainloop macro ---------------- */
#define TILE_B   10240            /* 128 rows * 80 B */
#define STAGE_B  (4*TILE_B)
#define GEMM_SMEM (2*STAGE_B)

#define GEMM_MAIN(Ahi, Alo, Bhi, Blo, Kdim)                                       \
    extern __shared__ char smem[];                                                \
    uint32_t sb = smem_u32(smem);                                                 \
    int tid = threadIdx.x, lane = tid & 31, wid = tid >> 5;                       \
    int wm = wid & 1, wn = wid >> 1;                                              \
    int bm = blockIdx.y * 128, bn = blockIdx.x * 128;                             \
    int lr = tid >> 2;                                                            \
    int lc = tid & 3;                                                             \
    const __nv_bfloat16* gA1 = (Ahi) + (size_t)(bm + lr) * (Kdim) + lc * 8;       \
    const __nv_bfloat16* gA2 = (Alo) + (size_t)(bm + lr) * (Kdim) + lc * 8;       \
    const __nv_bfloat16* gB1 = (Bhi) + (size_t)(bn + lr) * (Kdim) + lc * 8;       \
    const __nv_bfloat16* gB2 = (Blo) + (size_t)(bn + lr) * (Kdim) + lc * 8;       \
    size_t rstep = (size_t)32 * (Kdim);                                           \
    uint32_t soff = lr * 80 + lc * 16;                                            \
    float acc[4][8][4];                                                           \
    _Pragma("unroll")                                                             \
    for (int i = 0; i < 4; i++)                                                   \
        _Pragma("unroll")                                                         \
        for (int j = 0; j < 8; j++)                                               \
            _Pragma("unroll")                                                     \
            for (int t = 0; t < 4; t++) acc[i][j][t] = 0.f;                       \
    int nkt = (Kdim) >> 5;                                                        \
    {                                                                             \
        _Pragma("unroll")                                                         \
        for (int r = 0; r < 4; r++) {                                             \
            uint32_t so = sb + soff + r * 2560;                                   \
            cp16(so,              gA1 + r * rstep);                               \
            cp16(so + TILE_B,     gA2 + r * rstep);                               \
            cp16(so + 2*TILE_B,   gB1 + r * rstep);                               \
            cp16(so + 3*TILE_B,   gB2 + r * rstep);                               \
        }                                                                         \
    }                                                                             \
    cp_commit(); cp_wait0(); __syncthreads();                                     \
    uint32_t aBase = 2 * ((uint32_t)(wm * 64 + (lane & 15)) * 40 + ((lane >> 4) << 3)); \
    uint32_t bBase = 2 * ((uint32_t)(wn * 64 + (lane & 7) + ((lane >> 4) << 3)) * 40 + (lane & 8)); \
    for (int kt = 0; kt < nkt; kt++) {                                            \
        if (kt + 1 < nkt) {                                                       \
            int koff = (kt + 1) << 5;                                             \
            uint32_t st = sb + ((kt + 1) & 1) * STAGE_B;                          \
            _Pragma("unroll")                                                     \
            for (int r = 0; r < 4; r++) {                                         \
                uint32_t so = st + soff + r * 2560;                               \
                cp16(so,              gA1 + r * rstep + koff);                    \
                cp16(so + TILE_B,     gA2 + r * rstep + koff);                    \
                cp16(so + 2*TILE_B,   gB1 + r * rstep + koff);                    \
                cp16(so + 3*TILE_B,   gB2 + r * rstep + koff);                    \
            }                                                                     \
        }                                                                         \
        cp_commit();                                                              \
        uint32_t base = sb + (kt & 1) * STAGE_B;                                  \
        _Pragma("unroll")                                                         \
        for (int kb = 0; kb < 32; kb += 16) {                                     \
            uint32_t ah[4][4], al[4][4], bh[4][4], bl[4][4];                      \
            _Pragma("unroll")                                                     \
            for (int mt = 0; mt < 4; mt++) {                                      \
                uint32_t o = aBase + 2 * (mt * 16 * 40 + kb);                     \
                ldmx4(ah[mt], base + o);                                          \
                ldmx4(al[mt], base + TILE_B + o);                                 \
            }                                                                     \
            _Pragma("unroll")                                                     \
            for (int g = 0; g < 4; g++) {                                         \
                uint32_t o = bBase + 2 * (g * 16 * 40 + kb);                      \
                ldmx4(bh[g], base + 2*TILE_B + o);                                \
                ldmx4(bl[g], base + 3*TILE_B + o);                                \
            }                                                                     \
            _Pragma("unroll")                                                     \
            for (int mt = 0; mt < 4; mt++)                                        \
                _Pragma("unroll")                                                 \
                for (int nt = 0; nt < 8; nt++) {                                  \
                    const uint32_t* fh = &bh[nt >> 1][(nt & 1) * 2];              \
                    const uint32_t* fl = &bl[nt >> 1][(nt & 1) * 2];              \
                    mma16816(acc[mt][nt], ah[mt], fh);                            \
                    mma16816(acc[mt][nt], ah[mt], fl);                            \
                    mma16816(acc[mt][nt], al[mt], fh);                            \
                }                                                                 \
        }                                                                         \
        cp_wait0();                                                               \
        __syncthreads();                                                          \
    }

/* ---------------- generic GEMM (Wo projection) ---------------- */
__global__ __launch_bounds__(128, 2)
void hmma_gemm(const __nv_bfloat16* __restrict__ Ahi, const __nv_bfloat16* __restrict__ Alo,
               const __nv_bfloat16* __restrict__ Bhi, const __nv_bfloat16* __restrict__ Blo,
               float* __restrict__ C, int N, int K) {
    GEMM_MAIN(Ahi, Alo, Bhi, Blo, K)
    int er = lane >> 2, ec = (lane & 3) * 2;
#pragma unroll
    for (int mt = 0; mt < 4; mt++)
#pragma unroll
        for (int nt = 0; nt < 8; nt++) {
            int row = bm + wm * 64 + mt * 16 + er;
            int col = bn + wn * 64 + nt * 8 + ec;
            *(float2*)(C + (size_t)row * N + col) =
                make_float2(acc[mt][nt][0], acc[mt][nt][1]);
            *(float2*)(C + (size_t)(row + 8) * N + col) =
                make_float2(acc[mt][nt][2], acc[mt][nt][3]);
        }
}

/* ---------------- QKV GEMM with fused RoPE + hi/lo split epilogue ------- */
__global__ __launch_bounds__(128, 2)
void hmma_gemm_qkv() {
    GEMM_MAIN(g_xhi, g_xlo, g_wbhi, g_wblo, D_MODEL)
    int er = lane >> 2, ec = (lane & 3) * 2;
    int head = (bn + wn * 64) >> 6;           /* 0..47 */
    if (head < N_HEADS + N_KV) {
        bool isq = head < N_HEADS;
        float scl = isq ? SCALE_L2E : 1.0f;
        __nv_bfloat16* hi = isq ? g_qhi : g_khi;
        __nv_bfloat16* lo = isq ? g_qlo : g_klo;
        int dim  = isq ? QDIM : KVDIM;
        int hcol = (isq ? head : head - N_HEADS) * HD;
#pragma unroll
        for (int mt = 0; mt < 4; mt++) {
            int row = bm + wm * 64 + mt * 16 + er;
#pragma unroll
            for (int hr = 0; hr < 2; hr++) {
                int tok = row + hr * 8;
                int s = tok & (SEQ - 1);
                int e0 = hr * 2;
#pragma unroll
                for (int nt = 0; nt < 4; nt++) {
                    int j = nt * 8 + ec;
                    float c0 = g_cos[s*32 + j],   c1 = g_cos[s*32 + j + 1];
                    float n0 = g_sin[s*32 + j],   n1 = g_sin[s*32 + j + 1];
                    float x1a = acc[mt][nt][e0],     x1b = acc[mt][nt][e0+1];
                    float x2a = acc[mt][nt+4][e0],   x2b = acc[mt][nt+4][e0+1];
                    float r1a = (x1a*c0 - x2a*n0) * scl, r1b = (x1b*c1 - x2b*n1) * scl;
                    float r2a = (x2a*c0 + x1a*n0) * scl, r2b = (x2b*c1 + x1b*n1) * scl;
                    size_t o1 = (size_t)tok * dim + hcol + j;
                    *(uint32_t*)(hi + o1)      = pk(r1a, r1b);
                    *(uint32_t*)(lo + o1)      = pk(r1a - b2f(r1a), r1b - b2f(r1b));
                    *(uint32_t*)(hi + o1 + 32) = pk(r2a, r2b);
                    *(uint32_t*)(lo + o1 + 32) = pk(r2a - b2f(r2a), r2b - b2f(r2b));
                }
            }
        }
    } else {
        int hcol = (head - N_HEADS - N_KV) * HD;
#pragma unroll
        for (int mt = 0; mt < 4; mt++) {
            int row = bm + wm * 64 + mt * 16 + er;
#pragma unroll
            for (int nt = 0; nt < 8; nt++) {
                int jj = nt * 8 + ec;
                size_t o0 = (size_t)row * KVDIM + hcol + jj;
                size_t o1 = (size_t)(row + 8) * KVDIM + hcol + jj;
                float v0 = acc[mt][nt][0], v1 = acc[mt][nt][1];
                float v2 = acc[mt][nt][2], v3 = acc[mt][nt][3];
                *(uint32_t*)(g_vhi + o0) = pk(v0, v1);
                *(uint32_t*)(g_vlo + o0) = pk(v0 - b2f(v0), v1 - b2f(v1));
                *(uint32_t*)(g_vhi + o1) = pk(v2, v3);
                *(uint32_t*)(g_vlo + o1) = pk(v2 - b2f(v2), v3 - b2f(v3));
            }
        }
    }
}

/* ---------------- HMMA flash attention (R6 core; qb reversed = LPT) ----- */
#define AS_KH 0
#define AS_KL 9216
#define AS_VH 18432
#define AS_VL 27648
#define ATTN_SMEM 36864

__global__ __launch_bounds__(256)
void attn_kernel(const int* __restrict__ cu) {
    extern __shared__ char smem[];
    uint32_t sb = smem_u32(smem);
    int qb = gridDim.x - 1 - blockIdx.x;   /* heavy q-blocks scheduled first */
    int h = blockIdx.y, b = blockIdx.z;
    int kvh = h >> 2;
    int tid = threadIdx.x, lane = tid & 31, wid = tid >> 5;
    int wq = wid & 3, wk = wid >> 2;

    int b0 = min(max(cu[b*4+0], 0), SEQ);
    int b1 = min(max(cu[b*4+1], 0), SEQ);
    int b2 = min(max(cu[b*4+2], 0), SEQ);
    int b3 = min(max(cu[b*4+3], 0), SEQ);

    int p0 = qb * 64;
    int s_start = 0;
    if (b0 <= p0) s_start = b0;
    if (b1 <= p0) s_start = max(s_start, b1);
    if (b2 <= p0) s_start = max(s_start, b2);
    if (b3 <= p0) s_start = max(s_start, b3);
    int kb0 = s_start >> 6;

#pragma unroll
    for (int i = 0; i < 4; i++) {
        int arr = i >> 1;
        int rem = tid + (i & 1) * 256;
        int row = rem >> 3, c = rem & 7;
        const __nv_bfloat16* src = arr ? g_qlo : g_qhi;
        cp16(sb + arr*9216 + row*144 + c*16,
             src + (size_t)(b*SEQ + p0 + row) * QDIM + h*HD + c*8);
    }
    cp_commit(); cp_wait0(); __syncthreads();

    uint32_t qh[4][4], ql[4][4];
#pragma unroll
    for (int kt = 0; kt < 4; kt++) {
        uint32_t off = (uint32_t)(wq*16 + (lane & 15)) * 144 + (kt*16 + ((lane >> 4) << 3)) * 2;
        ldmx4(qh[kt], sb + off);
        ldmx4(ql[kt], sb + 9216 + off);
    }

    int qp0 = p0 + wq*16 + (lane >> 2);
    int qp1 = qp0 + 8;
    int qsg0 = (b0 <= qp0) + (b1 <= qp0) + (b2 <= qp0) + (b3 <= qp0);
    int qsg1 = (b0 <= qp1) + (b1 <= qp1) + (b2 <= qp1) + (b3 <= qp1);

    float m0 = -INFINITY, m1 = -INFINITY, l0 = 0.f, l1 = 0.f;
    float o[8][4];
#pragma unroll
    for (int nd = 0; nd < 8; nd++)
#pragma unroll
        for (int j = 0; j < 4; j++) o[nd][j] = 0.f;

    int colb = wk*32 + (lane & 3)*2;

    for (int kb = kb0; kb <= qb; kb++) {
        __syncthreads();
#pragma unroll
        for (int i = 0; i < 8; i++) {
            int arr = i >> 1;
            int rem = tid + (i & 1) * 256;
            int row = rem >> 3, c = rem & 7;
            const __nv_bfloat16* src = (arr == 0) ? g_khi : (arr == 1) ? g_klo
                                     : (arr == 2) ? g_vhi : g_vlo;
            cp16(sb + arr*9216 + row*144 + c*16,
                 src + (size_t)(b*SEQ + kb*64 + row) * KVDIM + kvh*HD + c*8);
        }
        cp_commit(); cp_wait0(); __syncthreads();

        float s[4][4];
#pragma unroll
        for (int nt = 0; nt < 4; nt++)
#pragma unroll
            for (int j = 0; j < 4; j++) s[nt][j] = 0.f;

#pragma unroll
        for (int kt = 0; kt < 4; kt++) {
            uint32_t khf[2][4], klf[2][4];
#pragma unroll
            for (int np = 0; np < 2; np++) {
                int mq = lane >> 3, r = lane & 7;
                uint32_t off = (uint32_t)(wk*32 + np*16 + ((mq & 2) ? 8 : 0) + r) * 144
                             + (kt*16 + ((mq & 1) ? 8 : 0)) * 2;
                ldmx4(khf[np], sb + AS_KH + off);
                ldmx4(klf[np], sb + AS_KL + off);
            }
#pragma unroll
            for (int nt = 0; nt < 4; nt++) {
                const uint32_t* fh = &khf[nt >> 1][(nt & 1) * 2];
                const uint32_t* fl = &klf[nt >> 1][(nt & 1) * 2];
                mma16816(s[nt], qh[kt], fh);
                mma16816(s[nt], qh[kt], fl);
                mma16816(s[nt], ql[kt], fh);
            }
        }

#pragma unroll
        for (int nt = 0; nt < 4; nt++)
#pragma unroll
            for (int e = 0; e < 2; e++) {
                int kp = kb*64 + colb + nt*8 + e;
                int sk = (b0 <= kp) + (b1 <= kp) + (b2 <= kp) + (b3 <= kp);
                if (kp > qp0 || sk != qsg0) s[nt][e]     = -INFINITY;
                if (kp > qp1 || sk != qsg1) s[nt][2 + e] = -INFINITY;
            }

        float rm0 = -INFINITY, rm1 = -INFINITY;
#pragma unroll
        for (int nt = 0; nt < 4; nt++) {
            rm0 = fmaxf(rm0, fmaxf(s[nt][0], s[nt][1]));
            rm1 = fmaxf(rm1, fmaxf(s[nt][2], s[nt][3]));
        }
        rm0 = fmaxf(rm0, __shfl_xor_sync(0xffffffffu, rm0, 1));
        rm0 = fmaxf(rm0, __shfl_xor_sync(0xffffffffu, rm0, 2));
        rm1 = fmaxf(rm1, __shfl_xor_sync(0xffffffffu, rm1, 1));
        rm1 = fmaxf(rm1, __shfl_xor_sync(0xffffffffu, rm1, 2));
        float mn0 = fmaxf(m0, rm0), mn1 = fmaxf(m1, rm1);
        bool lv0 = mn0 > -INFINITY, lv1 = mn1 > -INFINITY;
        float sc0 = lv0 ? ((m0 > -INFINITY) ? ex2(m0 - mn0) : 0.f) : 1.f;
        float sc1 = lv1 ? ((m1 > -INFINITY) ? ex2(m1 - mn1) : 0.f) : 1.f;

        float p[4][4], pl[4][4];
        float rs0 = 0.f, rs1 = 0.f;
#pragma unroll
        for (int nt = 0; nt < 4; nt++) {
#pragma unroll
            for (int e = 0; e < 2; e++) {
                float v0 = lv0 ? ex2(s[nt][e]     - mn0) : 0.f;
                float v1 = lv1 ? ex2(s[nt][2 + e] - mn1) : 0.f;
                p[nt][e] = v0;     rs0 += v0;
                p[nt][2+e] = v1;   rs1 += v1;
            }
        }
        rs0 += __shfl_xor_sync(0xffffffffu, rs0, 1);
        rs0 += __shfl_xor_sync(0xffffffffu, rs0, 2);
        rs1 += __shfl_xor_sync(0xffffffffu, rs1, 1);
        rs1 += __shfl_xor_sync(0xffffffffu, rs1, 2);
        l0 = l0 * sc0 + rs0;  m0 = mn0;
        l1 = l1 * sc1 + rs1;  m1 = mn1;
#pragma unroll
        for (int nd = 0; nd < 8; nd++) {
            o[nd][0] *= sc0; o[nd][1] *= sc0;
            o[nd][2] *= sc1; o[nd][3] *= sc1;
        }

#pragma unroll
        for (int nt = 0; nt < 4; nt++)
#pragma unroll
            for (int j = 0; j < 4; j++) {
                float hv = __bfloat162float(__float2bfloat16(p[nt][j]));
                pl[nt][j] = p[nt][j] - hv;
            }

#pragma unroll
        for (int kt2 = 0; kt2 < 2; kt2++) {
            uint32_t pah[4] = { pk(p[2*kt2][0],   p[2*kt2][1]),
                                pk(p[2*kt2][2],   p[2*kt2][3]),
                                pk(p[2*kt2+1][0], p[2*kt2+1][1]),
                                pk(p[2*kt2+1][2], p[2*kt2+1][3]) };
            uint32_t pal[4] = { pk(pl[2*kt2][0],   pl[2*kt2][1]),
                                pk(pl[2*kt2][2],   pl[2*kt2][3]),
                                pk(pl[2*kt2+1][0], pl[2*kt2+1][1]),
                                pk(pl[2*kt2+1][2], pl[2*kt2+1][3]) };
#pragma unroll
            for (int ndp = 0; ndp < 4; ndp++) {
                int mq = lane >> 3, r = lane & 7;
                uint32_t off = (uint32_t)(wk*32 + kt2*16 + ((mq & 1) ? 8 : 0) + r) * 144
                             + (ndp*16 + ((mq & 2) ? 8 : 0)) * 2;
                uint32_t vh4[4], vl4[4];
                ldmx4t(vh4, sb + AS_VH + off);
                ldmx4t(vl4, sb + AS_VL + off);
#pragma unroll
                for (int q2 = 0; q2 < 2; q2++) {
                    int nd = ndp*2 + q2;
                    mma16816(o[nd], pah, &vh4[q2*2]);
                    mma16816(o[nd], pah, &vl4[q2*2]);
                    mma16816(o[nd], pal, &vh4[q2*2]);
                }
            }
        }
    }

    __syncthreads();
    float* Osm = (float*)smem;
    float* msm = (float*)(smem + 17408);
    float* lsm = (float*)(smem + 17664);
    int rl = wq*16 + (lane >> 2);
    int c2 = (lane & 3)*2;
    if (wk == 1) {
#pragma unroll
        for (int nd = 0; nd < 8; nd++) {
            *(float2*)&Osm[rl*68 + nd*8 + c2]     = make_float2(o[nd][0], o[nd][1]);
            *(float2*)&Osm[(rl+8)*68 + nd*8 + c2] = make_float2(o[nd][2], o[nd][3]);
        }
        if ((lane & 3) == 0) {
            msm[rl] = m0; msm[rl+8] = m1;
            lsm[rl] = l0; lsm[rl+8] = l1;
        }
    }
    __syncthreads();
    if (wk == 0) {
        float pm0 = msm[rl], pm1 = msm[rl+8];
        float pl0 = lsm[rl], pl1 = lsm[rl+8];
        float M0 = fmaxf(m0, pm0), M1 = fmaxf(m1, pm1);
        float sa0 = (m0  > -INFINITY) ? ex2(m0  - M0) : 0.f;
        float sb0 = (pm0 > -INFINITY) ? ex2(pm0 - M0) : 0.f;
        float sa1 = (m1  > -INFINITY) ? ex2(m1  - M1) : 0.f;
        float sb1 = (pm1 > -INFINITY) ? ex2(pm1 - M1) : 0.f;
        float inv0 = 1.f / (l0*sa0 + pl0*sb0);
        float inv1 = 1.f / (l1*sa1 + pl1*sb1);
        size_t r0g = (size_t)(b*SEQ + p0 + rl) * QDIM + h*HD;
        size_t r1g = (size_t)(b*SEQ + p0 + rl + 8) * QDIM + h*HD;
#pragma unroll
        for (int nd = 0; nd < 8; nd++) {
            float v0 = (o[nd][0]*sa0 + Osm[rl*68 + nd*8 + c2]*sb0) * inv0;
            float v1 = (o[nd][1]*sa0 + Osm[rl*68 + nd*8 + c2 + 1]*sb0) * inv0;
            float v2 = (o[nd][2]*sa1 + Osm[(rl+8)*68 + nd*8 + c2]*sb1) * inv1;
            float v3 = (o[nd][3]*sa1 + Osm[(rl+8)*68 + nd*8 + c2 + 1]*sb1) * inv1;
            *(uint32_t*)(g_aohi + r0g + nd*8 + c2) = pk(v0, v1);
            *(uint32_t*)(g_aolo + r0g + nd*8 + c2) = pk(v0 - b2f(v0), v1 - b2f(v1));
            *(uint32_t*)(g_aohi + r1g + nd*8 + c2) = pk(v2, v3);
            *(uint32_t*)(g_aolo + r1g + nd*8 + c2) = pk(v2 - b2f(v2), v3 - b2f(v3));
        }
    }
}

/* ------------------------------------------------------------------ */
extern "C" void kernel_launch(void* const* d_in, const int* in_sizes, int n_in,
                              void* d_out, int out_size) {
    const float* x  = (const float*)d_in[0];
    const int*   cu = (const int*)  d_in[1];
    const float* Wq = (const float*)d_in[2];
    const float* Wk = (const float*)d_in[3];
    const float* Wv = (const float*)d_in[4];
    const float* Wo = (const float*)d_in[5];
    float* out = (float*)d_out;

    __nv_bfloat16 *xhi, *xlo, *wbhi, *wblo, *wohi, *wolo, *aohi, *aolo;
    cudaGetSymbolAddress((void**)&xhi, g_xhi);   cudaGetSymbolAddress((void**)&xlo, g_xlo);
    cudaGetSymbolAddress((void**)&wbhi, g_wbhi); cudaGetSymbolAddress((void**)&wblo, g_wblo);
    cudaGetSymbolAddress((void**)&wohi, g_wohi); cudaGetSymbolAddress((void**)&wolo, g_wolo);
    cudaGetSymbolAddress((void**)&aohi, g_aohi); cudaGetSymbolAddress((void**)&aolo, g_aolo);

    cudaFuncSetAttribute(attn_kernel,
                         cudaFuncAttributeMaxDynamicSharedMemorySize, ATTN_SMEM);
    cudaFuncSetAttribute(hmma_gemm,
                         cudaFuncAttributeMaxDynamicSharedMemorySize, GEMM_SMEM);
    cudaFuncSetAttribute(hmma_gemm_qkv,
                         cudaFuncAttributeMaxDynamicSharedMemorySize, GEMM_SMEM);

    /* launches 1-5: prep (so launch #6 = QKV GEMM gets profiled by -s 5 -c 1) */
    rope_table_kernel<<<(SEQ*(HD/2) + 255)/256, 256>>>();
    split_kernel<<<(NTOK*D_MODEL/4 + 255)/256, 256>>>(x, xhi, xlo, NTOK*D_MODEL/4);
    tsplit_kernel<<<dim3(QDIM /32, D_MODEL/32), dim3(32,8)>>>(Wq, wbhi, wblo, D_MODEL, QDIM,  0);
    tsplit_kernel<<<dim3(KVDIM/32, D_MODEL/32), dim3(32,8)>>>(Wk, wbhi, wblo, D_MODEL, KVDIM, QDIM);
    tsplit_kernel<<<dim3(KVDIM/32, D_MODEL/32), dim3(32,8)>>>(Wv, wbhi, wblo, D_MODEL, KVDIM, QDIM+KVDIM);

    /* launch 6: merged QKV projection with fused rope+split epilogue */
    hmma_gemm_qkv<<<dim3(QKVDIM/128, NTOK/128), 128, GEMM_SMEM>>>();

    /* Wo weight prep (only needed before final GEMM) */
    tsplit_kernel<<<dim3(D_MODEL/32, QDIM/32), dim3(32,8)>>>(Wo, wohi, wolo, QDIM, D_MODEL, 0);

    /* attention */
    attn_kernel<<<dim3(SEQ/64, N_HEADS, BATCH), 256, ATTN_SMEM>>>(cu);

    /* output projection */
    hmma_gemm<<<dim3(D_MODEL/128, NTOK/128), 128, GEMM_SMEM>>>(aohi, aolo, wohi, wolo, out,
                                                               D_MODEL, QDIM);
}

// round 10
// speedup vs baseline: 1.0658x; 1.0205x over previous
#include <cuda_runtime.h>
#include <cuda_bf16.h>
#include <math.h>
#include <stdint.h>

#define D_MODEL 2048
#define N_HEADS 32
#define N_KV    8
#define HD      64
#define SEQ     2048
#define BATCH   2
#define NTOK    (BATCH*SEQ)      /* 4096 */
#define QDIM    (N_HEADS*HD)     /* 2048 */
#define KVDIM   (N_KV*HD)        /* 512  */
#define QKVDIM  (QDIM + 2*KVDIM) /* 3072 */
#define ROPE_BASE 500000.0f
#define SCALE_L2E 0.1803368801111204f   /* 0.125 * log2(e) */

/* ---------------- static device scratch ---------------- */
__device__ float g_cos[SEQ*(HD/2)];
__device__ float g_sin[SEQ*(HD/2)];

__device__ __nv_bfloat16 g_xhi [NTOK*D_MODEL];
__device__ __nv_bfloat16 g_xlo [NTOK*D_MODEL];
__device__ __nv_bfloat16 g_wbhi[QKVDIM*D_MODEL];   /* packed Wq|Wk|Wv, [N,K] */
__device__ __nv_bfloat16 g_wblo[QKVDIM*D_MODEL];
__device__ __nv_bfloat16 g_wohi[D_MODEL*QDIM];
__device__ __nv_bfloat16 g_wolo[D_MODEL*QDIM];
__device__ __nv_bfloat16 g_aohi[NTOK*QDIM];
__device__ __nv_bfloat16 g_aolo[NTOK*QDIM];

/* attention operands (written by QKV-GEMM epilogue, rope applied) */
__device__ __nv_bfloat16 g_qhi[NTOK*QDIM];
__device__ __nv_bfloat16 g_qlo[NTOK*QDIM];
__device__ __nv_bfloat16 g_khi[NTOK*KVDIM];
__device__ __nv_bfloat16 g_klo[NTOK*KVDIM];
__device__ __nv_bfloat16 g_vhi[NTOK*KVDIM];
__device__ __nv_bfloat16 g_vlo[NTOK*KVDIM];

/* ---------------- PTX helpers ---------------- */
__device__ __forceinline__ uint32_t smem_u32(const void* p) {
    uint32_t a;
    asm("{ .reg .u64 t; cvta.to.shared.u64 t, %1; cvt.u32.u64 %0, t; }" : "=r"(a) : "l"(p));
    return a;
}
__device__ __forceinline__ void cp16(uint32_t saddr, const void* g) {
    asm volatile("cp.async.cg.shared.global [%0], [%1], 16;" :: "r"(saddr), "l"(g));
}
__device__ __forceinline__ void cp_commit() { asm volatile("cp.async.commit_group;" ::: "memory"); }
__device__ __forceinline__ void cp_wait0()  { asm volatile("cp.async.wait_group 0;"  ::: "memory"); }

__device__ __forceinline__ void ldmx4(uint32_t* r, uint32_t addr) {
    asm volatile("ldmatrix.sync.aligned.m8n8.x4.shared.b16 {%0,%1,%2,%3}, [%4];"
                 : "=r"(r[0]), "=r"(r[1]), "=r"(r[2]), "=r"(r[3]) : "r"(addr));
}
__device__ __forceinline__ void ldmx4t(uint32_t* r, uint32_t addr) {
    asm volatile("ldmatrix.sync.aligned.m8n8.x4.trans.shared.b16 {%0,%1,%2,%3}, [%4];"
                 : "=r"(r[0]), "=r"(r[1]), "=r"(r[2]), "=r"(r[3]) : "r"(addr));
}
__device__ __forceinline__ void mma16816(float* d, const uint32_t* a, const uint32_t* b) {
    asm volatile(
        "mma.sync.aligned.m16n8k16.row.col.f32.bf16.bf16.f32 "
        "{%0,%1,%2,%3}, {%4,%5,%6,%7}, {%8,%9}, {%0,%1,%2,%3};"
        : "+f"(d[0]), "+f"(d[1]), "+f"(d[2]), "+f"(d[3])
        : "r"(a[0]), "r"(a[1]), "r"(a[2]), "r"(a[3]), "r"(b[0]), "r"(b[1]));
}
__device__ __forceinline__ float ex2(float x) {
    float y; asm("ex2.approx.f32 %0, %1;" : "=f"(y) : "f"(x)); return y;
}
__device__ __forceinline__ uint32_t pk(float a, float b) {
    __nv_bfloat162 t = __float22bfloat162_rn(make_float2(a, b));
    return *(uint32_t*)&t;
}
__device__ __forceinline__ float b2f(float v) {
    return __bfloat162float(__float2bfloat16(v));
}

/* ---------------- split kernels ---------------- */
__global__ __launch_bounds__(256) void split_kernel(const float* __restrict__ src,
                                                    __nv_bfloat16* __restrict__ hi,
                                                    __nv_bfloat16* __restrict__ lo,
                                                    int n4) {
    int i = blockIdx.x * blockDim.x + threadIdx.x;
    if (i >= n4) return;
    float4 v = ((const float4*)src)[i];
    __nv_bfloat16 h[4], l[4];
    float vv[4] = {v.x, v.y, v.z, v.w};
#pragma unroll
    for (int j = 0; j < 4; j++) {
        h[j] = __float2bfloat16(vv[j]);
        l[j] = __float2bfloat16(vv[j] - __bfloat162float(h[j]));
    }
    ((uint2*)hi)[i] = *(uint2*)h;
    ((uint2*)lo)[i] = *(uint2*)l;
}

/* generic transpose+split into a packed [N,K] buffer at row offset nOff */
__global__ __launch_bounds__(256) void tsplit_kernel(const float* __restrict__ W,
                                                     __nv_bfloat16* __restrict__ hi,
                                                     __nv_bfloat16* __restrict__ lo,
                                                     int K, int N, int nOff) {
    __shared__ float t[32][33];
    int n0 = blockIdx.x * 32, k0 = blockIdx.y * 32;
    int tx = threadIdx.x, ty = threadIdx.y;
#pragma unroll
    for (int i = 0; i < 32; i += 8)
        t[ty + i][tx] = W[(size_t)(k0 + ty + i) * N + n0 + tx];
    __syncthreads();
#pragma unroll
    for (int i = 0; i < 32; i += 8) {
        float v = t[tx][ty + i];
        __nv_bfloat16 h = __float2bfloat16(v);
        float r = v - __bfloat162float(h);
        size_t o = (size_t)(nOff + n0 + ty + i) * K + k0 + tx;
        hi[o] = h;
        lo[o] = __float2bfloat16(r);
    }
}

/* fused transpose+split for Wq|Wk|Wv into packed g_wbhi/g_wblo (one launch) */
__global__ __launch_bounds__(256) void tsplit_qkv_kernel(const float* __restrict__ Wq,
                                                         const float* __restrict__ Wk,
                                                         const float* __restrict__ Wv) {
    __shared__ float t[32][33];
    int np = blockIdx.x * 32;               /* packed row base, 0..3040 */
    int k0 = blockIdx.y * 32;
    const float* W;
    int N, off;
    if (np < QDIM)              { W = Wq; N = QDIM;  off = 0; }
    else if (np < QDIM + KVDIM) { W = Wk; N = KVDIM; off = QDIM; }
    else                        { W = Wv; N = KVDIM; off = QDIM + KVDIM; }
    int n0 = np - off;
    int tx = threadIdx.x, ty = threadIdx.y;
#pragma unroll
    for (int i = 0; i < 32; i += 8)
        t[ty + i][tx] = W[(size_t)(k0 + ty + i) * N + n0 + tx];
    __syncthreads();
#pragma unroll
    for (int i = 0; i < 32; i += 8) {
        float v = t[tx][ty + i];
        __nv_bfloat16 h = __float2bfloat16(v);
        float r = v - __bfloat162float(h);
        size_t o = (size_t)(np + ty + i) * D_MODEL + k0 + tx;
        g_wbhi[o] = h;
        g_wblo[o] = __float2bfloat16(r);
    }
}

/* ---------------- RoPE table (fp32 fast path) ---------------- */
__global__ void rope_table_kernel() {
    int i = blockIdx.x * blockDim.x + threadIdx.x;
    if (i >= SEQ * (HD/2)) return;
    int t = i >> 5;
    int j = i & 31;
    float ex = (float)j * (1.0f / 32.0f);
    float inv = powf(ROPE_BASE, -ex);
    float ang = (float)t * inv;
    float s, c;
    sincosf(ang, &s, &c);
    g_cos[i] = c;
    g_sin[i] = s;
}

/* ---------------- shared GEMM mainloop macro ---------------- */
#define TILE_B   10240            /* 128 rows * 80 B */
#define STAGE_B  (4*TILE_B)
#define GEMM_SMEM (2*STAGE_B)

#define GEMM_MAIN(Ahi, Alo, Bhi, Blo, Kdim)                                       \
    extern __shared__ char smem[];                                                \
    uint32_t sb = smem_u32(smem);                                                 \
    int tid = threadIdx.x, lane = tid & 31, wid = tid >> 5;                       \
    int wm = wid & 1, wn = wid >> 1;                                              \
    int bm = blockIdx.y * 128, bn = blockIdx.x * 128;                             \
    int lr = tid >> 2;                                                            \
    int lc = tid & 3;                                                             \
    const __nv_bfloat16* gA1 = (Ahi) + (size_t)(bm + lr) * (Kdim) + lc * 8;       \
    const __nv_bfloat16* gA2 = (Alo) + (size_t)(bm + lr) * (Kdim) + lc * 8;       \
    const __nv_bfloat16* gB1 = (Bhi) + (size_t)(bn + lr) * (Kdim) + lc * 8;       \
    const __nv_bfloat16* gB2 = (Blo) + (size_t)(bn + lr) * (Kdim) + lc * 8;       \
    size_t rstep = (size_t)32 * (Kdim);                                           \
    uint32_t soff = lr * 80 + lc * 16;                                            \
    float acc[4][8][4];                                                           \
    _Pragma("unroll")                                                             \
    for (int i = 0; i < 4; i++)                                                   \
        _Pragma("unroll")                                                         \
        for (int j = 0; j < 8; j++)                                               \
            _Pragma("unroll")                                                     \
            for (int t = 0; t < 4; t++) acc[i][j][t] = 0.f;                       \
    int nkt = (Kdim) >> 5;                                                        \
    {                                                                             \
        _Pragma("unroll")                                                         \
        for (int r = 0; r < 4; r++) {                                             \
            uint32_t so = sb + soff + r * 2560;                                   \
            cp16(so,              gA1 + r * rstep);                               \
            cp16(so + TILE_B,     gA2 + r * rstep);                               \
            cp16(so + 2*TILE_B,   gB1 + r * rstep);                               \
            cp16(so + 3*TILE_B,   gB2 + r * rstep);                               \
        }                                                                         \
    }                                                                             \
    cp_commit(); cp_wait0(); __syncthreads();                                     \
    uint32_t aBase = 2 * ((uint32_t)(wm * 64 + (lane & 15)) * 40 + ((lane >> 4) << 3)); \
    uint32_t bBase = 2 * ((uint32_t)(wn * 64 + (lane & 7) + ((lane >> 4) << 3)) * 40 + (lane & 8)); \
    for (int kt = 0; kt < nkt; kt++) {                                            \
        if (kt + 1 < nkt) {                                                       \
            int koff = (kt + 1) << 5;                                             \
            uint32_t st = sb + ((kt + 1) & 1) * STAGE_B;                          \
            _Pragma("unroll")                                                     \
            for (int r = 0; r < 4; r++) {                                         \
                uint32_t so = st + soff + r * 2560;                               \
                cp16(so,              gA1 + r * rstep + koff);                    \
                cp16(so + TILE_B,     gA2 + r * rstep + koff);                    \
                cp16(so + 2*TILE_B,   gB1 + r * rstep + koff);                    \
                cp16(so + 3*TILE_B,   gB2 + r * rstep + koff);                    \
            }                                                                     \
        }                                                                         \
        cp_commit();                                                              \
        uint32_t base = sb + (kt & 1) * STAGE_B;                                  \
        _Pragma("unroll")                                                         \
        for (int kb = 0; kb < 32; kb += 16) {                                     \
            uint32_t ah[4][4], al[4][4], bh[4][4], bl[4][4];                      \
            _Pragma("unroll")                                                     \
            for (int mt = 0; mt < 4; mt++) {                                      \
                uint32_t o = aBase + 2 * (mt * 16 * 40 + kb);                     \
                ldmx4(ah[mt], base + o);                                          \
                ldmx4(al[mt], base + TILE_B + o);                                 \
            }                                                                     \
            _Pragma("unroll")                                                     \
            for (int g = 0; g < 4; g++) {                                         \
                uint32_t o = bBase + 2 * (g * 16 * 40 + kb);                      \
                ldmx4(bh[g], base + 2*TILE_B + o);                                \
                ldmx4(bl[g], base + 3*TILE_B + o);                                \
            }                                                                     \
            _Pragma("unroll")                                                     \
            for (int mt = 0; mt < 4; mt++)                                        \
                _Pragma("unroll")                                                 \
                for (int nt = 0; nt < 8; nt++) {                                  \
                    const uint32_t* fh = &bh[nt >> 1][(nt & 1) * 2];              \
                    const uint32_t* fl = &bl[nt >> 1][(nt & 1) * 2];              \
                    mma16816(acc[mt][nt], ah[mt], fh);                            \
                    mma16816(acc[mt][nt], ah[mt], fl);                            \
                    mma16816(acc[mt][nt], al[mt], fh);                            \
                }                                                                 \
        }                                                                         \
        cp_wait0();                                                               \
        __syncthreads();                                                          \
    }

/* ---------------- generic GEMM (Wo projection) ---------------- */
__global__ __launch_bounds__(128, 2)
void hmma_gemm(const __nv_bfloat16* __restrict__ Ahi, const __nv_bfloat16* __restrict__ Alo,
               const __nv_bfloat16* __restrict__ Bhi, const __nv_bfloat16* __restrict__ Blo,
               float* __restrict__ C, int N, int K) {
    GEMM_MAIN(Ahi, Alo, Bhi, Blo, K)
    int er = lane >> 2, ec = (lane & 3) * 2;
#pragma unroll
    for (int mt = 0; mt < 4; mt++)
#pragma unroll
        for (int nt = 0; nt < 8; nt++) {
            int row = bm + wm * 64 + mt * 16 + er;
            int col = bn + wn * 64 + nt * 8 + ec;
            *(float2*)(C + (size_t)row * N + col) =
                make_float2(acc[mt][nt][0], acc[mt][nt][1]);
            *(float2*)(C + (size_t)(row + 8) * N + col) =
                make_float2(acc[mt][nt][2], acc[mt][nt][3]);
        }
}

/* ---------------- QKV GEMM with fused RoPE + hi/lo split epilogue ------- */
__global__ __launch_bounds__(128, 2)
void hmma_gemm_qkv() {
    GEMM_MAIN(g_xhi, g_xlo, g_wbhi, g_wblo, D_MODEL)
    int er = lane >> 2, ec = (lane & 3) * 2;
    int head = (bn + wn * 64) >> 6;           /* 0..47 */
    if (head < N_HEADS + N_KV) {
        bool isq = head < N_HEADS;
        float scl = isq ? SCALE_L2E : 1.0f;
        __nv_bfloat16* hi = isq ? g_qhi : g_khi;
        __nv_bfloat16* lo = isq ? g_qlo : g_klo;
        int dim  = isq ? QDIM : KVDIM;
        int hcol = (isq ? head : head - N_HEADS) * HD;
#pragma unroll
        for (int mt = 0; mt < 4; mt++) {
            int row = bm + wm * 64 + mt * 16 + er;
#pragma unroll
            for (int hr = 0; hr < 2; hr++) {
                int tok = row + hr * 8;
                int s = tok & (SEQ - 1);
                int e0 = hr * 2;
#pragma unroll
                for (int nt = 0; nt < 4; nt++) {
                    int j = nt * 8 + ec;
                    float c0 = g_cos[s*32 + j],   c1 = g_cos[s*32 + j + 1];
                    float n0 = g_sin[s*32 + j],   n1 = g_sin[s*32 + j + 1];
                    float x1a = acc[mt][nt][e0],     x1b = acc[mt][nt][e0+1];
                    float x2a = acc[mt][nt+4][e0],   x2b = acc[mt][nt+4][e0+1];
                    float r1a = (x1a*c0 - x2a*n0) * scl, r1b = (x1b*c1 - x2b*n1) * scl;
                    float r2a = (x2a*c0 + x1a*n0) * scl, r2b = (x2b*c1 + x1b*n1) * scl;
                    size_t o1 = (size_t)tok * dim + hcol + j;
                    *(uint32_t*)(hi + o1)      = pk(r1a, r1b);
                    *(uint32_t*)(lo + o1)      = pk(r1a - b2f(r1a), r1b - b2f(r1b));
                    *(uint32_t*)(hi + o1 + 32) = pk(r2a, r2b);
                    *(uint32_t*)(lo + o1 + 32) = pk(r2a - b2f(r2a), r2b - b2f(r2b));
                }
            }
        }
    } else {
        int hcol = (head - N_HEADS - N_KV) * HD;
#pragma unroll
        for (int mt = 0; mt < 4; mt++) {
            int row = bm + wm * 64 + mt * 16 + er;
#pragma unroll
            for (int nt = 0; nt < 8; nt++) {
                int jj = nt * 8 + ec;
                size_t o0 = (size_t)row * KVDIM + hcol + jj;
                size_t o1 = (size_t)(row + 8) * KVDIM + hcol + jj;
                float v0 = acc[mt][nt][0], v1 = acc[mt][nt][1];
                float v2 = acc[mt][nt][2], v3 = acc[mt][nt][3];
                *(uint32_t*)(g_vhi + o0) = pk(v0, v1);
                *(uint32_t*)(g_vlo + o0) = pk(v0 - b2f(v0), v1 - b2f(v1));
                *(uint32_t*)(g_vhi + o1) = pk(v2, v3);
                *(uint32_t*)(g_vlo + o1) = pk(v2 - b2f(v2), v3 - b2f(v3));
            }
        }
    }
}

/* ---------------- HMMA flash attention (R6/R8 proven core) -------------- */
#define AS_KH 0
#define AS_KL 9216
#define AS_VH 18432
#define AS_VL 27648
#define ATTN_SMEM 36864

__global__ __launch_bounds__(256)
void attn_kernel(const int* __restrict__ cu) {
    extern __shared__ char smem[];
    uint32_t sb = smem_u32(smem);
    int qb = blockIdx.x, h = blockIdx.y, b = blockIdx.z;
    int kvh = h >> 2;
    int tid = threadIdx.x, lane = tid & 31, wid = tid >> 5;
    int wq = wid & 3, wk = wid >> 2;

    int b0 = min(max(cu[b*4+0], 0), SEQ);
    int b1 = min(max(cu[b*4+1], 0), SEQ);
    int b2 = min(max(cu[b*4+2], 0), SEQ);
    int b3 = min(max(cu[b*4+3], 0), SEQ);

    int p0 = qb * 64;
    int s_start = 0;
    if (b0 <= p0) s_start = b0;
    if (b1 <= p0) s_start = max(s_start, b1);
    if (b2 <= p0) s_start = max(s_start, b2);
    if (b3 <= p0) s_start = max(s_start, b3);
    int kb0 = s_start >> 6;

#pragma unroll
    for (int i = 0; i < 4; i++) {
        int arr = i >> 1;
        int rem = tid + (i & 1) * 256;
        int row = rem >> 3, c = rem & 7;
        const __nv_bfloat16* src = arr ? g_qlo : g_qhi;
        cp16(sb + arr*9216 + row*144 + c*16,
             src + (size_t)(b*SEQ + p0 + row) * QDIM + h*HD + c*8);
    }
    cp_commit(); cp_wait0(); __syncthreads();

    uint32_t qh[4][4], ql[4][4];
#pragma unroll
    for (int kt = 0; kt < 4; kt++) {
        uint32_t off = (uint32_t)(wq*16 + (lane & 15)) * 144 + (kt*16 + ((lane >> 4) << 3)) * 2;
        ldmx4(qh[kt], sb + off);
        ldmx4(ql[kt], sb + 9216 + off);
    }

    int qp0 = p0 + wq*16 + (lane >> 2);
    int qp1 = qp0 + 8;
    int qsg0 = (b0 <= qp0) + (b1 <= qp0) + (b2 <= qp0) + (b3 <= qp0);
    int qsg1 = (b0 <= qp1) + (b1 <= qp1) + (b2 <= qp1) + (b3 <= qp1);

    float m0 = -INFINITY, m1 = -INFINITY, l0 = 0.f, l1 = 0.f;
    float o[8][4];
#pragma unroll
    for (int nd = 0; nd < 8; nd++)
#pragma unroll
        for (int j = 0; j < 4; j++) o[nd][j] = 0.f;

    int colb = wk*32 + (lane & 3)*2;

    for (int kb = kb0; kb <= qb; kb++) {
        __syncthreads();
#pragma unroll
        for (int i = 0; i < 8; i++) {
            int arr = i >> 1;
            int rem = tid + (i & 1) * 256;
            int row = rem >> 3, c = rem & 7;
            const __nv_bfloat16* src = (arr == 0) ? g_khi : (arr == 1) ? g_klo
                                     : (arr == 2) ? g_vhi : g_vlo;
            cp16(sb + arr*9216 + row*144 + c*16,
                 src + (size_t)(b*SEQ + kb*64 + row) * KVDIM + kvh*HD + c*8);
        }
        cp_commit(); cp_wait0(); __syncthreads();

        float s[4][4];
#pragma unroll
        for (int nt = 0; nt < 4; nt++)
#pragma unroll
            for (int j = 0; j < 4; j++) s[nt][j] = 0.f;

#pragma unroll
        for (int kt = 0; kt < 4; kt++) {
            uint32_t khf[2][4], klf[2][4];
#pragma unroll
            for (int np = 0; np < 2; np++) {
                int mq = lane >> 3, r = lane & 7;
                uint32_t off = (uint32_t)(wk*32 + np*16 + ((mq & 2) ? 8 : 0) + r) * 144
                             + (kt*16 + ((mq & 1) ? 8 : 0)) * 2;
                ldmx4(khf[np], sb + AS_KH + off);
                ldmx4(klf[np], sb + AS_KL + off);
            }
#pragma unroll
            for (int nt = 0; nt < 4; nt++) {
                const uint32_t* fh = &khf[nt >> 1][(nt & 1) * 2];
                const uint32_t* fl = &klf[nt >> 1][(nt & 1) * 2];
                mma16816(s[nt], qh[kt], fh);
                mma16816(s[nt], qh[kt], fl);
                mma16816(s[nt], ql[kt], fh);
            }
        }

#pragma unroll
        for (int nt = 0; nt < 4; nt++)
#pragma unroll
            for (int e = 0; e < 2; e++) {
                int kp = kb*64 + colb + nt*8 + e;
                int sk = (b0 <= kp) + (b1 <= kp) + (b2 <= kp) + (b3 <= kp);
                if (kp > qp0 || sk != qsg0) s[nt][e]     = -INFINITY;
                if (kp > qp1 || sk != qsg1) s[nt][2 + e] = -INFINITY;
            }

        float rm0 = -INFINITY, rm1 = -INFINITY;
#pragma unroll
        for (int nt = 0; nt < 4; nt++) {
            rm0 = fmaxf(rm0, fmaxf(s[nt][0], s[nt][1]));
            rm1 = fmaxf(rm1, fmaxf(s[nt][2], s[nt][3]));
        }
        rm0 = fmaxf(rm0, __shfl_xor_sync(0xffffffffu, rm0, 1));
        rm0 = fmaxf(rm0, __shfl_xor_sync(0xffffffffu, rm0, 2));
        rm1 = fmaxf(rm1, __shfl_xor_sync(0xffffffffu, rm1, 1));
        rm1 = fmaxf(rm1, __shfl_xor_sync(0xffffffffu, rm1, 2));
        float mn0 = fmaxf(m0, rm0), mn1 = fmaxf(m1, rm1);
        bool lv0 = mn0 > -INFINITY, lv1 = mn1 > -INFINITY;
        float sc0 = lv0 ? ((m0 > -INFINITY) ? ex2(m0 - mn0) : 0.f) : 1.f;
        float sc1 = lv1 ? ((m1 > -INFINITY) ? ex2(m1 - mn1) : 0.f) : 1.f;

        float p[4][4], pl[4][4];
        float rs0 = 0.f, rs1 = 0.f;
#pragma unroll
        for (int nt = 0; nt < 4; nt++) {
#pragma unroll
            for (int e = 0; e < 2; e++) {
                float v0 = lv0 ? ex2(s[nt][e]     - mn0) : 0.f;
                float v1 = lv1 ? ex2(s[nt][2 + e] - mn1) : 0.f;
                p[nt][e] = v0;     rs0 += v0;
                p[nt][2+e] = v1;   rs1 += v1;
            }
        }
        rs0 += __shfl_xor_sync(0xffffffffu, rs0, 1);
        rs0 += __shfl_xor_sync(0xffffffffu, rs0, 2);
        rs1 += __shfl_xor_sync(0xffffffffu, rs1, 1);
        rs1 += __shfl_xor_sync(0xffffffffu, rs1, 2);
        l0 = l0 * sc0 + rs0;  m0 = mn0;
        l1 = l1 * sc1 + rs1;  m1 = mn1;
#pragma unroll
        for (int nd = 0; nd < 8; nd++) {
            o[nd][0] *= sc0; o[nd][1] *= sc0;
            o[nd][2] *= sc1; o[nd][3] *= sc1;
        }

#pragma unroll
        for (int nt = 0; nt < 4; nt++)
#pragma unroll
            for (int j = 0; j < 4; j++) {
                float hv = __bfloat162float(__float2bfloat16(p[nt][j]));
                pl[nt][j] = p[nt][j] - hv;
            }

#pragma unroll
        for (int kt2 = 0; kt2 < 2; kt2++) {
            uint32_t pah[4] = { pk(p[2*kt2][0],   p[2*kt2][1]),
                                pk(p[2*kt2][2],   p[2*kt2][3]),
                                pk(p[2*kt2+1][0], p[2*kt2+1][1]),
                                pk(p[2*kt2+1][2], p[2*kt2+1][3]) };
            uint32_t pal[4] = { pk(pl[2*kt2][0],   pl[2*kt2][1]),
                                pk(pl[2*kt2][2],   pl[2*kt2][3]),
                                pk(pl[2*kt2+1][0], pl[2*kt2+1][1]),
                                pk(pl[2*kt2+1][2], pl[2*kt2+1][3]) };
#pragma unroll
            for (int ndp = 0; ndp < 4; ndp++) {
                int mq = lane >> 3, r = lane & 7;
                uint32_t off = (uint32_t)(wk*32 + kt2*16 + ((mq & 1) ? 8 : 0) + r) * 144
                             + (ndp*16 + ((mq & 2) ? 8 : 0)) * 2;
                uint32_t vh4[4], vl4[4];
                ldmx4t(vh4, sb + AS_VH + off);
                ldmx4t(vl4, sb + AS_VL + off);
#pragma unroll
                for (int q2 = 0; q2 < 2; q2++) {
                    int nd = ndp*2 + q2;
                    mma16816(o[nd], pah, &vh4[q2*2]);
                    mma16816(o[nd], pah, &vl4[q2*2]);
                    mma16816(o[nd], pal, &vh4[q2*2]);
                }
            }
        }
    }

    __syncthreads();
    float* Osm = (float*)smem;
    float* msm = (float*)(smem + 17408);
    float* lsm = (float*)(smem + 17664);
    int rl = wq*16 + (lane >> 2);
    int c2 = (lane & 3)*2;
    if (wk == 1) {
#pragma unroll
        for (int nd = 0; nd < 8; nd++) {
            *(float2*)&Osm[rl*68 + nd*8 + c2]     = make_float2(o[nd][0], o[nd][1]);
            *(float2*)&Osm[(rl+8)*68 + nd*8 + c2] = make_float2(o[nd][2], o[nd][3]);
        }
        if ((lane & 3) == 0) {
            msm[rl] = m0; msm[rl+8] = m1;
            lsm[rl] = l0; lsm[rl+8] = l1;
        }
    }
    __syncthreads();
    if (wk == 0) {
        float pm0 = msm[rl], pm1 = msm[rl+8];
        float pl0 = lsm[rl], pl1 = lsm[rl+8];
        float M0 = fmaxf(m0, pm0), M1 = fmaxf(m1, pm1);
        float sa0 = (m0  > -INFINITY) ? ex2(m0  - M0) : 0.f;
        float sb0 = (pm0 > -INFINITY) ? ex2(pm0 - M0) : 0.f;
        float sa1 = (m1  > -INFINITY) ? ex2(m1  - M1) : 0.f;
        float sb1 = (pm1 > -INFINITY) ? ex2(pm1 - M1) : 0.f;
        float inv0 = 1.f / (l0*sa0 + pl0*sb0);
        float inv1 = 1.f / (l1*sa1 + pl1*sb1);
        size_t r0g = (size_t)(b*SEQ + p0 + rl) * QDIM + h*HD;
        size_t r1g = (size_t)(b*SEQ + p0 + rl + 8) * QDIM + h*HD;
#pragma unroll
        for (int nd = 0; nd < 8; nd++) {
            float v0 = (o[nd][0]*sa0 + Osm[rl*68 + nd*8 + c2]*sb0) * inv0;
            float v1 = (o[nd][1]*sa0 + Osm[rl*68 + nd*8 + c2 + 1]*sb0) * inv0;
            float v2 = (o[nd][2]*sa1 + Osm[(rl+8)*68 + nd*8 + c2]*sb1) * inv1;
            float v3 = (o[nd][3]*sa1 + Osm[(rl+8)*68 + nd*8 + c2 + 1]*sb1) * inv1;
            *(uint32_t*)(g_aohi + r0g + nd*8 + c2) = pk(v0, v1);
            *(uint32_t*)(g_aolo + r0g + nd*8 + c2) = pk(v0 - b2f(v0), v1 - b2f(v1));
            *(uint32_t*)(g_aohi + r1g + nd*8 + c2) = pk(v2, v3);
            *(uint32_t*)(g_aolo + r1g + nd*8 + c2) = pk(v2 - b2f(v2), v3 - b2f(v3));
        }
    }
}

/* ------------------------------------------------------------------ */
extern "C" void kernel_launch(void* const* d_in, const int* in_sizes, int n_in,
                              void* d_out, int out_size) {
    const float* x  = (const float*)d_in[0];
    const int*   cu = (const int*)  d_in[1];
    const float* Wq = (const float*)d_in[2];
    const float* Wk = (const float*)d_in[3];
    const float* Wv = (const float*)d_in[4];
    const float* Wo = (const float*)d_in[5];
    float* out = (float*)d_out;

    __nv_bfloat16 *xhi, *xlo, *wohi, *wolo, *aohi, *aolo;
    cudaGetSymbolAddress((void**)&xhi, g_xhi);   cudaGetSymbolAddress((void**)&xlo, g_xlo);
    cudaGetSymbolAddress((void**)&wohi, g_wohi); cudaGetSymbolAddress((void**)&wolo, g_wolo);
    cudaGetSymbolAddress((void**)&aohi, g_aohi); cudaGetSymbolAddress((void**)&aolo, g_aolo);

    cudaFuncSetAttribute(attn_kernel,
                         cudaFuncAttributeMaxDynamicSharedMemorySize, ATTN_SMEM);
    cudaFuncSetAttribute(hmma_gemm,
                         cudaFuncAttributeMaxDynamicSharedMemorySize, GEMM_SMEM);
    cudaFuncSetAttribute(hmma_gemm_qkv,
                         cudaFuncAttributeMaxDynamicSharedMemorySize, GEMM_SMEM);

    /* launches 1-4: prep (harness poison launch +1 puts ncu -s5 on #5 = QKV GEMM) */
    rope_table_kernel<<<(SEQ*(HD/2) + 255)/256, 256>>>();
    split_kernel<<<(NTOK*D_MODEL/4 + 255)/256, 256>>>(x, xhi, xlo, NTOK*D_MODEL/4);
    tsplit_qkv_kernel<<<dim3(QKVDIM/32, D_MODEL/32), dim3(32,8)>>>(Wq, Wk, Wv);
    tsplit_kernel<<<dim3(D_MODEL/32, QDIM/32), dim3(32,8)>>>(Wo, wohi, wolo, QDIM, D_MODEL, 0);

    /* launch 5: merged QKV projection with fused rope+split epilogue */
    hmma_gemm_qkv<<<dim3(QKVDIM/128, NTOK/128), 128, GEMM_SMEM>>>();

    /* launch 6: attention */
    attn_kernel<<<dim3(SEQ/64, N_HEADS, BATCH), 256, ATTN_SMEM>>>(cu);

    /* launch 7: output projection */
    hmma_gemm<<<dim3(D_MODEL/128, NTOK/128), 128, GEMM_SMEM>>>(aohi, aolo, wohi, wolo, out,
                                                               D_MODEL, QDIM);
}

// round 11
// speedup vs baseline: 1.3966x; 1.3104x over previous
#include <cuda_runtime.h>
#include <cuda_bf16.h>
#include <cuda_fp16.h>
#include <math.h>
#include <stdint.h>

#define D_MODEL 2048
#define N_HEADS 32
#define N_KV    8
#define HD      64
#define SEQ     2048
#define BATCH   2
#define NTOK    (BATCH*SEQ)      /* 4096 */
#define QDIM    (N_HEADS*HD)     /* 2048 */
#define KVDIM   (N_KV*HD)        /* 512  */
#define QKVDIM  (QDIM + 2*KVDIM) /* 3072 */
#define ROPE_BASE 500000.0f
#define SCALE_L2E 0.1803368801111204f   /* 0.125 * log2(e) */

/* ---------------- static device scratch ---------------- */
__device__ float g_cos[SEQ*(HD/2)];
__device__ float g_sin[SEQ*(HD/2)];

/* GEMM operands: fp16. Activations split hi/lo, weights single. */
__device__ __half g_xh [NTOK*D_MODEL];
__device__ __half g_xl [NTOK*D_MODEL];
__device__ __half g_wb [QKVDIM*D_MODEL];   /* packed Wq|Wk|Wv, [N,K] */
__device__ __half g_wo [D_MODEL*QDIM];
__device__ __half g_ah [NTOK*QDIM];        /* attention out hi */
__device__ __half g_al [NTOK*QDIM];        /* attention out lo */

/* attention operands (bf16 split, written by QKV-GEMM epilogue) */
__device__ __nv_bfloat16 g_qhi[NTOK*QDIM];
__device__ __nv_bfloat16 g_qlo[NTOK*QDIM];
__device__ __nv_bfloat16 g_khi[NTOK*KVDIM];
__device__ __nv_bfloat16 g_klo[NTOK*KVDIM];
__device__ __nv_bfloat16 g_vhi[NTOK*KVDIM];
__device__ __nv_bfloat16 g_vlo[NTOK*KVDIM];

/* ---------------- PTX helpers ---------------- */
__device__ __forceinline__ uint32_t smem_u32(const void* p) {
    uint32_t a;
    asm("{ .reg .u64 t; cvta.to.shared.u64 t, %1; cvt.u32.u64 %0, t; }" : "=r"(a) : "l"(p));
    return a;
}
__device__ __forceinline__ void cp16(uint32_t saddr, const void* g) {
    asm volatile("cp.async.cg.shared.global [%0], [%1], 16;" :: "r"(saddr), "l"(g));
}
__device__ __forceinline__ void cp_commit() { asm volatile("cp.async.commit_group;" ::: "memory"); }
__device__ __forceinline__ void cp_wait0()  { asm volatile("cp.async.wait_group 0;"  ::: "memory"); }

__device__ __forceinline__ void ldmx4(uint32_t* r, uint32_t addr) {
    asm volatile("ldmatrix.sync.aligned.m8n8.x4.shared.b16 {%0,%1,%2,%3}, [%4];"
                 : "=r"(r[0]), "=r"(r[1]), "=r"(r[2]), "=r"(r[3]) : "r"(addr));
}
__device__ __forceinline__ void ldmx4t(uint32_t* r, uint32_t addr) {
    asm volatile("ldmatrix.sync.aligned.m8n8.x4.trans.shared.b16 {%0,%1,%2,%3}, [%4];"
                 : "=r"(r[0]), "=r"(r[1]), "=r"(r[2]), "=r"(r[3]) : "r"(addr));
}
/* bf16 mma (attention) */
__device__ __forceinline__ void mma16816(float* d, const uint32_t* a, const uint32_t* b) {
    asm volatile(
        "mma.sync.aligned.m16n8k16.row.col.f32.bf16.bf16.f32 "
        "{%0,%1,%2,%3}, {%4,%5,%6,%7}, {%8,%9}, {%0,%1,%2,%3};"
        : "+f"(d[0]), "+f"(d[1]), "+f"(d[2]), "+f"(d[3])
        : "r"(a[0]), "r"(a[1]), "r"(a[2]), "r"(a[3]), "r"(b[0]), "r"(b[1]));
}
/* fp16 mma (projections) */
__device__ __forceinline__ void mma16816h(float* d, const uint32_t* a, const uint32_t* b) {
    asm volatile(
        "mma.sync.aligned.m16n8k16.row.col.f32.f16.f16.f32 "
        "{%0,%1,%2,%3}, {%4,%5,%6,%7}, {%8,%9}, {%0,%1,%2,%3};"
        : "+f"(d[0]), "+f"(d[1]), "+f"(d[2]), "+f"(d[3])
        : "r"(a[0]), "r"(a[1]), "r"(a[2]), "r"(a[3]), "r"(b[0]), "r"(b[1]));
}
__device__ __forceinline__ float ex2(float x) {
    float y; asm("ex2.approx.f32 %0, %1;" : "=f"(y) : "f"(x)); return y;
}
__device__ __forceinline__ uint32_t pk(float a, float b) {
    __nv_bfloat162 t = __float22bfloat162_rn(make_float2(a, b));
    return *(uint32_t*)&t;
}
__device__ __forceinline__ uint32_t pkh(float a, float b) {
    __half2 t = __floats2half2_rn(a, b);
    return *(uint32_t*)&t;
}
__device__ __forceinline__ float b2f(float v) {
    return __bfloat162float(__float2bfloat16(v));
}
__device__ __forceinline__ float h2f(float v) {
    return __half2float(__float2half_rn(v));
}

/* ---------------- prep kernels ---------------- */
/* split x into fp16 hi/lo */
__global__ __launch_bounds__(256) void splitx_kernel(const float* __restrict__ src, int n4) {
    int i = blockIdx.x * blockDim.x + threadIdx.x;
    if (i >= n4) return;
    float4 v = ((const float4*)src)[i];
    float vv[4] = {v.x, v.y, v.z, v.w};
    __half h[4], l[4];
#pragma unroll
    for (int j = 0; j < 4; j++) {
        h[j] = __float2half_rn(vv[j]);
        l[j] = __float2half_rn(vv[j] - __half2float(h[j]));
    }
    ((uint2*)g_xh)[i] = *(uint2*)h;
    ((uint2*)g_xl)[i] = *(uint2*)l;
}

/* fused transpose+convert Wq|Wk|Wv -> packed fp16 [QKVDIM, D_MODEL] */
__global__ __launch_bounds__(256) void tconv_qkv_kernel(const float* __restrict__ Wq,
                                                        const float* __restrict__ Wk,
                                                        const float* __restrict__ Wv) {
    __shared__ float t[32][33];
    int np = blockIdx.x * 32;
    int k0 = blockIdx.y * 32;
    const float* W;
    int N, off;
    if (np < QDIM)              { W = Wq; N = QDIM;  off = 0; }
    else if (np < QDIM + KVDIM) { W = Wk; N = KVDIM; off = QDIM; }
    else                        { W = Wv; N = KVDIM; off = QDIM + KVDIM; }
    int n0 = np - off;
    int tx = threadIdx.x, ty = threadIdx.y;
#pragma unroll
    for (int i = 0; i < 32; i += 8)
        t[ty + i][tx] = W[(size_t)(k0 + ty + i) * N + n0 + tx];
    __syncthreads();
#pragma unroll
    for (int i = 0; i < 32; i += 8)
        g_wb[(size_t)(np + ty + i) * D_MODEL + k0 + tx] = __float2half_rn(t[tx][ty + i]);
}

/* transpose+convert Wo -> fp16 [D_MODEL, QDIM] */
__global__ __launch_bounds__(256) void tconv_wo_kernel(const float* __restrict__ W) {
    __shared__ float t[32][33];
    int n0 = blockIdx.x * 32, k0 = blockIdx.y * 32;
    int tx = threadIdx.x, ty = threadIdx.y;
#pragma unroll
    for (int i = 0; i < 32; i += 8)
        t[ty + i][tx] = W[(size_t)(k0 + ty + i) * D_MODEL + n0 + tx];
    __syncthreads();
#pragma unroll
    for (int i = 0; i < 32; i += 8)
        g_wo[(size_t)(n0 + ty + i) * QDIM + k0 + tx] = __float2half_rn(t[tx][ty + i]);
}

/* ---------------- RoPE table (fp32) ---------------- */
__global__ void rope_table_kernel() {
    int i = blockIdx.x * blockDim.x + threadIdx.x;
    if (i >= SEQ * (HD/2)) return;
    int t = i >> 5;
    int j = i & 31;
    float ex = (float)j * (1.0f / 32.0f);
    float inv = powf(ROPE_BASE, -ex);
    float ang = (float)t * inv;
    float s, c;
    sincosf(ang, &s, &c);
    g_cos[i] = c;
    g_sin[i] = s;
}

/* ---------------- fp16x2 GEMM mainloop macro ----------------
 * C = (Ahi+Alo)[M,K] @ B[N,K]^T ; 2 MMAs per (mt,nt) k-step.
 * Tiles per stage: AH | AL | B, each 128 rows x 80B (64B data).
 */
#define TILE_B   10240
#define STAGE_B  (3*TILE_B)
#define GEMM_SMEM (2*STAGE_B)     /* 61440 */

#define GEMM_MAIN(Ahi, Alo, Bp, Kdim)                                             \
    extern __shared__ char smem[];                                                \
    uint32_t sb = smem_u32(smem);                                                 \
    int tid = threadIdx.x, lane = tid & 31, wid = tid >> 5;                       \
    int wm = wid & 1, wn = wid >> 1;                                              \
    int bm = blockIdx.y * 128, bn = blockIdx.x * 128;                             \
    int lr = tid >> 2;                                                            \
    int lc = tid & 3;                                                             \
    const __half* gA1 = (Ahi) + (size_t)(bm + lr) * (Kdim) + lc * 8;              \
    const __half* gA2 = (Alo) + (size_t)(bm + lr) * (Kdim) + lc * 8;              \
    const __half* gB1 = (Bp)  + (size_t)(bn + lr) * (Kdim) + lc * 8;              \
    size_t rstep = (size_t)32 * (Kdim);                                           \
    uint32_t soff = lr * 80 + lc * 16;                                            \
    float acc[4][8][4];                                                           \
    _Pragma("unroll")                                                             \
    for (int i = 0; i < 4; i++)                                                   \
        _Pragma("unroll")                                                         \
        for (int j = 0; j < 8; j++)                                               \
            _Pragma("unroll")                                                     \
            for (int t = 0; t < 4; t++) acc[i][j][t] = 0.f;                       \
    int nkt = (Kdim) >> 5;                                                        \
    {                                                                             \
        _Pragma("unroll")                                                         \
        for (int r = 0; r < 4; r++) {                                             \
            uint32_t so = sb + soff + r * 2560;                                   \
            cp16(so,              gA1 + r * rstep);                               \
            cp16(so + TILE_B,     gA2 + r * rstep);                               \
            cp16(so + 2*TILE_B,   gB1 + r * rstep);                               \
        }                                                                         \
    }                                                                             \
    cp_commit(); cp_wait0(); __syncthreads();                                     \
    uint32_t aBase = 2 * ((uint32_t)(wm * 64 + (lane & 15)) * 40 + ((lane >> 4) << 3)); \
    uint32_t bBase = 2 * ((uint32_t)(wn * 64 + (lane & 7) + ((lane >> 4) << 3)) * 40 + (lane & 8)); \
    for (int kt = 0; kt < nkt; kt++) {                                            \
        if (kt + 1 < nkt) {                                                       \
            int koff = (kt + 1) << 5;                                             \
            uint32_t st = sb + ((kt + 1) & 1) * STAGE_B;                          \
            _Pragma("unroll")                                                     \
            for (int r = 0; r < 4; r++) {                                         \
                uint32_t so = st + soff + r * 2560;                               \
                cp16(so,              gA1 + r * rstep + koff);                    \
                cp16(so + TILE_B,     gA2 + r * rstep + koff);                    \
                cp16(so + 2*TILE_B,   gB1 + r * rstep + koff);                    \
            }                                                                     \
        }                                                                         \
        cp_commit();                                                              \
        uint32_t base = sb + (kt & 1) * STAGE_B;                                  \
        _Pragma("unroll")                                                         \
        for (int kb = 0; kb < 32; kb += 16) {                                     \
            uint32_t ah[4][4], al[4][4], bf[4][4];                                \
            _Pragma("unroll")                                                     \
            for (int mt = 0; mt < 4; mt++) {                                      \
                uint32_t o = aBase + 2 * (mt * 16 * 40 + kb);                     \
                ldmx4(ah[mt], base + o);                                          \
                ldmx4(al[mt], base + TILE_B + o);                                 \
            }                                                                     \
            _Pragma("unroll")                                                     \
            for (int g = 0; g < 4; g++) {                                         \
                uint32_t o = bBase + 2 * (g * 16 * 40 + kb);                      \
                ldmx4(bf[g], base + 2*TILE_B + o);                                \
            }                                                                     \
            _Pragma("unroll")                                                     \
            for (int mt = 0; mt < 4; mt++)                                        \
                _Pragma("unroll")                                                 \
                for (int nt = 0; nt < 8; nt++) {                                  \
                    const uint32_t* fb = &bf[nt >> 1][(nt & 1) * 2];              \
                    mma16816h(acc[mt][nt], ah[mt], fb);                           \
                    mma16816h(acc[mt][nt], al[mt], fb);                           \
                }                                                                 \
        }                                                                         \
        cp_wait0();                                                               \
        __syncthreads();                                                          \
    }

/* ---------------- Wo GEMM ---------------- */
__global__ __launch_bounds__(128, 2)
void hmma_gemm_wo(float* __restrict__ C) {
    GEMM_MAIN(g_ah, g_al, g_wo, QDIM)
    int er = lane >> 2, ec = (lane & 3) * 2;
#pragma unroll
    for (int mt = 0; mt < 4; mt++)
#pragma unroll
        for (int nt = 0; nt < 8; nt++) {
            int row = bm + wm * 64 + mt * 16 + er;
            int col = bn + wn * 64 + nt * 8 + ec;
            *(float2*)(C + (size_t)row * D_MODEL + col) =
                make_float2(acc[mt][nt][0], acc[mt][nt][1]);
            *(float2*)(C + (size_t)(row + 8) * D_MODEL + col) =
                make_float2(acc[mt][nt][2], acc[mt][nt][3]);
        }
}

/* ---------------- QKV GEMM with fused RoPE + bf16 split epilogue -------- */
__global__ __launch_bounds__(128, 2)
void hmma_gemm_qkv() {
    GEMM_MAIN(g_xh, g_xl, g_wb, D_MODEL)
    int er = lane >> 2, ec = (lane & 3) * 2;
    int head = (bn + wn * 64) >> 6;           /* 0..47 */
    if (head < N_HEADS + N_KV) {
        bool isq = head < N_HEADS;
        float scl = isq ? SCALE_L2E : 1.0f;
        __nv_bfloat16* hi = isq ? g_qhi : g_khi;
        __nv_bfloat16* lo = isq ? g_qlo : g_klo;
        int dim  = isq ? QDIM : KVDIM;
        int hcol = (isq ? head : head - N_HEADS) * HD;
#pragma unroll
        for (int mt = 0; mt < 4; mt++) {
            int row = bm + wm * 64 + mt * 16 + er;
#pragma unroll
            for (int hr = 0; hr < 2; hr++) {
                int tok = row + hr * 8;
                int s = tok & (SEQ - 1);
                int e0 = hr * 2;
#pragma unroll
                for (int nt = 0; nt < 4; nt++) {
                    int j = nt * 8 + ec;
                    float c0 = g_cos[s*32 + j],   c1 = g_cos[s*32 + j + 1];
                    float n0 = g_sin[s*32 + j],   n1 = g_sin[s*32 + j + 1];
                    float x1a = acc[mt][nt][e0],     x1b = acc[mt][nt][e0+1];
                    float x2a = acc[mt][nt+4][e0],   x2b = acc[mt][nt+4][e0+1];
                    float r1a = (x1a*c0 - x2a*n0) * scl, r1b = (x1b*c1 - x2b*n1) * scl;
                    float r2a = (x2a*c0 + x1a*n0) * scl, r2b = (x2b*c1 + x1b*n1) * scl;
                    size_t o1 = (size_t)tok * dim + hcol + j;
                    *(uint32_t*)(hi + o1)      = pk(r1a, r1b);
                    *(uint32_t*)(lo + o1)      = pk(r1a - b2f(r1a), r1b - b2f(r1b));
                    *(uint32_t*)(hi + o1 + 32) = pk(r2a, r2b);
                    *(uint32_t*)(lo + o1 + 32) = pk(r2a - b2f(r2a), r2b - b2f(r2b));
                }
            }
        }
    } else {
        int hcol = (head - N_HEADS - N_KV) * HD;
#pragma unroll
        for (int mt = 0; mt < 4; mt++) {
            int row = bm + wm * 64 + mt * 16 + er;
#pragma unroll
            for (int nt = 0; nt < 8; nt++) {
                int jj = nt * 8 + ec;
                size_t o0 = (size_t)row * KVDIM + hcol + jj;
                size_t o1 = (size_t)(row + 8) * KVDIM + hcol + jj;
                float v0 = acc[mt][nt][0], v1 = acc[mt][nt][1];
                float v2 = acc[mt][nt][2], v3 = acc[mt][nt][3];
                *(uint32_t*)(g_vhi + o0) = pk(v0, v1);
                *(uint32_t*)(g_vlo + o0) = pk(v0 - b2f(v0), v1 - b2f(v1));
                *(uint32_t*)(g_vhi + o1) = pk(v2, v3);
                *(uint32_t*)(g_vlo + o1) = pk(v2 - b2f(v2), v3 - b2f(v3));
            }
        }
    }
}

/* ---------------- HMMA flash attention (R6/R8 proven core) -------------- */
#define AS_KH 0
#define AS_KL 9216
#define AS_VH 18432
#define AS_VL 27648
#define ATTN_SMEM 36864

__global__ __launch_bounds__(256)
void attn_kernel(const int* __restrict__ cu) {
    extern __shared__ char smem[];
    uint32_t sb = smem_u32(smem);
    int qb = blockIdx.x, h = blockIdx.y, b = blockIdx.z;
    int kvh = h >> 2;
    int tid = threadIdx.x, lane = tid & 31, wid = tid >> 5;
    int wq = wid & 3, wk = wid >> 2;

    int b0 = min(max(cu[b*4+0], 0), SEQ);
    int b1 = min(max(cu[b*4+1], 0), SEQ);
    int b2 = min(max(cu[b*4+2], 0), SEQ);
    int b3 = min(max(cu[b*4+3], 0), SEQ);

    int p0 = qb * 64;
    int s_start = 0;
    if (b0 <= p0) s_start = b0;
    if (b1 <= p0) s_start = max(s_start, b1);
    if (b2 <= p0) s_start = max(s_start, b2);
    if (b3 <= p0) s_start = max(s_start, b3);
    int kb0 = s_start >> 6;

#pragma unroll
    for (int i = 0; i < 4; i++) {
        int arr = i >> 1;
        int rem = tid + (i & 1) * 256;
        int row = rem >> 3, c = rem & 7;
        const __nv_bfloat16* src = arr ? g_qlo : g_qhi;
        cp16(sb + arr*9216 + row*144 + c*16,
             src + (size_t)(b*SEQ + p0 + row) * QDIM + h*HD + c*8);
    }
    cp_commit(); cp_wait0(); __syncthreads();

    uint32_t qh[4][4], ql[4][4];
#pragma unroll
    for (int kt = 0; kt < 4; kt++) {
        uint32_t off = (uint32_t)(wq*16 + (lane & 15)) * 144 + (kt*16 + ((lane >> 4) << 3)) * 2;
        ldmx4(qh[kt], sb + off);
        ldmx4(ql[kt], sb + 9216 + off);
    }

    int qp0 = p0 + wq*16 + (lane >> 2);
    int qp1 = qp0 + 8;
    int qsg0 = (b0 <= qp0) + (b1 <= qp0) + (b2 <= qp0) + (b3 <= qp0);
    int qsg1 = (b0 <= qp1) + (b1 <= qp1) + (b2 <= qp1) + (b3 <= qp1);

    float m0 = -INFINITY, m1 = -INFINITY, l0 = 0.f, l1 = 0.f;
    float o[8][4];
#pragma unroll
    for (int nd = 0; nd < 8; nd++)
#pragma unroll
        for (int j = 0; j < 4; j++) o[nd][j] = 0.f;

    int colb = wk*32 + (lane & 3)*2;

    for (int kb = kb0; kb <= qb; kb++) {
        __syncthreads();
#pragma unroll
        for (int i = 0; i < 8; i++) {
            int arr = i >> 1;
            int rem = tid + (i & 1) * 256;
            int row = rem >> 3, c = rem & 7;
            const __nv_bfloat16* src = (arr == 0) ? g_khi : (arr == 1) ? g_klo
                                     : (arr == 2) ? g_vhi : g_vlo;
            cp16(sb + arr*9216 + row*144 + c*16,
                 src + (size_t)(b*SEQ + kb*64 + row) * KVDIM + kvh*HD + c*8);
        }
        cp_commit(); cp_wait0(); __syncthreads();

        float s[4][4];
#pragma unroll
        for (int nt = 0; nt < 4; nt++)
#pragma unroll
            for (int j = 0; j < 4; j++) s[nt][j] = 0.f;

#pragma unroll
        for (int kt = 0; kt < 4; kt++) {
            uint32_t khf[2][4], klf[2][4];
#pragma unroll
            for (int np = 0; np < 2; np++) {
                int mq = lane >> 3, r = lane & 7;
                uint32_t off = (uint32_t)(wk*32 + np*16 + ((mq & 2) ? 8 : 0) + r) * 144
                             + (kt*16 + ((mq & 1) ? 8 : 0)) * 2;
                ldmx4(khf[np], sb + AS_KH + off);
                ldmx4(klf[np], sb + AS_KL + off);
            }
#pragma unroll
            for (int nt = 0; nt < 4; nt++) {
                const uint32_t* fh = &khf[nt >> 1][(nt & 1) * 2];
                const uint32_t* fl = &klf[nt >> 1][(nt & 1) * 2];
                mma16816(s[nt], qh[kt], fh);
                mma16816(s[nt], qh[kt], fl);
                mma16816(s[nt], ql[kt], fh);
            }
        }

#pragma unroll
        for (int nt = 0; nt < 4; nt++)
#pragma unroll
            for (int e = 0; e < 2; e++) {
                int kp = kb*64 + colb + nt*8 + e;
                int sk = (b0 <= kp) + (b1 <= kp) + (b2 <= kp) + (b3 <= kp);
                if (kp > qp0 || sk != qsg0) s[nt][e]     = -INFINITY;
                if (kp > qp1 || sk != qsg1) s[nt][2 + e] = -INFINITY;
            }

        float rm0 = -INFINITY, rm1 = -INFINITY;
#pragma unroll
        for (int nt = 0; nt < 4; nt++) {
            rm0 = fmaxf(rm0, fmaxf(s[nt][0], s[nt][1]));
            rm1 = fmaxf(rm1, fmaxf(s[nt][2], s[nt][3]));
        }
        rm0 = fmaxf(rm0, __shfl_xor_sync(0xffffffffu, rm0, 1));
        rm0 = fmaxf(rm0, __shfl_xor_sync(0xffffffffu, rm0, 2));
        rm1 = fmaxf(rm1, __shfl_xor_sync(0xffffffffu, rm1, 1));
        rm1 = fmaxf(rm1, __shfl_xor_sync(0xffffffffu, rm1, 2));
        float mn0 = fmaxf(m0, rm0), mn1 = fmaxf(m1, rm1);
        bool lv0 = mn0 > -INFINITY, lv1 = mn1 > -INFINITY;
        float sc0 = lv0 ? ((m0 > -INFINITY) ? ex2(m0 - mn0) : 0.f) : 1.f;
        float sc1 = lv1 ? ((m1 > -INFINITY) ? ex2(m1 - mn1) : 0.f) : 1.f;

        float p[4][4], pl[4][4];
        float rs0 = 0.f, rs1 = 0.f;
#pragma unroll
        for (int nt = 0; nt < 4; nt++) {
#pragma unroll
            for (int e = 0; e < 2; e++) {
                float v0 = lv0 ? ex2(s[nt][e]     - mn0) : 0.f;
                float v1 = lv1 ? ex2(s[nt][2 + e] - mn1) : 0.f;
                p[nt][e] = v0;     rs0 += v0;
                p[nt][2+e] = v1;   rs1 += v1;
            }
        }
        rs0 += __shfl_xor_sync(0xffffffffu, rs0, 1);
        rs0 += __shfl_xor_sync(0xffffffffu, rs0, 2);
        rs1 += __shfl_xor_sync(0xffffffffu, rs1, 1);
        rs1 += __shfl_xor_sync(0xffffffffu, rs1, 2);
        l0 = l0 * sc0 + rs0;  m0 = mn0;
        l1 = l1 * sc1 + rs1;  m1 = mn1;
#pragma unroll
        for (int nd = 0; nd < 8; nd++) {
            o[nd][0] *= sc0; o[nd][1] *= sc0;
            o[nd][2] *= sc1; o[nd][3] *= sc1;
        }

#pragma unroll
        for (int nt = 0; nt < 4; nt++)
#pragma unroll
            for (int j = 0; j < 4; j++) {
                float hv = __bfloat162float(__float2bfloat16(p[nt][j]));
                pl[nt][j] = p[nt][j] - hv;
            }

#pragma unroll
        for (int kt2 = 0; kt2 < 2; kt2++) {
            uint32_t pah[4] = { pk(p[2*kt2][0],   p[2*kt2][1]),
                                pk(p[2*kt2][2],   p[2*kt2][3]),
                                pk(p[2*kt2+1][0], p[2*kt2+1][1]),
                                pk(p[2*kt2+1][2], p[2*kt2+1][3]) };
            uint32_t pal[4] = { pk(pl[2*kt2][0],   pl[2*kt2][1]),
                                pk(pl[2*kt2][2],   pl[2*kt2][3]),
                                pk(pl[2*kt2+1][0], pl[2*kt2+1][1]),
                                pk(pl[2*kt2+1][2], pl[2*kt2+1][3]) };
#pragma unroll
            for (int ndp = 0; ndp < 4; ndp++) {
                int mq = lane >> 3, r = lane & 7;
                uint32_t off = (uint32_t)(wk*32 + kt2*16 + ((mq & 1) ? 8 : 0) + r) * 144
                             + (ndp*16 + ((mq & 2) ? 8 : 0)) * 2;
                uint32_t vh4[4], vl4[4];
                ldmx4t(vh4, sb + AS_VH + off);
                ldmx4t(vl4, sb + AS_VL + off);
#pragma unroll
                for (int q2 = 0; q2 < 2; q2++) {
                    int nd = ndp*2 + q2;
                    mma16816(o[nd], pah, &vh4[q2*2]);
                    mma16816(o[nd], pah, &vl4[q2*2]);
                    mma16816(o[nd], pal, &vh4[q2*2]);
                }
            }
        }
    }

    __syncthreads();
    float* Osm = (float*)smem;
    float* msm = (float*)(smem + 17408);
    float* lsm = (float*)(smem + 17664);
    int rl = wq*16 + (lane >> 2);
    int c2 = (lane & 3)*2;
    if (wk == 1) {
#pragma unroll
        for (int nd = 0; nd < 8; nd++) {
            *(float2*)&Osm[rl*68 + nd*8 + c2]     = make_float2(o[nd][0], o[nd][1]);
            *(float2*)&Osm[(rl+8)*68 + nd*8 + c2] = make_float2(o[nd][2], o[nd][3]);
        }
        if ((lane & 3) == 0) {
            msm[rl] = m0; msm[rl+8] = m1;
            lsm[rl] = l0; lsm[rl+8] = l1;
        }
    }
    __syncthreads();
    if (wk == 0) {
        float pm0 = msm[rl], pm1 = msm[rl+8];
        float pl0 = lsm[rl], pl1 = lsm[rl+8];
        float M0 = fmaxf(m0, pm0), M1 = fmaxf(m1, pm1);
        float sa0 = (m0  > -INFINITY) ? ex2(m0  - M0) : 0.f;
        float sb0 = (pm0 > -INFINITY) ? ex2(pm0 - M0) : 0.f;
        float sa1 = (m1  > -INFINITY) ? ex2(m1  - M1) : 0.f;
        float sb1 = (pm1 > -INFINITY) ? ex2(pm1 - M1) : 0.f;
        float inv0 = 1.f / (l0*sa0 + pl0*sb0);
        float inv1 = 1.f / (l1*sa1 + pl1*sb1);
        size_t r0g = (size_t)(b*SEQ + p0 + rl) * QDIM + h*HD;
        size_t r1g = (size_t)(b*SEQ + p0 + rl + 8) * QDIM + h*HD;
#pragma unroll
        for (int nd = 0; nd < 8; nd++) {
            float v0 = (o[nd][0]*sa0 + Osm[rl*68 + nd*8 + c2]*sb0) * inv0;
            float v1 = (o[nd][1]*sa0 + Osm[rl*68 + nd*8 + c2 + 1]*sb0) * inv0;
            float v2 = (o[nd][2]*sa1 + Osm[(rl+8)*68 + nd*8 + c2]*sb1) * inv1;
            float v3 = (o[nd][3]*sa1 + Osm[(rl+8)*68 + nd*8 + c2 + 1]*sb1) * inv1;
            *(uint32_t*)(g_ah + r0g + nd*8 + c2) = pkh(v0, v1);
            *(uint32_t*)(g_al + r0g + nd*8 + c2) = pkh(v0 - h2f(v0), v1 - h2f(v1));
            *(uint32_t*)(g_ah + r1g + nd*8 + c2) = pkh(v2, v3);
            *(uint32_t*)(g_al + r1g + nd*8 + c2) = pkh(v2 - h2f(v2), v3 - h2f(v3));
        }
    }
}

/* ------------------------------------------------------------------ */
extern "C" void kernel_launch(void* const* d_in, const int* in_sizes, int n_in,
                              void* d_out, int out_size) {
    const float* x  = (const float*)d_in[0];
    const int*   cu = (const int*)  d_in[1];
    const float* Wq = (const float*)d_in[2];
    const float* Wk = (const float*)d_in[3];
    const float* Wv = (const float*)d_in[4];
    const float* Wo = (const float*)d_in[5];
    float* out = (float*)d_out;

    cudaFuncSetAttribute(attn_kernel,
                         cudaFuncAttributeMaxDynamicSharedMemorySize, ATTN_SMEM);
    cudaFuncSetAttribute(hmma_gemm_wo,
                         cudaFuncAttributeMaxDynamicSharedMemorySize, GEMM_SMEM);
    cudaFuncSetAttribute(hmma_gemm_qkv,
                         cudaFuncAttributeMaxDynamicSharedMemorySize, GEMM_SMEM);

    /* prep */
    rope_table_kernel<<<(SEQ*(HD/2) + 255)/256, 256>>>();
    splitx_kernel<<<(NTOK*D_MODEL/4 + 255)/256, 256>>>(x, NTOK*D_MODEL/4);
    tconv_qkv_kernel<<<dim3(QKVDIM/32, D_MODEL/32), dim3(32,8)>>>(Wq, Wk, Wv);
    tconv_wo_kernel<<<dim3(D_MODEL/32, QDIM/32), dim3(32,8)>>>(Wo);

    /* merged QKV projection with fused rope+split epilogue */
    hmma_gemm_qkv<<<dim3(QKVDIM/128, NTOK/128), 128, GEMM_SMEM>>>();

    /* attention */
    attn_kernel<<<dim3(SEQ/64, N_HEADS, BATCH), 256, ATTN_SMEM>>>(cu);

    /* output projection */
    hmma_gemm_wo<<<dim3(D_MODEL/128, NTOK/128), 128, GEMM_SMEM>>>(out);
}

// round 12
// speedup vs baseline: 1.5120x; 1.0826x over previous
#include <cuda_runtime.h>
#include <cuda_bf16.h>
#include <cuda_fp16.h>
#include <math.h>
#include <stdint.h>

#define D_MODEL 2048
#define N_HEADS 32
#define N_KV    8
#define HD      64
#define SEQ     2048
#define BATCH   2
#define NTOK    (BATCH*SEQ)      /* 4096 */
#define QDIM    (N_HEADS*HD)     /* 2048 */
#define KVDIM   (N_KV*HD)        /* 512  */
#define QKVDIM  (QDIM + 2*KVDIM) /* 3072 */
#define ROPE_BASE 500000.0f
#define SCALE_L2E 0.1803368801111204f   /* 0.125 * log2(e) */

/* ---------------- static device scratch ---------------- */
__device__ float g_cos[SEQ*(HD/2)];
__device__ float g_sin[SEQ*(HD/2)];

/* GEMM operands: fp16. Activations split hi/lo, weights single. */
__device__ __half g_xh [NTOK*D_MODEL];
__device__ __half g_xl [NTOK*D_MODEL];
__device__ __half g_wb [QKVDIM*D_MODEL];   /* packed Wq|Wk|Wv, [N,K] */
__device__ __half g_wo [D_MODEL*QDIM];
__device__ __half g_ah [NTOK*QDIM];        /* attention out hi */
__device__ __half g_al [NTOK*QDIM];        /* attention out lo */

/* attention operands (fp16; q unscaled hi/lo, k/v single) */
__device__ __half g_qh2[NTOK*QDIM];
__device__ __half g_ql2[NTOK*QDIM];
__device__ __half g_kf [NTOK*KVDIM];
__device__ __half g_vf [NTOK*KVDIM];

/* ---------------- PTX helpers ---------------- */
__device__ __forceinline__ uint32_t smem_u32(const void* p) {
    uint32_t a;
    asm("{ .reg .u64 t; cvta.to.shared.u64 t, %1; cvt.u32.u64 %0, t; }" : "=r"(a) : "l"(p));
    return a;
}
__device__ __forceinline__ void cp16(uint32_t saddr, const void* g) {
    asm volatile("cp.async.cg.shared.global [%0], [%1], 16;" :: "r"(saddr), "l"(g));
}
__device__ __forceinline__ void cp_commit() { asm volatile("cp.async.commit_group;" ::: "memory"); }
__device__ __forceinline__ void cp_wait0()  { asm volatile("cp.async.wait_group 0;"  ::: "memory"); }

__device__ __forceinline__ void ldmx4(uint32_t* r, uint32_t addr) {
    asm volatile("ldmatrix.sync.aligned.m8n8.x4.shared.b16 {%0,%1,%2,%3}, [%4];"
                 : "=r"(r[0]), "=r"(r[1]), "=r"(r[2]), "=r"(r[3]) : "r"(addr));
}
__device__ __forceinline__ void ldmx4t(uint32_t* r, uint32_t addr) {
    asm volatile("ldmatrix.sync.aligned.m8n8.x4.trans.shared.b16 {%0,%1,%2,%3}, [%4];"
                 : "=r"(r[0]), "=r"(r[1]), "=r"(r[2]), "=r"(r[3]) : "r"(addr));
}
/* fp16 mma */
__device__ __forceinline__ void mma16816h(float* d, const uint32_t* a, const uint32_t* b) {
    asm volatile(
        "mma.sync.aligned.m16n8k16.row.col.f32.f16.f16.f32 "
        "{%0,%1,%2,%3}, {%4,%5,%6,%7}, {%8,%9}, {%0,%1,%2,%3};"
        : "+f"(d[0]), "+f"(d[1]), "+f"(d[2]), "+f"(d[3])
        : "r"(a[0]), "r"(a[1]), "r"(a[2]), "r"(a[3]), "r"(b[0]), "r"(b[1]));
}
__device__ __forceinline__ float ex2(float x) {
    float y; asm("ex2.approx.f32 %0, %1;" : "=f"(y) : "f"(x)); return y;
}
__device__ __forceinline__ uint32_t pkh(float a, float b) {
    __half2 t = __floats2half2_rn(a, b);
    return *(uint32_t*)&t;
}
__device__ __forceinline__ float h2f(float v) {
    return __half2float(__float2half_rn(v));
}

/* ---------------- prep kernels ---------------- */
__global__ __launch_bounds__(256) void splitx_kernel(const float* __restrict__ src, int n4) {
    int i = blockIdx.x * blockDim.x + threadIdx.x;
    if (i >= n4) return;
    float4 v = ((const float4*)src)[i];
    float vv[4] = {v.x, v.y, v.z, v.w};
    __half h[4], l[4];
#pragma unroll
    for (int j = 0; j < 4; j++) {
        h[j] = __float2half_rn(vv[j]);
        l[j] = __float2half_rn(vv[j] - __half2float(h[j]));
    }
    ((uint2*)g_xh)[i] = *(uint2*)h;
    ((uint2*)g_xl)[i] = *(uint2*)l;
}

__global__ __launch_bounds__(256) void tconv_qkv_kernel(const float* __restrict__ Wq,
                                                        const float* __restrict__ Wk,
                                                        const float* __restrict__ Wv) {
    __shared__ float t[32][33];
    int np = blockIdx.x * 32;
    int k0 = blockIdx.y * 32;
    const float* W;
    int N, off;
    if (np < QDIM)              { W = Wq; N = QDIM;  off = 0; }
    else if (np < QDIM + KVDIM) { W = Wk; N = KVDIM; off = QDIM; }
    else                        { W = Wv; N = KVDIM; off = QDIM + KVDIM; }
    int n0 = np - off;
    int tx = threadIdx.x, ty = threadIdx.y;
#pragma unroll
    for (int i = 0; i < 32; i += 8)
        t[ty + i][tx] = W[(size_t)(k0 + ty + i) * N + n0 + tx];
    __syncthreads();
#pragma unroll
    for (int i = 0; i < 32; i += 8)
        g_wb[(size_t)(np + ty + i) * D_MODEL + k0 + tx] = __float2half_rn(t[tx][ty + i]);
}

__global__ __launch_bounds__(256) void tconv_wo_kernel(const float* __restrict__ W) {
    __shared__ float t[32][33];
    int n0 = blockIdx.x * 32, k0 = blockIdx.y * 32;
    int tx = threadIdx.x, ty = threadIdx.y;
#pragma unroll
    for (int i = 0; i < 32; i += 8)
        t[ty + i][tx] = W[(size_t)(k0 + ty + i) * D_MODEL + n0 + tx];
    __syncthreads();
#pragma unroll
    for (int i = 0; i < 32; i += 8)
        g_wo[(size_t)(n0 + ty + i) * QDIM + k0 + tx] = __float2half_rn(t[tx][ty + i]);
}

/* ---------------- RoPE table (fp32) ---------------- */
__global__ void rope_table_kernel() {
    int i = blockIdx.x * blockDim.x + threadIdx.x;
    if (i >= SEQ * (HD/2)) return;
    int t = i >> 5;
    int j = i & 31;
    float ex = (float)j * (1.0f / 32.0f);
    float inv = powf(ROPE_BASE, -ex);
    float ang = (float)t * inv;
    float s, c;
    sincosf(ang, &s, &c);
    g_cos[i] = c;
    g_sin[i] = s;
}

/* ---------------- fp16x2 GEMM mainloop macro ---------------- */
#define TILE_B   10240
#define STAGE_B  (3*TILE_B)
#define GEMM_SMEM (2*STAGE_B)

#define GEMM_MAIN(Ahi, Alo, Bp, Kdim)                                             \
    extern __shared__ char smem[];                                                \
    uint32_t sb = smem_u32(smem);                                                 \
    int tid = threadIdx.x, lane = tid & 31, wid = tid >> 5;                       \
    int wm = wid & 1, wn = wid >> 1;                                              \
    int bm = blockIdx.y * 128, bn = blockIdx.x * 128;                             \
    int lr = tid >> 2;                                                            \
    int lc = tid & 3;                                                             \
    const __half* gA1 = (Ahi) + (size_t)(bm + lr) * (Kdim) + lc * 8;              \
    const __half* gA2 = (Alo) + (size_t)(bm + lr) * (Kdim) + lc * 8;              \
    const __half* gB1 = (Bp)  + (size_t)(bn + lr) * (Kdim) + lc * 8;              \
    size_t rstep = (size_t)32 * (Kdim);                                           \
    uint32_t soff = lr * 80 + lc * 16;                                            \
    float acc[4][8][4];                                                           \
    _Pragma("unroll")                                                             \
    for (int i = 0; i < 4; i++)                                                   \
        _Pragma("unroll")                                                         \
        for (int j = 0; j < 8; j++)                                               \
            _Pragma("unroll")                                                     \
            for (int t = 0; t < 4; t++) acc[i][j][t] = 0.f;                       \
    int nkt = (Kdim) >> 5;                                                        \
    {                                                                             \
        _Pragma("unroll")                                                         \
        for (int r = 0; r < 4; r++) {                                             \
            uint32_t so = sb + soff + r * 2560;                                   \
            cp16(so,              gA1 + r * rstep);                               \
            cp16(so + TILE_B,     gA2 + r * rstep);                               \
            cp16(so + 2*TILE_B,   gB1 + r * rstep);                               \
        }                                                                         \
    }                                                                             \
    cp_commit(); cp_wait0(); __syncthreads();                                     \
    uint32_t aBase = 2 * ((uint32_t)(wm * 64 + (lane & 15)) * 40 + ((lane >> 4) << 3)); \
    uint32_t bBase = 2 * ((uint32_t)(wn * 64 + (lane & 7) + ((lane >> 4) << 3)) * 40 + (lane & 8)); \
    for (int kt = 0; kt < nkt; kt++) {                                            \
        if (kt + 1 < nkt) {                                                       \
            int koff = (kt + 1) << 5;                                             \
            uint32_t st = sb + ((kt + 1) & 1) * STAGE_B;                          \
            _Pragma("unroll")                                                     \
            for (int r = 0; r < 4; r++) {                                         \
                uint32_t so = st + soff + r * 2560;                               \
                cp16(so,              gA1 + r * rstep + koff);                    \
                cp16(so + TILE_B,     gA2 + r * rstep + koff);                    \
                cp16(so + 2*TILE_B,   gB1 + r * rstep + koff);                    \
            }                                                                     \
        }                                                                         \
        cp_commit();                                                              \
        uint32_t base = sb + (kt & 1) * STAGE_B;                                  \
        _Pragma("unroll")                                                         \
        for (int kb = 0; kb < 32; kb += 16) {                                     \
            uint32_t ah[4][4], al[4][4], bf[4][4];                                \
            _Pragma("unroll")                                                     \
            for (int mt = 0; mt < 4; mt++) {                                      \
                uint32_t o = aBase + 2 * (mt * 16 * 40 + kb);                     \
                ldmx4(ah[mt], base + o);                                          \
                ldmx4(al[mt], base + TILE_B + o);                                 \
            }                                                                     \
            _Pragma("unroll")                                                     \
            for (int g = 0; g < 4; g++) {                                         \
                uint32_t o = bBase + 2 * (g * 16 * 40 + kb);                      \
                ldmx4(bf[g], base + 2*TILE_B + o);                                \
            }                                                                     \
            _Pragma("unroll")                                                     \
            for (int mt = 0; mt < 4; mt++)                                        \
                _Pragma("unroll")                                                 \
                for (int nt = 0; nt < 8; nt++) {                                  \
                    const uint32_t* fb = &bf[nt >> 1][(nt & 1) * 2];              \
                    mma16816h(acc[mt][nt], ah[mt], fb);                           \
                    mma16816h(acc[mt][nt], al[mt], fb);                           \
                }                                                                 \
        }                                                                         \
        cp_wait0();                                                               \
        __syncthreads();                                                          \
    }

/* ---------------- Wo GEMM ---------------- */
__global__ __launch_bounds__(128, 2)
void hmma_gemm_wo(float* __restrict__ C) {
    GEMM_MAIN(g_ah, g_al, g_wo, QDIM)
    int er = lane >> 2, ec = (lane & 3) * 2;
#pragma unroll
    for (int mt = 0; mt < 4; mt++)
#pragma unroll
        for (int nt = 0; nt < 8; nt++) {
            int row = bm + wm * 64 + mt * 16 + er;
            int col = bn + wn * 64 + nt * 8 + ec;
            *(float2*)(C + (size_t)row * D_MODEL + col) =
                make_float2(acc[mt][nt][0], acc[mt][nt][1]);
            *(float2*)(C + (size_t)(row + 8) * D_MODEL + col) =
                make_float2(acc[mt][nt][2], acc[mt][nt][3]);
        }
}

/* ---------------- QKV GEMM with fused RoPE + fp16 epilogue -------------- */
__global__ __launch_bounds__(128, 2)
void hmma_gemm_qkv() {
    GEMM_MAIN(g_xh, g_xl, g_wb, D_MODEL)
    int er = lane >> 2, ec = (lane & 3) * 2;
    int head = (bn + wn * 64) >> 6;           /* 0..47 */
    if (head < N_HEADS + N_KV) {
        bool isq = head < N_HEADS;
        int dim  = isq ? QDIM : KVDIM;
        int hcol = (isq ? head : head - N_HEADS) * HD;
#pragma unroll
        for (int mt = 0; mt < 4; mt++) {
            int row = bm + wm * 64 + mt * 16 + er;
#pragma unroll
            for (int hr = 0; hr < 2; hr++) {
                int tok = row + hr * 8;
                int s = tok & (SEQ - 1);
                int e0 = hr * 2;
#pragma unroll
                for (int nt = 0; nt < 4; nt++) {
                    int j = nt * 8 + ec;
                    float c0 = g_cos[s*32 + j],   c1 = g_cos[s*32 + j + 1];
                    float n0 = g_sin[s*32 + j],   n1 = g_sin[s*32 + j + 1];
                    float x1a = acc[mt][nt][e0],     x1b = acc[mt][nt][e0+1];
                    float x2a = acc[mt][nt+4][e0],   x2b = acc[mt][nt+4][e0+1];
                    float r1a = x1a*c0 - x2a*n0, r1b = x1b*c1 - x2b*n1;
                    float r2a = x2a*c0 + x1a*n0, r2b = x2b*c1 + x1b*n1;
                    size_t o1 = (size_t)tok * dim + hcol + j;
                    if (isq) {
                        *(uint32_t*)(g_qh2 + o1)      = pkh(r1a, r1b);
                        *(uint32_t*)(g_ql2 + o1)      = pkh(r1a - h2f(r1a), r1b - h2f(r1b));
                        *(uint32_t*)(g_qh2 + o1 + 32) = pkh(r2a, r2b);
                        *(uint32_t*)(g_ql2 + o1 + 32) = pkh(r2a - h2f(r2a), r2b - h2f(r2b));
                    } else {
                        *(uint32_t*)(g_kf + o1)      = pkh(r1a, r1b);
                        *(uint32_t*)(g_kf + o1 + 32) = pkh(r2a, r2b);
                    }
                }
            }
        }
    } else {
        int hcol = (head - N_HEADS - N_KV) * HD;
#pragma unroll
        for (int mt = 0; mt < 4; mt++) {
            int row = bm + wm * 64 + mt * 16 + er;
#pragma unroll
            for (int nt = 0; nt < 8; nt++) {
                int jj = nt * 8 + ec;
                *(uint32_t*)(g_vf + (size_t)row * KVDIM + hcol + jj) =
                    pkh(acc[mt][nt][0], acc[mt][nt][1]);
                *(uint32_t*)(g_vf + (size_t)(row + 8) * KVDIM + hcol + jj) =
                    pkh(acc[mt][nt][2], acc[mt][nt][3]);
            }
        }
    }
}

/* ---------------- fp16 flash attention ----------------
 * q-block 64, kv-block 64. 8 warps: wq (16 q rows), wk (kv half).
 * Q hi/lo fp16 (unscaled), K/V single fp16; scale applied to scores.
 * smem: stage = K(9216) | V(9216); Q staged in same space initially.
 */
#define AS_K 0
#define AS_V 9216
#define ATTN_SMEM 18432

__global__ __launch_bounds__(256)
void attn_kernel(const int* __restrict__ cu) {
    extern __shared__ char smem[];
    uint32_t sb = smem_u32(smem);
    int qb = blockIdx.x, h = blockIdx.y, b = blockIdx.z;
    int kvh = h >> 2;
    int tid = threadIdx.x, lane = tid & 31, wid = tid >> 5;
    int wq = wid & 3, wk = wid >> 2;

    int b0 = min(max(cu[b*4+0], 0), SEQ);
    int b1 = min(max(cu[b*4+1], 0), SEQ);
    int b2 = min(max(cu[b*4+2], 0), SEQ);
    int b3 = min(max(cu[b*4+3], 0), SEQ);

    int p0 = qb * 64;
    int s_start = 0;
    if (b0 <= p0) s_start = b0;
    if (b1 <= p0) s_start = max(s_start, b1);
    if (b2 <= p0) s_start = max(s_start, b2);
    if (b3 <= p0) s_start = max(s_start, b3);
    int kb0 = s_start >> 6;

    /* stage Q hi/lo (64 x 64 fp16 each) */
#pragma unroll
    for (int i = 0; i < 4; i++) {
        int arr = i >> 1;
        int rem = tid + (i & 1) * 256;
        int row = rem >> 3, c = rem & 7;
        const __half* src = arr ? g_ql2 : g_qh2;
        cp16(sb + arr*9216 + row*144 + c*16,
             src + (size_t)(b*SEQ + p0 + row) * QDIM + h*HD + c*8);
    }
    cp_commit(); cp_wait0(); __syncthreads();

    uint32_t qh[4][4], ql[4][4];
#pragma unroll
    for (int kt = 0; kt < 4; kt++) {
        uint32_t off = (uint32_t)(wq*16 + (lane & 15)) * 144 + (kt*16 + ((lane >> 4) << 3)) * 2;
        ldmx4(qh[kt], sb + off);
        ldmx4(ql[kt], sb + 9216 + off);
    }
    __syncthreads();  /* Q smem consumed; KV staging may overwrite */

    int qp0 = p0 + wq*16 + (lane >> 2);
    int qp1 = qp0 + 8;
    int qsg0 = (b0 <= qp0) + (b1 <= qp0) + (b2 <= qp0) + (b3 <= qp0);
    int qsg1 = (b0 <= qp1) + (b1 <= qp1) + (b2 <= qp1) + (b3 <= qp1);

    float m0 = -INFINITY, m1 = -INFINITY, l0 = 0.f, l1 = 0.f;
    float o[8][4];
#pragma unroll
    for (int nd = 0; nd < 8; nd++)
#pragma unroll
        for (int j = 0; j < 4; j++) o[nd][j] = 0.f;

    int colb = wk*32 + (lane & 3)*2;

    for (int kb = kb0; kb <= qb; kb++) {
        __syncthreads();
#pragma unroll
        for (int i = 0; i < 4; i++) {
            int arr = i >> 1;
            int rem = tid + (i & 1) * 256;
            int row = rem >> 3, c = rem & 7;
            const __half* src = arr ? g_vf : g_kf;
            cp16(sb + arr*9216 + row*144 + c*16,
                 src + (size_t)(b*SEQ + kb*64 + row) * KVDIM + kvh*HD + c*8);
        }
        cp_commit(); cp_wait0(); __syncthreads();

        /* S = Q K^T (fp16 split-A x single-B) */
        float s[4][4];
#pragma unroll
        for (int nt = 0; nt < 4; nt++)
#pragma unroll
            for (int j = 0; j < 4; j++) s[nt][j] = 0.f;

#pragma unroll
        for (int kt = 0; kt < 4; kt++) {
            uint32_t khf[2][4];
#pragma unroll
            for (int np = 0; np < 2; np++) {
                int mq = lane >> 3, r = lane & 7;
                uint32_t off = (uint32_t)(wk*32 + np*16 + ((mq & 2) ? 8 : 0) + r) * 144
                             + (kt*16 + ((mq & 1) ? 8 : 0)) * 2;
                ldmx4(khf[np], sb + AS_K + off);
            }
#pragma unroll
            for (int nt = 0; nt < 4; nt++) {
                const uint32_t* fh = &khf[nt >> 1][(nt & 1) * 2];
                mma16816h(s[nt], qh[kt], fh);
                mma16816h(s[nt], ql[kt], fh);
            }
        }

        /* scale to base-2 logits, then mask */
#pragma unroll
        for (int nt = 0; nt < 4; nt++)
#pragma unroll
            for (int j = 0; j < 4; j++) s[nt][j] *= SCALE_L2E;

#pragma unroll
        for (int nt = 0; nt < 4; nt++)
#pragma unroll
            for (int e = 0; e < 2; e++) {
                int kp = kb*64 + colb + nt*8 + e;
                int sk = (b0 <= kp) + (b1 <= kp) + (b2 <= kp) + (b3 <= kp);
                if (kp > qp0 || sk != qsg0) s[nt][e]     = -INFINITY;
                if (kp > qp1 || sk != qsg1) s[nt][2 + e] = -INFINITY;
            }

        float rm0 = -INFINITY, rm1 = -INFINITY;
#pragma unroll
        for (int nt = 0; nt < 4; nt++) {
            rm0 = fmaxf(rm0, fmaxf(s[nt][0], s[nt][1]));
            rm1 = fmaxf(rm1, fmaxf(s[nt][2], s[nt][3]));
        }
        rm0 = fmaxf(rm0, __shfl_xor_sync(0xffffffffu, rm0, 1));
        rm0 = fmaxf(rm0, __shfl_xor_sync(0xffffffffu, rm0, 2));
        rm1 = fmaxf(rm1, __shfl_xor_sync(0xffffffffu, rm1, 1));
        rm1 = fmaxf(rm1, __shfl_xor_sync(0xffffffffu, rm1, 2));
        float mn0 = fmaxf(m0, rm0), mn1 = fmaxf(m1, rm1);
        bool lv0 = mn0 > -INFINITY, lv1 = mn1 > -INFINITY;
        float sc0 = lv0 ? ((m0 > -INFINITY) ? ex2(m0 - mn0) : 0.f) : 1.f;
        float sc1 = lv1 ? ((m1 > -INFINITY) ? ex2(m1 - mn1) : 0.f) : 1.f;

        float p[4][4], pl[4][4];
        float rs0 = 0.f, rs1 = 0.f;
#pragma unroll
        for (int nt = 0; nt < 4; nt++) {
#pragma unroll
            for (int e = 0; e < 2; e++) {
                float v0 = lv0 ? ex2(s[nt][e]     - mn0) : 0.f;
                float v1 = lv1 ? ex2(s[nt][2 + e] - mn1) : 0.f;
                p[nt][e] = v0;     rs0 += v0;
                p[nt][2+e] = v1;   rs1 += v1;
            }
        }
        rs0 += __shfl_xor_sync(0xffffffffu, rs0, 1);
        rs0 += __shfl_xor_sync(0xffffffffu, rs0, 2);
        rs1 += __shfl_xor_sync(0xffffffffu, rs1, 1);
        rs1 += __shfl_xor_sync(0xffffffffu, rs1, 2);
        l0 = l0 * sc0 + rs0;  m0 = mn0;
        l1 = l1 * sc1 + rs1;  m1 = mn1;
#pragma unroll
        for (int nd = 0; nd < 8; nd++) {
            o[nd][0] *= sc0; o[nd][1] *= sc0;
            o[nd][2] *= sc1; o[nd][3] *= sc1;
        }

        /* P hi/lo (fp16) */
#pragma unroll
        for (int nt = 0; nt < 4; nt++)
#pragma unroll
            for (int j = 0; j < 4; j++)
                pl[nt][j] = p[nt][j] - h2f(p[nt][j]);

        /* O += P V (split-A x single-B) */
#pragma unroll
        for (int kt2 = 0; kt2 < 2; kt2++) {
            uint32_t pah[4] = { pkh(p[2*kt2][0],   p[2*kt2][1]),
                                pkh(p[2*kt2][2],   p[2*kt2][3]),
                                pkh(p[2*kt2+1][0], p[2*kt2+1][1]),
                                pkh(p[2*kt2+1][2], p[2*kt2+1][3]) };
            uint32_t pal[4] = { pkh(pl[2*kt2][0],   pl[2*kt2][1]),
                                pkh(pl[2*kt2][2],   pl[2*kt2][3]),
                                pkh(pl[2*kt2+1][0], pl[2*kt2+1][1]),
                                pkh(pl[2*kt2+1][2], pl[2*kt2+1][3]) };
#pragma unroll
            for (int ndp = 0; ndp < 4; ndp++) {
                int mq = lane >> 3, r = lane & 7;
                uint32_t off = (uint32_t)(wk*32 + kt2*16 + ((mq & 1) ? 8 : 0) + r) * 144
                             + (ndp*16 + ((mq & 2) ? 8 : 0)) * 2;
                uint32_t vh4[4];
                ldmx4t(vh4, sb + AS_V + off);
#pragma unroll
                for (int q2 = 0; q2 < 2; q2++) {
                    int nd = ndp*2 + q2;
                    mma16816h(o[nd], pah, &vh4[q2*2]);
                    mma16816h(o[nd], pal, &vh4[q2*2]);
                }
            }
        }
    }

    /* merge kv-halves via smem */
    __syncthreads();
    float* Osm = (float*)smem;
    float* msm = (float*)(smem + 17408);
    float* lsm = (float*)(smem + 17664);
    int rl = wq*16 + (lane >> 2);
    int c2 = (lane & 3)*2;
    if (wk == 1) {
#pragma unroll
        for (int nd = 0; nd < 8; nd++) {
            *(float2*)&Osm[rl*68 + nd*8 + c2]     = make_float2(o[nd][0], o[nd][1]);
            *(float2*)&Osm[(rl+8)*68 + nd*8 + c2] = make_float2(o[nd][2], o[nd][3]);
        }
        if ((lane & 3) == 0) {
            msm[rl] = m0; msm[rl+8] = m1;
            lsm[rl] = l0; lsm[rl+8] = l1;
        }
    }
    __syncthreads();
    if (wk == 0) {
        float pm0 = msm[rl], pm1 = msm[rl+8];
        float pl0 = lsm[rl], pl1 = lsm[rl+8];
        float M0 = fmaxf(m0, pm0), M1 = fmaxf(m1, pm1);
        float sa0 = (m0  > -INFINITY) ? ex2(m0  - M0) : 0.f;
        float sb0 = (pm0 > -INFINITY) ? ex2(pm0 - M0) : 0.f;
        float sa1 = (m1  > -INFINITY) ? ex2(m1  - M1) : 0.f;
        float sb1 = (pm1 > -INFINITY) ? ex2(pm1 - M1) : 0.f;
        float inv0 = 1.f / (l0*sa0 + pl0*sb0);
        float inv1 = 1.f / (l1*sa1 + pl1*sb1);
        size_t r0g = (size_t)(b*SEQ + p0 + rl) * QDIM + h*HD;
        size_t r1g = (size_t)(b*SEQ + p0 + rl + 8) * QDIM + h*HD;
#pragma unroll
        for (int nd = 0; nd < 8; nd++) {
            float v0 = (o[nd][0]*sa0 + Osm[rl*68 + nd*8 + c2]*sb0) * inv0;
            float v1 = (o[nd][1]*sa0 + Osm[rl*68 + nd*8 + c2 + 1]*sb0) * inv0;
            float v2 = (o[nd][2]*sa1 + Osm[(rl+8)*68 + nd*8 + c2]*sb1) * inv1;
            float v3 = (o[nd][3]*sa1 + Osm[(rl+8)*68 + nd*8 + c2 + 1]*sb1) * inv1;
            *(uint32_t*)(g_ah + r0g + nd*8 + c2) = pkh(v0, v1);
            *(uint32_t*)(g_al + r0g + nd*8 + c2) = pkh(v0 - h2f(v0), v1 - h2f(v1));
            *(uint32_t*)(g_ah + r1g + nd*8 + c2) = pkh(v2, v3);
            *(uint32_t*)(g_al + r1g + nd*8 + c2) = pkh(v2 - h2f(v2), v3 - h2f(v3));
        }
    }
}

/* ------------------------------------------------------------------ */
extern "C" void kernel_launch(void* const* d_in, const int* in_sizes, int n_in,
                              void* d_out, int out_size) {
    const float* x  = (const float*)d_in[0];
    const int*   cu = (const int*)  d_in[1];
    const float* Wq = (const float*)d_in[2];
    const float* Wk = (const float*)d_in[3];
    const float* Wv = (const float*)d_in[4];
    const float* Wo = (const float*)d_in[5];
    float* out = (float*)d_out;

    cudaFuncSetAttribute(attn_kernel,
                         cudaFuncAttributeMaxDynamicSharedMemorySize, ATTN_SMEM);
    cudaFuncSetAttribute(hmma_gemm_wo,
                         cudaFuncAttributeMaxDynamicSharedMemorySize, GEMM_SMEM);
    cudaFuncSetAttribute(hmma_gemm_qkv,
                         cudaFuncAttributeMaxDynamicSharedMemorySize, GEMM_SMEM);

    /* prep */
    rope_table_kernel<<<(SEQ*(HD/2) + 255)/256, 256>>>();
    splitx_kernel<<<(NTOK*D_MODEL/4 + 255)/256, 256>>>(x, NTOK*D_MODEL/4);
    tconv_qkv_kernel<<<dim3(QKVDIM/32, D_MODEL/32), dim3(32,8)>>>(Wq, Wk, Wv);
    tconv_wo_kernel<<<dim3(D_MODEL/32, QDIM/32), dim3(32,8)>>>(Wo);

    /* merged QKV projection with fused rope+fp16 epilogue */
    hmma_gemm_qkv<<<dim3(QKVDIM/128, NTOK/128), 128, GEMM_SMEM>>>();

    /* attention */
    attn_kernel<<<dim3(SEQ/64, N_HEADS, BATCH), 256, ATTN_SMEM>>>(cu);

    /* output projection */
    hmma_gemm_wo<<<dim3(D_MODEL/128, NTOK/128), 128, GEMM_SMEM>>>(out);
}

// round 13
// speedup vs baseline: 2.1996x; 1.4548x over previous
#include <cuda_runtime.h>
#include <cuda_bf16.h>
#include <cuda_fp16.h>
#include <math.h>
#include <stdint.h>

#define D_MODEL 2048
#define N_HEADS 32
#define N_KV    8
#define HD      64
#define SEQ     2048
#define BATCH   2
#define NTOK    (BATCH*SEQ)      /* 4096 */
#define QDIM    (N_HEADS*HD)     /* 2048 */
#define KVDIM   (N_KV*HD)        /* 512  */
#define QKVDIM  (QDIM + 2*KVDIM) /* 3072 */
#define ROPE_BASE 500000.0f
#define SCALE_L2E 0.1803368801111204f   /* 0.125 * log2(e) */

/* ---------------- static device scratch ---------------- */
__device__ float g_cos[SEQ*(HD/2)];
__device__ float g_sin[SEQ*(HD/2)];

/* GEMM operands: single fp16 */
__device__ __half g_x  [NTOK*D_MODEL];
__device__ __half g_wb [QKVDIM*D_MODEL];   /* packed Wq|Wk|Wv, [N,K] */
__device__ __half g_wo [D_MODEL*QDIM];
__device__ __half g_ao [NTOK*QDIM];        /* attention out */

/* attention operands (fp16; q unscaled hi/lo, k/v single) */
__device__ __half g_qh2[NTOK*QDIM];
__device__ __half g_ql2[NTOK*QDIM];
__device__ __half g_kf [NTOK*KVDIM];
__device__ __half g_vf [NTOK*KVDIM];

/* ---------------- PTX helpers ---------------- */
__device__ __forceinline__ uint32_t smem_u32(const void* p) {
    uint32_t a;
    asm("{ .reg .u64 t; cvta.to.shared.u64 t, %1; cvt.u32.u64 %0, t; }" : "=r"(a) : "l"(p));
    return a;
}
__device__ __forceinline__ void cp16(uint32_t saddr, const void* g) {
    asm volatile("cp.async.cg.shared.global [%0], [%1], 16;" :: "r"(saddr), "l"(g));
}
__device__ __forceinline__ void cp_commit() { asm volatile("cp.async.commit_group;" ::: "memory"); }
__device__ __forceinline__ void cp_wait0()  { asm volatile("cp.async.wait_group 0;"  ::: "memory"); }

__device__ __forceinline__ void ldmx4(uint32_t* r, uint32_t addr) {
    asm volatile("ldmatrix.sync.aligned.m8n8.x4.shared.b16 {%0,%1,%2,%3}, [%4];"
                 : "=r"(r[0]), "=r"(r[1]), "=r"(r[2]), "=r"(r[3]) : "r"(addr));
}
__device__ __forceinline__ void ldmx4t(uint32_t* r, uint32_t addr) {
    asm volatile("ldmatrix.sync.aligned.m8n8.x4.trans.shared.b16 {%0,%1,%2,%3}, [%4];"
                 : "=r"(r[0]), "=r"(r[1]), "=r"(r[2]), "=r"(r[3]) : "r"(addr));
}
__device__ __forceinline__ void mma16816h(float* d, const uint32_t* a, const uint32_t* b) {
    asm volatile(
        "mma.sync.aligned.m16n8k16.row.col.f32.f16.f16.f32 "
        "{%0,%1,%2,%3}, {%4,%5,%6,%7}, {%8,%9}, {%0,%1,%2,%3};"
        : "+f"(d[0]), "+f"(d[1]), "+f"(d[2]), "+f"(d[3])
        : "r"(a[0]), "r"(a[1]), "r"(a[2]), "r"(a[3]), "r"(b[0]), "r"(b[1]));
}
__device__ __forceinline__ float ex2(float x) {
    float y; asm("ex2.approx.f32 %0, %1;" : "=f"(y) : "f"(x)); return y;
}
__device__ __forceinline__ uint32_t pkh(float a, float b) {
    __half2 t = __floats2half2_rn(a, b);
    return *(uint32_t*)&t;
}
__device__ __forceinline__ float h2f(float v) {
    return __half2float(__float2half_rn(v));
}

/* ---------------- prep kernels ---------------- */
__global__ __launch_bounds__(256) void convx_kernel(const float* __restrict__ src, int n4) {
    int i = blockIdx.x * blockDim.x + threadIdx.x;
    if (i >= n4) return;
    float4 v = ((const float4*)src)[i];
    __half h[4] = { __float2half_rn(v.x), __float2half_rn(v.y),
                    __float2half_rn(v.z), __float2half_rn(v.w) };
    ((uint2*)g_x)[i] = *(uint2*)h;
}

__global__ __launch_bounds__(256) void tconv_qkv_kernel(const float* __restrict__ Wq,
                                                        const float* __restrict__ Wk,
                                                        const float* __restrict__ Wv) {
    __shared__ float t[32][33];
    int np = blockIdx.x * 32;
    int k0 = blockIdx.y * 32;
    const float* W;
    int N, off;
    if (np < QDIM)              { W = Wq; N = QDIM;  off = 0; }
    else if (np < QDIM + KVDIM) { W = Wk; N = KVDIM; off = QDIM; }
    else                        { W = Wv; N = KVDIM; off = QDIM + KVDIM; }
    int n0 = np - off;
    int tx = threadIdx.x, ty = threadIdx.y;
#pragma unroll
    for (int i = 0; i < 32; i += 8)
        t[ty + i][tx] = W[(size_t)(k0 + ty + i) * N + n0 + tx];
    __syncthreads();
#pragma unroll
    for (int i = 0; i < 32; i += 8)
        g_wb[(size_t)(np + ty + i) * D_MODEL + k0 + tx] = __float2half_rn(t[tx][ty + i]);
}

__global__ __launch_bounds__(256) void tconv_wo_kernel(const float* __restrict__ W) {
    __shared__ float t[32][33];
    int n0 = blockIdx.x * 32, k0 = blockIdx.y * 32;
    int tx = threadIdx.x, ty = threadIdx.y;
#pragma unroll
    for (int i = 0; i < 32; i += 8)
        t[ty + i][tx] = W[(size_t)(k0 + ty + i) * D_MODEL + n0 + tx];
    __syncthreads();
#pragma unroll
    for (int i = 0; i < 32; i += 8)
        g_wo[(size_t)(n0 + ty + i) * QDIM + k0 + tx] = __float2half_rn(t[tx][ty + i]);
}

/* ---------------- RoPE table (fp32) ---------------- */
__global__ void rope_table_kernel() {
    int i = blockIdx.x * blockDim.x + threadIdx.x;
    if (i >= SEQ * (HD/2)) return;
    int t = i >> 5;
    int j = i & 31;
    float ex = (float)j * (1.0f / 32.0f);
    float inv = powf(ROPE_BASE, -ex);
    float ang = (float)t * inv;
    float s, c;
    sincosf(ang, &s, &c);
    g_cos[i] = c;
    g_sin[i] = s;
}

/* ---------------- single-fp16 GEMM mainloop macro ----------------
 * C = A[M,K] @ B[N,K]^T ; 1 MMA per (mt,nt) k16-step.
 * Tiles per stage: A | B, each 128 rows x 80B.
 */
#define TILE_B   10240
#define STAGE_B  (2*TILE_B)
#define GEMM_SMEM (2*STAGE_B)     /* 40960 */

#define GEMM_MAIN(Ap, Bp, Kdim)                                                   \
    extern __shared__ char smem[];                                                \
    uint32_t sb = smem_u32(smem);                                                 \
    int tid = threadIdx.x, lane = tid & 31, wid = tid >> 5;                       \
    int wm = wid & 1, wn = wid >> 1;                                              \
    int bm = blockIdx.y * 128, bn = blockIdx.x * 128;                             \
    int lr = tid >> 2;                                                            \
    int lc = tid & 3;                                                             \
    const __half* gA1 = (Ap) + (size_t)(bm + lr) * (Kdim) + lc * 8;               \
    const __half* gB1 = (Bp) + (size_t)(bn + lr) * (Kdim) + lc * 8;               \
    size_t rstep = (size_t)32 * (Kdim);                                           \
    uint32_t soff = lr * 80 + lc * 16;                                            \
    float acc[4][8][4];                                                           \
    _Pragma("unroll")                                                             \
    for (int i = 0; i < 4; i++)                                                   \
        _Pragma("unroll")                                                         \
        for (int j = 0; j < 8; j++)                                               \
            _Pragma("unroll")                                                     \
            for (int t = 0; t < 4; t++) acc[i][j][t] = 0.f;                       \
    int nkt = (Kdim) >> 5;                                                        \
    {                                                                             \
        _Pragma("unroll")                                                         \
        for (int r = 0; r < 4; r++) {                                             \
            uint32_t so = sb + soff + r * 2560;                                   \
            cp16(so,          gA1 + r * rstep);                                   \
            cp16(so + TILE_B, gB1 + r * rstep);                                   \
        }                                                                         \
    }                                                                             \
    cp_commit(); cp_wait0(); __syncthreads();                                     \
    uint32_t aBase = 2 * ((uint32_t)(wm * 64 + (lane & 15)) * 40 + ((lane >> 4) << 3)); \
    uint32_t bBase = 2 * ((uint32_t)(wn * 64 + (lane & 7) + ((lane >> 4) << 3)) * 40 + (lane & 8)); \
    for (int kt = 0; kt < nkt; kt++) {                                            \
        if (kt + 1 < nkt) {                                                       \
            int koff = (kt + 1) << 5;                                             \
            uint32_t st = sb + ((kt + 1) & 1) * STAGE_B;                          \
            _Pragma("unroll")                                                     \
            for (int r = 0; r < 4; r++) {                                         \
                uint32_t so = st + soff + r * 2560;                               \
                cp16(so,          gA1 + r * rstep + koff);                        \
                cp16(so + TILE_B, gB1 + r * rstep + koff);                        \
            }                                                                     \
        }                                                                         \
        cp_commit();                                                              \
        uint32_t base = sb + (kt & 1) * STAGE_B;                                  \
        _Pragma("unroll")                                                         \
        for (int kb = 0; kb < 32; kb += 16) {                                     \
            uint32_t af[4][4], bf[4][4];                                          \
            _Pragma("unroll")                                                     \
            for (int mt = 0; mt < 4; mt++)                                        \
                ldmx4(af[mt], base + aBase + 2 * (mt * 16 * 40 + kb));            \
            _Pragma("unroll")                                                     \
            for (int g = 0; g < 4; g++)                                           \
                ldmx4(bf[g], base + TILE_B + bBase + 2 * (g * 16 * 40 + kb));     \
            _Pragma("unroll")                                                     \
            for (int mt = 0; mt < 4; mt++)                                        \
                _Pragma("unroll")                                                 \
                for (int nt = 0; nt < 8; nt++)                                    \
                    mma16816h(acc[mt][nt], af[mt], &bf[nt >> 1][(nt & 1) * 2]);   \
        }                                                                         \
        cp_wait0();                                                               \
        __syncthreads();                                                          \
    }

/* ---------------- Wo GEMM ---------------- */
__global__ __launch_bounds__(128, 2)
void hmma_gemm_wo(float* __restrict__ C) {
    GEMM_MAIN(g_ao, g_wo, QDIM)
    int er = lane >> 2, ec = (lane & 3) * 2;
#pragma unroll
    for (int mt = 0; mt < 4; mt++)
#pragma unroll
        for (int nt = 0; nt < 8; nt++) {
            int row = bm + wm * 64 + mt * 16 + er;
            int col = bn + wn * 64 + nt * 8 + ec;
            *(float2*)(C + (size_t)row * D_MODEL + col) =
                make_float2(acc[mt][nt][0], acc[mt][nt][1]);
            *(float2*)(C + (size_t)(row + 8) * D_MODEL + col) =
                make_float2(acc[mt][nt][2], acc[mt][nt][3]);
        }
}

/* ---------------- QKV GEMM with fused RoPE + fp16 epilogue -------------- */
__global__ __launch_bounds__(128, 2)
void hmma_gemm_qkv() {
    GEMM_MAIN(g_x, g_wb, D_MODEL)
    int er = lane >> 2, ec = (lane & 3) * 2;
    int head = (bn + wn * 64) >> 6;           /* 0..47 */
    if (head < N_HEADS + N_KV) {
        bool isq = head < N_HEADS;
        int dim  = isq ? QDIM : KVDIM;
        int hcol = (isq ? head : head - N_HEADS) * HD;
#pragma unroll
        for (int mt = 0; mt < 4; mt++) {
            int row = bm + wm * 64 + mt * 16 + er;
#pragma unroll
            for (int hr = 0; hr < 2; hr++) {
                int tok = row + hr * 8;
                int s = tok & (SEQ - 1);
                int e0 = hr * 2;
#pragma unroll
                for (int nt = 0; nt < 4; nt++) {
                    int j = nt * 8 + ec;
                    float c0 = g_cos[s*32 + j],   c1 = g_cos[s*32 + j + 1];
                    float n0 = g_sin[s*32 + j],   n1 = g_sin[s*32 + j + 1];
                    float x1a = acc[mt][nt][e0],     x1b = acc[mt][nt][e0+1];
                    float x2a = acc[mt][nt+4][e0],   x2b = acc[mt][nt+4][e0+1];
                    float r1a = x1a*c0 - x2a*n0, r1b = x1b*c1 - x2b*n1;
                    float r2a = x2a*c0 + x1a*n0, r2b = x2b*c1 + x1b*n1;
                    size_t o1 = (size_t)tok * dim + hcol + j;
                    if (isq) {
                        *(uint32_t*)(g_qh2 + o1)      = pkh(r1a, r1b);
                        *(uint32_t*)(g_ql2 + o1)      = pkh(r1a - h2f(r1a), r1b - h2f(r1b));
                        *(uint32_t*)(g_qh2 + o1 + 32) = pkh(r2a, r2b);
                        *(uint32_t*)(g_ql2 + o1 + 32) = pkh(r2a - h2f(r2a), r2b - h2f(r2b));
                    } else {
                        *(uint32_t*)(g_kf + o1)      = pkh(r1a, r1b);
                        *(uint32_t*)(g_kf + o1 + 32) = pkh(r2a, r2b);
                    }
                }
            }
        }
    } else {
        int hcol = (head - N_HEADS - N_KV) * HD;
#pragma unroll
        for (int mt = 0; mt < 4; mt++) {
            int row = bm + wm * 64 + mt * 16 + er;
#pragma unroll
            for (int nt = 0; nt < 8; nt++) {
                int jj = nt * 8 + ec;
                *(uint32_t*)(g_vf + (size_t)row * KVDIM + hcol + jj) =
                    pkh(acc[mt][nt][0], acc[mt][nt][1]);
                *(uint32_t*)(g_vf + (size_t)(row + 8) * KVDIM + hcol + jj) =
                    pkh(acc[mt][nt][2], acc[mt][nt][3]);
            }
        }
    }
}

/* ---------------- fp16 flash attention (R12 core) ---------------- */
#define AS_K 0
#define AS_V 9216
#define ATTN_SMEM 18432

__global__ __launch_bounds__(256)
void attn_kernel(const int* __restrict__ cu) {
    extern __shared__ char smem[];
    uint32_t sb = smem_u32(smem);
    int qb = blockIdx.x, h = blockIdx.y, b = blockIdx.z;
    int kvh = h >> 2;
    int tid = threadIdx.x, lane = tid & 31, wid = tid >> 5;
    int wq = wid & 3, wk = wid >> 2;

    int b0 = min(max(cu[b*4+0], 0), SEQ);
    int b1 = min(max(cu[b*4+1], 0), SEQ);
    int b2 = min(max(cu[b*4+2], 0), SEQ);
    int b3 = min(max(cu[b*4+3], 0), SEQ);

    int p0 = qb * 64;
    int s_start = 0;
    if (b0 <= p0) s_start = b0;
    if (b1 <= p0) s_start = max(s_start, b1);
    if (b2 <= p0) s_start = max(s_start, b2);
    if (b3 <= p0) s_start = max(s_start, b3);
    int kb0 = s_start >> 6;

    /* stage Q hi/lo (64 x 64 fp16 each) */
#pragma unroll
    for (int i = 0; i < 4; i++) {
        int arr = i >> 1;
        int rem = tid + (i & 1) * 256;
        int row = rem >> 3, c = rem & 7;
        const __half* src = arr ? g_ql2 : g_qh2;
        cp16(sb + arr*9216 + row*144 + c*16,
             src + (size_t)(b*SEQ + p0 + row) * QDIM + h*HD + c*8);
    }
    cp_commit(); cp_wait0(); __syncthreads();

    uint32_t qh[4][4], ql[4][4];
#pragma unroll
    for (int kt = 0; kt < 4; kt++) {
        uint32_t off = (uint32_t)(wq*16 + (lane & 15)) * 144 + (kt*16 + ((lane >> 4) << 3)) * 2;
        ldmx4(qh[kt], sb + off);
        ldmx4(ql[kt], sb + 9216 + off);
    }
    __syncthreads();

    int qp0 = p0 + wq*16 + (lane >> 2);
    int qp1 = qp0 + 8;
    int qsg0 = (b0 <= qp0) + (b1 <= qp0) + (b2 <= qp0) + (b3 <= qp0);
    int qsg1 = (b0 <= qp1) + (b1 <= qp1) + (b2 <= qp1) + (b3 <= qp1);

    float m0 = -INFINITY, m1 = -INFINITY, l0 = 0.f, l1 = 0.f;
    float o[8][4];
#pragma unroll
    for (int nd = 0; nd < 8; nd++)
#pragma unroll
        for (int j = 0; j < 4; j++) o[nd][j] = 0.f;

    int colb = wk*32 + (lane & 3)*2;

    for (int kb = kb0; kb <= qb; kb++) {
        __syncthreads();
#pragma unroll
        for (int i = 0; i < 4; i++) {
            int arr = i >> 1;
            int rem = tid + (i & 1) * 256;
            int row = rem >> 3, c = rem & 7;
            const __half* src = arr ? g_vf : g_kf;
            cp16(sb + arr*9216 + row*144 + c*16,
                 src + (size_t)(b*SEQ + kb*64 + row) * KVDIM + kvh*HD + c*8);
        }
        cp_commit(); cp_wait0(); __syncthreads();

        float s[4][4];
#pragma unroll
        for (int nt = 0; nt < 4; nt++)
#pragma unroll
            for (int j = 0; j < 4; j++) s[nt][j] = 0.f;

#pragma unroll
        for (int kt = 0; kt < 4; kt++) {
            uint32_t khf[2][4];
#pragma unroll
            for (int np = 0; np < 2; np++) {
                int mq = lane >> 3, r = lane & 7;
                uint32_t off = (uint32_t)(wk*32 + np*16 + ((mq & 2) ? 8 : 0) + r) * 144
                             + (kt*16 + ((mq & 1) ? 8 : 0)) * 2;
                ldmx4(khf[np], sb + AS_K + off);
            }
#pragma unroll
            for (int nt = 0; nt < 4; nt++) {
                const uint32_t* fh = &khf[nt >> 1][(nt & 1) * 2];
                mma16816h(s[nt], qh[kt], fh);
                mma16816h(s[nt], ql[kt], fh);
            }
        }

#pragma unroll
        for (int nt = 0; nt < 4; nt++)
#pragma unroll
            for (int j = 0; j < 4; j++) s[nt][j] *= SCALE_L2E;

#pragma unroll
        for (int nt = 0; nt < 4; nt++)
#pragma unroll
            for (int e = 0; e < 2; e++) {
                int kp = kb*64 + colb + nt*8 + e;
                int sk = (b0 <= kp) + (b1 <= kp) + (b2 <= kp) + (b3 <= kp);
                if (kp > qp0 || sk != qsg0) s[nt][e]     = -INFINITY;
                if (kp > qp1 || sk != qsg1) s[nt][2 + e] = -INFINITY;
            }

        float rm0 = -INFINITY, rm1 = -INFINITY;
#pragma unroll
        for (int nt = 0; nt < 4; nt++) {
            rm0 = fmaxf(rm0, fmaxf(s[nt][0], s[nt][1]));
            rm1 = fmaxf(rm1, fmaxf(s[nt][2], s[nt][3]));
        }
        rm0 = fmaxf(rm0, __shfl_xor_sync(0xffffffffu, rm0, 1));
        rm0 = fmaxf(rm0, __shfl_xor_sync(0xffffffffu, rm0, 2));
        rm1 = fmaxf(rm1, __shfl_xor_sync(0xffffffffu, rm1, 1));
        rm1 = fmaxf(rm1, __shfl_xor_sync(0xffffffffu, rm1, 2));
        float mn0 = fmaxf(m0, rm0), mn1 = fmaxf(m1, rm1);
        bool lv0 = mn0 > -INFINITY, lv1 = mn1 > -INFINITY;
        float sc0 = lv0 ? ((m0 > -INFINITY) ? ex2(m0 - mn0) : 0.f) : 1.f;
        float sc1 = lv1 ? ((m1 > -INFINITY) ? ex2(m1 - mn1) : 0.f) : 1.f;

        float p[4][4], pl[4][4];
        float rs0 = 0.f, rs1 = 0.f;
#pragma unroll
        for (int nt = 0; nt < 4; nt++) {
#pragma unroll
            for (int e = 0; e < 2; e++) {
                float v0 = lv0 ? ex2(s[nt][e]     - mn0) : 0.f;
                float v1 = lv1 ? ex2(s[nt][2 + e] - mn1) : 0.f;
                p[nt][e] = v0;     rs0 += v0;
                p[nt][2+e] = v1;   rs1 += v1;
            }
        }
        rs0 += __shfl_xor_sync(0xffffffffu, rs0, 1);
        rs0 += __shfl_xor_sync(0xffffffffu, rs0, 2);
        rs1 += __shfl_xor_sync(0xffffffffu, rs1, 1);
        rs1 += __shfl_xor_sync(0xffffffffu, rs1, 2);
        l0 = l0 * sc0 + rs0;  m0 = mn0;
        l1 = l1 * sc1 + rs1;  m1 = mn1;
#pragma unroll
        for (int nd = 0; nd < 8; nd++) {
            o[nd][0] *= sc0; o[nd][1] *= sc0;
            o[nd][2] *= sc1; o[nd][3] *= sc1;
        }

#pragma unroll
        for (int nt = 0; nt < 4; nt++)
#pragma unroll
            for (int j = 0; j < 4; j++)
                pl[nt][j] = p[nt][j] - h2f(p[nt][j]);

#pragma unroll
        for (int kt2 = 0; kt2 < 2; kt2++) {
            uint32_t pah[4] = { pkh(p[2*kt2][0],   p[2*kt2][1]),
                                pkh(p[2*kt2][2],   p[2*kt2][3]),
                                pkh(p[2*kt2+1][0], p[2*kt2+1][1]),
                                pkh(p[2*kt2+1][2], p[2*kt2+1][3]) };
            uint32_t pal[4] = { pkh(pl[2*kt2][0],   pl[2*kt2][1]),
                                pkh(pl[2*kt2][2],   pl[2*kt2][3]),
                                pkh(pl[2*kt2+1][0], pl[2*kt2+1][1]),
                                pkh(pl[2*kt2+1][2], pl[2*kt2+1][3]) };
#pragma unroll
            for (int ndp = 0; ndp < 4; ndp++) {
                int mq = lane >> 3, r = lane & 7;
                uint32_t off = (uint32_t)(wk*32 + kt2*16 + ((mq & 1) ? 8 : 0) + r) * 144
                             + (ndp*16 + ((mq & 2) ? 8 : 0)) * 2;
                uint32_t vh4[4];
                ldmx4t(vh4, sb + AS_V + off);
#pragma unroll
                for (int q2 = 0; q2 < 2; q2++) {
                    int nd = ndp*2 + q2;
                    mma16816h(o[nd], pah, &vh4[q2*2]);
                    mma16816h(o[nd], pal, &vh4[q2*2]);
                }
            }
        }
    }

    /* merge kv-halves via smem */
    __syncthreads();
    float* Osm = (float*)smem;
    float* msm = (float*)(smem + 17408);
    float* lsm = (float*)(smem + 17664);
    int rl = wq*16 + (lane >> 2);
    int c2 = (lane & 3)*2;
    if (wk == 1) {
#pragma unroll
        for (int nd = 0; nd < 8; nd++) {
            *(float2*)&Osm[rl*68 + nd*8 + c2]     = make_float2(o[nd][0], o[nd][1]);
            *(float2*)&Osm[(rl+8)*68 + nd*8 + c2] = make_float2(o[nd][2], o[nd][3]);
        }
        if ((lane & 3) == 0) {
            msm[rl] = m0; msm[rl+8] = m1;
            lsm[rl] = l0; lsm[rl+8] = l1;
        }
    }
    __syncthreads();
    if (wk == 0) {
        float pm0 = msm[rl], pm1 = msm[rl+8];
        float pl0 = lsm[rl], pl1 = lsm[rl+8];
        float M0 = fmaxf(m0, pm0), M1 = fmaxf(m1, pm1);
        float sa0 = (m0  > -INFINITY) ? ex2(m0  - M0) : 0.f;
        float sb0 = (pm0 > -INFINITY) ? ex2(pm0 - M0) : 0.f;
        float sa1 = (m1  > -INFINITY) ? ex2(m1  - M1) : 0.f;
        float sb1 = (pm1 > -INFINITY) ? ex2(pm1 - M1) : 0.f;
        float inv0 = 1.f / (l0*sa0 + pl0*sb0);
        float inv1 = 1.f / (l1*sa1 + pl1*sb1);
        size_t r0g = (size_t)(b*SEQ + p0 + rl) * QDIM + h*HD;
        size_t r1g = (size_t)(b*SEQ + p0 + rl + 8) * QDIM + h*HD;
#pragma unroll
        for (int nd = 0; nd < 8; nd++) {
            float v0 = (o[nd][0]*sa0 + Osm[rl*68 + nd*8 + c2]*sb0) * inv0;
            float v1 = (o[nd][1]*sa0 + Osm[rl*68 + nd*8 + c2 + 1]*sb0) * inv0;
            float v2 = (o[nd][2]*sa1 + Osm[(rl+8)*68 + nd*8 + c2]*sb1) * inv1;
            float v3 = (o[nd][3]*sa1 + Osm[(rl+8)*68 + nd*8 + c2 + 1]*sb1) * inv1;
            *(uint32_t*)(g_ao + r0g + nd*8 + c2) = pkh(v0, v1);
            *(uint32_t*)(g_ao + r1g + nd*8 + c2) = pkh(v2, v3);
        }
    }
}

/* ------------------------------------------------------------------ */
extern "C" void kernel_launch(void* const* d_in, const int* in_sizes, int n_in,
                              void* d_out, int out_size) {
    const float* x  = (const float*)d_in[0];
    const int*   cu = (const int*)  d_in[1];
    const float* Wq = (const float*)d_in[2];
    const float* Wk = (const float*)d_in[3];
    const float* Wv = (const float*)d_in[4];
    const float* Wo = (const float*)d_in[5];
    float* out = (float*)d_out;

    cudaFuncSetAttribute(attn_kernel,
                         cudaFuncAttributeMaxDynamicSharedMemorySize, ATTN_SMEM);
    cudaFuncSetAttribute(hmma_gemm_wo,
                         cudaFuncAttributeMaxDynamicSharedMemorySize, GEMM_SMEM);
    cudaFuncSetAttribute(hmma_gemm_qkv,
                         cudaFuncAttributeMaxDynamicSharedMemorySize, GEMM_SMEM);

    /* prep */
    rope_table_kernel<<<(SEQ*(HD/2) + 255)/256, 256>>>();
    convx_kernel<<<(NTOK*D_MODEL/4 + 255)/256, 256>>>(x, NTOK*D_MODEL/4);
    tconv_qkv_kernel<<<dim3(QKVDIM/32, D_MODEL/32), dim3(32,8)>>>(Wq, Wk, Wv);
    tconv_wo_kernel<<<dim3(D_MODEL/32, QDIM/32), dim3(32,8)>>>(Wo);

    /* merged QKV projection with fused rope+fp16 epilogue */
    hmma_gemm_qkv<<<dim3(QKVDIM/128, NTOK/128), 128, GEMM_SMEM>>>();

    /* attention */
    attn_kernel<<<dim3(SEQ/64, N_HEADS, BATCH), 256, ATTN_SMEM>>>(cu);

    /* output projection */
    hmma_gemm_wo<<<dim3(D_MODEL/128, NTOK/128), 128, GEMM_SMEM>>>(out);
}

// round 14
// speedup vs baseline: 2.2999x; 1.0456x over previous
#include <cuda_runtime.h>
#include <cuda_bf16.h>
#include <cuda_fp16.h>
#include <math.h>
#include <stdint.h>

#define D_MODEL 2048
#define N_HEADS 32
#define N_KV    8
#define HD      64
#define SEQ     2048
#define BATCH   2
#define NTOK    (BATCH*SEQ)      /* 4096 */
#define QDIM    (N_HEADS*HD)     /* 2048 */
#define KVDIM   (N_KV*HD)        /* 512  */
#define QKVDIM  (QDIM + 2*KVDIM) /* 3072 */
#define ROPE_BASE 500000.0f
#define SCALE_L2E 0.1803368801111204f   /* 0.125 * log2(e) */

/* ---------------- static device scratch ---------------- */
__device__ float g_cos[SEQ*(HD/2)];
__device__ float g_sin[SEQ*(HD/2)];

/* GEMM operands: single fp16 */
__device__ __half g_x  [NTOK*D_MODEL];
__device__ __half g_wb [QKVDIM*D_MODEL];   /* packed Wq|Wk|Wv, [N,K] */
__device__ __half g_wo [D_MODEL*QDIM];
__device__ __half g_ao [NTOK*QDIM];        /* attention out */

/* attention operands (all single fp16; q unscaled) */
__device__ __half g_qf [NTOK*QDIM];
__device__ __half g_kf [NTOK*KVDIM];
__device__ __half g_vf [NTOK*KVDIM];

/* ---------------- PTX helpers ---------------- */
__device__ __forceinline__ uint32_t smem_u32(const void* p) {
    uint32_t a;
    asm("{ .reg .u64 t; cvta.to.shared.u64 t, %1; cvt.u32.u64 %0, t; }" : "=r"(a) : "l"(p));
    return a;
}
__device__ __forceinline__ void cp16(uint32_t saddr, const void* g) {
    asm volatile("cp.async.cg.shared.global [%0], [%1], 16;" :: "r"(saddr), "l"(g));
}
__device__ __forceinline__ void cp_commit() { asm volatile("cp.async.commit_group;" ::: "memory"); }
__device__ __forceinline__ void cp_wait0()  { asm volatile("cp.async.wait_group 0;"  ::: "memory"); }

__device__ __forceinline__ void ldmx4(uint32_t* r, uint32_t addr) {
    asm volatile("ldmatrix.sync.aligned.m8n8.x4.shared.b16 {%0,%1,%2,%3}, [%4];"
                 : "=r"(r[0]), "=r"(r[1]), "=r"(r[2]), "=r"(r[3]) : "r"(addr));
}
__device__ __forceinline__ void ldmx4t(uint32_t* r, uint32_t addr) {
    asm volatile("ldmatrix.sync.aligned.m8n8.x4.trans.shared.b16 {%0,%1,%2,%3}, [%4];"
                 : "=r"(r[0]), "=r"(r[1]), "=r"(r[2]), "=r"(r[3]) : "r"(addr));
}
__device__ __forceinline__ void mma16816h(float* d, const uint32_t* a, const uint32_t* b) {
    asm volatile(
        "mma.sync.aligned.m16n8k16.row.col.f32.f16.f16.f32 "
        "{%0,%1,%2,%3}, {%4,%5,%6,%7}, {%8,%9}, {%0,%1,%2,%3};"
        : "+f"(d[0]), "+f"(d[1]), "+f"(d[2]), "+f"(d[3])
        : "r"(a[0]), "r"(a[1]), "r"(a[2]), "r"(a[3]), "r"(b[0]), "r"(b[1]));
}
__device__ __forceinline__ float ex2(float x) {
    float y; asm("ex2.approx.f32 %0, %1;" : "=f"(y) : "f"(x)); return y;
}
__device__ __forceinline__ uint32_t pkh(float a, float b) {
    __half2 t = __floats2half2_rn(a, b);
    return *(uint32_t*)&t;
}

/* ---------------- prep kernels ---------------- */
__global__ __launch_bounds__(256) void convx_kernel(const float* __restrict__ src, int n4) {
    int i = blockIdx.x * blockDim.x + threadIdx.x;
    if (i >= n4) return;
    float4 v = ((const float4*)src)[i];
    __half h[4] = { __float2half_rn(v.x), __float2half_rn(v.y),
                    __float2half_rn(v.z), __float2half_rn(v.w) };
    ((uint2*)g_x)[i] = *(uint2*)h;
}

__global__ __launch_bounds__(256) void tconv_qkv_kernel(const float* __restrict__ Wq,
                                                        const float* __restrict__ Wk,
                                                        const float* __restrict__ Wv) {
    __shared__ float t[32][33];
    int np = blockIdx.x * 32;
    int k0 = blockIdx.y * 32;
    const float* W;
    int N, off;
    if (np < QDIM)              { W = Wq; N = QDIM;  off = 0; }
    else if (np < QDIM + KVDIM) { W = Wk; N = KVDIM; off = QDIM; }
    else                        { W = Wv; N = KVDIM; off = QDIM + KVDIM; }
    int n0 = np - off;
    int tx = threadIdx.x, ty = threadIdx.y;
#pragma unroll
    for (int i = 0; i < 32; i += 8)
        t[ty + i][tx] = W[(size_t)(k0 + ty + i) * N + n0 + tx];
    __syncthreads();
#pragma unroll
    for (int i = 0; i < 32; i += 8)
        g_wb[(size_t)(np + ty + i) * D_MODEL + k0 + tx] = __float2half_rn(t[tx][ty + i]);
}

__global__ __launch_bounds__(256) void tconv_wo_kernel(const float* __restrict__ W) {
    __shared__ float t[32][33];
    int n0 = blockIdx.x * 32, k0 = blockIdx.y * 32;
    int tx = threadIdx.x, ty = threadIdx.y;
#pragma unroll
    for (int i = 0; i < 32; i += 8)
        t[ty + i][tx] = W[(size_t)(k0 + ty + i) * D_MODEL + n0 + tx];
    __syncthreads();
#pragma unroll
    for (int i = 0; i < 32; i += 8)
        g_wo[(size_t)(n0 + ty + i) * QDIM + k0 + tx] = __float2half_rn(t[tx][ty + i]);
}

/* ---------------- RoPE table (fp32) ---------------- */
__global__ void rope_table_kernel() {
    int i = blockIdx.x * blockDim.x + threadIdx.x;
    if (i >= SEQ * (HD/2)) return;
    int t = i >> 5;
    int j = i & 31;
    float ex = (float)j * (1.0f / 32.0f);
    float inv = powf(ROPE_BASE, -ex);
    float ang = (float)t * inv;
    float s, c;
    sincosf(ang, &s, &c);
    g_cos[i] = c;
    g_sin[i] = s;
}

/* ---------------- single-fp16 GEMM mainloop macro ---------------- */
#define TILE_B   10240
#define STAGE_B  (2*TILE_B)
#define GEMM_SMEM (2*STAGE_B)     /* 40960 */

#define GEMM_MAIN(Ap, Bp, Kdim)                                                   \
    extern __shared__ char smem[];                                                \
    uint32_t sb = smem_u32(smem);                                                 \
    int tid = threadIdx.x, lane = tid & 31, wid = tid >> 5;                       \
    int wm = wid & 1, wn = wid >> 1;                                              \
    int bm = blockIdx.y * 128, bn = blockIdx.x * 128;                             \
    int lr = tid >> 2;                                                            \
    int lc = tid & 3;                                                             \
    const __half* gA1 = (Ap) + (size_t)(bm + lr) * (Kdim) + lc * 8;               \
    const __half* gB1 = (Bp) + (size_t)(bn + lr) * (Kdim) + lc * 8;               \
    size_t rstep = (size_t)32 * (Kdim);                                           \
    uint32_t soff = lr * 80 + lc * 16;                                            \
    float acc[4][8][4];                                                           \
    _Pragma("unroll")                                                             \
    for (int i = 0; i < 4; i++)                                                   \
        _Pragma("unroll")                                                         \
        for (int j = 0; j < 8; j++)                                               \
            _Pragma("unroll")                                                     \
            for (int t = 0; t < 4; t++) acc[i][j][t] = 0.f;                       \
    int nkt = (Kdim) >> 5;                                                        \
    {                                                                             \
        _Pragma("unroll")                                                         \
        for (int r = 0; r < 4; r++) {                                             \
            uint32_t so = sb + soff + r * 2560;                                   \
            cp16(so,          gA1 + r * rstep);                                   \
            cp16(so + TILE_B, gB1 + r * rstep);                                   \
        }                                                                         \
    }                                                                             \
    cp_commit(); cp_wait0(); __syncthreads();                                     \
    uint32_t aBase = 2 * ((uint32_t)(wm * 64 + (lane & 15)) * 40 + ((lane >> 4) << 3)); \
    uint32_t bBase = 2 * ((uint32_t)(wn * 64 + (lane & 7) + ((lane >> 4) << 3)) * 40 + (lane & 8)); \
    for (int kt = 0; kt < nkt; kt++) {                                            \
        if (kt + 1 < nkt) {                                                       \
            int koff = (kt + 1) << 5;                                             \
            uint32_t st = sb + ((kt + 1) & 1) * STAGE_B;                          \
            _Pragma("unroll")                                                     \
            for (int r = 0; r < 4; r++) {                                         \
                uint32_t so = st + soff + r * 2560;                               \
                cp16(so,          gA1 + r * rstep + koff);                        \
                cp16(so + TILE_B, gB1 + r * rstep + koff);                        \
            }                                                                     \
        }                                                                         \
        cp_commit();                                                              \
        uint32_t base = sb + (kt & 1) * STAGE_B;                                  \
        _Pragma("unroll")                                                         \
        for (int kb = 0; kb < 32; kb += 16) {                                     \
            uint32_t af[4][4], bf[4][4];                                          \
            _Pragma("unroll")                                                     \
            for (int mt = 0; mt < 4; mt++)                                        \
                ldmx4(af[mt], base + aBase + 2 * (mt * 16 * 40 + kb));            \
            _Pragma("unroll")                                                     \
            for (int g = 0; g < 4; g++)                                           \
                ldmx4(bf[g], base + TILE_B + bBase + 2 * (g * 16 * 40 + kb));     \
            _Pragma("unroll")                                                     \
            for (int mt = 0; mt < 4; mt++)                                        \
                _Pragma("unroll")                                                 \
                for (int nt = 0; nt < 8; nt++)                                    \
                    mma16816h(acc[mt][nt], af[mt], &bf[nt >> 1][(nt & 1) * 2]);   \
        }                                                                         \
        cp_wait0();                                                               \
        __syncthreads();                                                          \
    }

/* ---------------- Wo GEMM ---------------- */
__global__ __launch_bounds__(128, 2)
void hmma_gemm_wo(float* __restrict__ C) {
    GEMM_MAIN(g_ao, g_wo, QDIM)
    int er = lane >> 2, ec = (lane & 3) * 2;
#pragma unroll
    for (int mt = 0; mt < 4; mt++)
#pragma unroll
        for (int nt = 0; nt < 8; nt++) {
            int row = bm + wm * 64 + mt * 16 + er;
            int col = bn + wn * 64 + nt * 8 + ec;
            *(float2*)(C + (size_t)row * D_MODEL + col) =
                make_float2(acc[mt][nt][0], acc[mt][nt][1]);
            *(float2*)(C + (size_t)(row + 8) * D_MODEL + col) =
                make_float2(acc[mt][nt][2], acc[mt][nt][3]);
        }
}

/* ---------------- QKV GEMM with fused RoPE + fp16 epilogue -------------- */
__global__ __launch_bounds__(128, 2)
void hmma_gemm_qkv() {
    GEMM_MAIN(g_x, g_wb, D_MODEL)
    int er = lane >> 2, ec = (lane & 3) * 2;
    int head = (bn + wn * 64) >> 6;           /* 0..47 */
    if (head < N_HEADS + N_KV) {
        bool isq = head < N_HEADS;
        int dim  = isq ? QDIM : KVDIM;
        int hcol = (isq ? head : head - N_HEADS) * HD;
        __half* dst = isq ? g_qf : g_kf;
#pragma unroll
        for (int mt = 0; mt < 4; mt++) {
            int row = bm + wm * 64 + mt * 16 + er;
#pragma unroll
            for (int hr = 0; hr < 2; hr++) {
                int tok = row + hr * 8;
                int s = tok & (SEQ - 1);
                int e0 = hr * 2;
#pragma unroll
                for (int nt = 0; nt < 4; nt++) {
                    int j = nt * 8 + ec;
                    float c0 = g_cos[s*32 + j],   c1 = g_cos[s*32 + j + 1];
                    float n0 = g_sin[s*32 + j],   n1 = g_sin[s*32 + j + 1];
                    float x1a = acc[mt][nt][e0],     x1b = acc[mt][nt][e0+1];
                    float x2a = acc[mt][nt+4][e0],   x2b = acc[mt][nt+4][e0+1];
                    size_t o1 = (size_t)tok * dim + hcol + j;
                    *(uint32_t*)(dst + o1)      = pkh(x1a*c0 - x2a*n0, x1b*c1 - x2b*n1);
                    *(uint32_t*)(dst + o1 + 32) = pkh(x2a*c0 + x1a*n0, x2b*c1 + x1b*n1);
                }
            }
        }
    } else {
        int hcol = (head - N_HEADS - N_KV) * HD;
#pragma unroll
        for (int mt = 0; mt < 4; mt++) {
            int row = bm + wm * 64 + mt * 16 + er;
#pragma unroll
            for (int nt = 0; nt < 8; nt++) {
                int jj = nt * 8 + ec;
                *(uint32_t*)(g_vf + (size_t)row * KVDIM + hcol + jj) =
                    pkh(acc[mt][nt][0], acc[mt][nt][1]);
                *(uint32_t*)(g_vf + (size_t)(row + 8) * KVDIM + hcol + jj) =
                    pkh(acc[mt][nt][2], acc[mt][nt][3]);
            }
        }
    }
}

/* ---------------- fp16 flash attention (all-single fp16) ---------------- */
#define AS_K 0
#define AS_V 9216
#define ATTN_SMEM 18432

__global__ __launch_bounds__(256)
void attn_kernel(const int* __restrict__ cu) {
    extern __shared__ char smem[];
    uint32_t sb = smem_u32(smem);
    int qb = blockIdx.x, h = blockIdx.y, b = blockIdx.z;
    int kvh = h >> 2;
    int tid = threadIdx.x, lane = tid & 31, wid = tid >> 5;
    int wq = wid & 3, wk = wid >> 2;

    int b0 = min(max(cu[b*4+0], 0), SEQ);
    int b1 = min(max(cu[b*4+1], 0), SEQ);
    int b2 = min(max(cu[b*4+2], 0), SEQ);
    int b3 = min(max(cu[b*4+3], 0), SEQ);

    int p0 = qb * 64;
    int s_start = 0;
    if (b0 <= p0) s_start = b0;
    if (b1 <= p0) s_start = max(s_start, b1);
    if (b2 <= p0) s_start = max(s_start, b2);
    if (b3 <= p0) s_start = max(s_start, b3);
    int kb0 = s_start >> 6;

    /* stage Q (64 x 64 fp16) */
#pragma unroll
    for (int i = 0; i < 2; i++) {
        int rem = tid + i * 256;
        int row = rem >> 3, c = rem & 7;
        cp16(sb + row*144 + c*16,
             g_qf + (size_t)(b*SEQ + p0 + row) * QDIM + h*HD + c*8);
    }
    cp_commit(); cp_wait0(); __syncthreads();

    uint32_t qh[4][4];
#pragma unroll
    for (int kt = 0; kt < 4; kt++) {
        uint32_t off = (uint32_t)(wq*16 + (lane & 15)) * 144 + (kt*16 + ((lane >> 4) << 3)) * 2;
        ldmx4(qh[kt], sb + off);
    }
    __syncthreads();

    int qp0 = p0 + wq*16 + (lane >> 2);
    int qp1 = qp0 + 8;
    int qsg0 = (b0 <= qp0) + (b1 <= qp0) + (b2 <= qp0) + (b3 <= qp0);
    int qsg1 = (b0 <= qp1) + (b1 <= qp1) + (b2 <= qp1) + (b3 <= qp1);

    float m0 = -INFINITY, m1 = -INFINITY, l0 = 0.f, l1 = 0.f;
    float o[8][4];
#pragma unroll
    for (int nd = 0; nd < 8; nd++)
#pragma unroll
        for (int j = 0; j < 4; j++) o[nd][j] = 0.f;

    int colb = wk*32 + (lane & 3)*2;

    for (int kb = kb0; kb <= qb; kb++) {
        __syncthreads();
#pragma unroll
        for (int i = 0; i < 4; i++) {
            int arr = i >> 1;
            int rem = tid + (i & 1) * 256;
            int row = rem >> 3, c = rem & 7;
            const __half* src = arr ? g_vf : g_kf;
            cp16(sb + arr*9216 + row*144 + c*16,
                 src + (size_t)(b*SEQ + kb*64 + row) * KVDIM + kvh*HD + c*8);
        }
        cp_commit(); cp_wait0(); __syncthreads();

        /* S = Q K^T */
        float s[4][4];
#pragma unroll
        for (int nt = 0; nt < 4; nt++)
#pragma unroll
            for (int j = 0; j < 4; j++) s[nt][j] = 0.f;

#pragma unroll
        for (int kt = 0; kt < 4; kt++) {
            uint32_t khf[2][4];
#pragma unroll
            for (int np = 0; np < 2; np++) {
                int mq = lane >> 3, r = lane & 7;
                uint32_t off = (uint32_t)(wk*32 + np*16 + ((mq & 2) ? 8 : 0) + r) * 144
                             + (kt*16 + ((mq & 1) ? 8 : 0)) * 2;
                ldmx4(khf[np], sb + AS_K + off);
            }
#pragma unroll
            for (int nt = 0; nt < 4; nt++)
                mma16816h(s[nt], qh[kt], &khf[nt >> 1][(nt & 1) * 2]);
        }

#pragma unroll
        for (int nt = 0; nt < 4; nt++)
#pragma unroll
            for (int j = 0; j < 4; j++) s[nt][j] *= SCALE_L2E;

#pragma unroll
        for (int nt = 0; nt < 4; nt++)
#pragma unroll
            for (int e = 0; e < 2; e++) {
                int kp = kb*64 + colb + nt*8 + e;
                int sk = (b0 <= kp) + (b1 <= kp) + (b2 <= kp) + (b3 <= kp);
                if (kp > qp0 || sk != qsg0) s[nt][e]     = -INFINITY;
                if (kp > qp1 || sk != qsg1) s[nt][2 + e] = -INFINITY;
            }

        float rm0 = -INFINITY, rm1 = -INFINITY;
#pragma unroll
        for (int nt = 0; nt < 4; nt++) {
            rm0 = fmaxf(rm0, fmaxf(s[nt][0], s[nt][1]));
            rm1 = fmaxf(rm1, fmaxf(s[nt][2], s[nt][3]));
        }
        rm0 = fmaxf(rm0, __shfl_xor_sync(0xffffffffu, rm0, 1));
        rm0 = fmaxf(rm0, __shfl_xor_sync(0xffffffffu, rm0, 2));
        rm1 = fmaxf(rm1, __shfl_xor_sync(0xffffffffu, rm1, 1));
        rm1 = fmaxf(rm1, __shfl_xor_sync(0xffffffffu, rm1, 2));
        float mn0 = fmaxf(m0, rm0), mn1 = fmaxf(m1, rm1);
        bool lv0 = mn0 > -INFINITY, lv1 = mn1 > -INFINITY;
        float sc0 = lv0 ? ((m0 > -INFINITY) ? ex2(m0 - mn0) : 0.f) : 1.f;
        float sc1 = lv1 ? ((m1 > -INFINITY) ? ex2(m1 - mn1) : 0.f) : 1.f;

        float p[4][4];
        float rs0 = 0.f, rs1 = 0.f;
#pragma unroll
        for (int nt = 0; nt < 4; nt++) {
#pragma unroll
            for (int e = 0; e < 2; e++) {
                float v0 = lv0 ? ex2(s[nt][e]     - mn0) : 0.f;
                float v1 = lv1 ? ex2(s[nt][2 + e] - mn1) : 0.f;
                p[nt][e] = v0;     rs0 += v0;
                p[nt][2+e] = v1;   rs1 += v1;
            }
        }
        rs0 += __shfl_xor_sync(0xffffffffu, rs0, 1);
        rs0 += __shfl_xor_sync(0xffffffffu, rs0, 2);
        rs1 += __shfl_xor_sync(0xffffffffu, rs1, 1);
        rs1 += __shfl_xor_sync(0xffffffffu, rs1, 2);
        l0 = l0 * sc0 + rs0;  m0 = mn0;
        l1 = l1 * sc1 + rs1;  m1 = mn1;
#pragma unroll
        for (int nd = 0; nd < 8; nd++) {
            o[nd][0] *= sc0; o[nd][1] *= sc0;
            o[nd][2] *= sc1; o[nd][3] *= sc1;
        }

        /* O += P V (single fp16 both sides) */
#pragma unroll
        for (int kt2 = 0; kt2 < 2; kt2++) {
            uint32_t pah[4] = { pkh(p[2*kt2][0],   p[2*kt2][1]),
                                pkh(p[2*kt2][2],   p[2*kt2][3]),
                                pkh(p[2*kt2+1][0], p[2*kt2+1][1]),
                                pkh(p[2*kt2+1][2], p[2*kt2+1][3]) };
#pragma unroll
            for (int ndp = 0; ndp < 4; ndp++) {
                int mq = lane >> 3, r = lane & 7;
                uint32_t off = (uint32_t)(wk*32 + kt2*16 + ((mq & 1) ? 8 : 0) + r) * 144
                             + (ndp*16 + ((mq & 2) ? 8 : 0)) * 2;
                uint32_t vh4[4];
                ldmx4t(vh4, sb + AS_V + off);
#pragma unroll
                for (int q2 = 0; q2 < 2; q2++)
                    mma16816h(o[ndp*2 + q2], pah, &vh4[q2*2]);
            }
        }
    }

    /* merge kv-halves via smem */
    __syncthreads();
    float* Osm = (float*)smem;
    float* msm = (float*)(smem + 17408);
    float* lsm = (float*)(smem + 17664);
    int rl = wq*16 + (lane >> 2);
    int c2 = (lane & 3)*2;
    if (wk == 1) {
#pragma unroll
        for (int nd = 0; nd < 8; nd++) {
            *(float2*)&Osm[rl*68 + nd*8 + c2]     = make_float2(o[nd][0], o[nd][1]);
            *(float2*)&Osm[(rl+8)*68 + nd*8 + c2] = make_float2(o[nd][2], o[nd][3]);
        }
        if ((lane & 3) == 0) {
            msm[rl] = m0; msm[rl+8] = m1;
            lsm[rl] = l0; lsm[rl+8] = l1;
        }
    }
    __syncthreads();
    if (wk == 0) {
        float pm0 = msm[rl], pm1 = msm[rl+8];
        float pl0 = lsm[rl], pl1 = lsm[rl+8];
        float M0 = fmaxf(m0, pm0), M1 = fmaxf(m1, pm1);
        float sa0 = (m0  > -INFINITY) ? ex2(m0  - M0) : 0.f;
        float sb0 = (pm0 > -INFINITY) ? ex2(pm0 - M0) : 0.f;
        float sa1 = (m1  > -INFINITY) ? ex2(m1  - M1) : 0.f;
        float sb1 = (pm1 > -INFINITY) ? ex2(pm1 - M1) : 0.f;
        float inv0 = 1.f / (l0*sa0 + pl0*sb0);
        float inv1 = 1.f / (l1*sa1 + pl1*sb1);
        size_t r0g = (size_t)(b*SEQ + p0 + rl) * QDIM + h*HD;
        size_t r1g = (size_t)(b*SEQ + p0 + rl + 8) * QDIM + h*HD;
#pragma unroll
        for (int nd = 0; nd < 8; nd++) {
            float v0 = (o[nd][0]*sa0 + Osm[rl*68 + nd*8 + c2]*sb0) * inv0;
            float v1 = (o[nd][1]*sa0 + Osm[rl*68 + nd*8 + c2 + 1]*sb0) * inv0;
            float v2 = (o[nd][2]*sa1 + Osm[(rl+8)*68 + nd*8 + c2]*sb1) * inv1;
            float v3 = (o[nd][3]*sa1 + Osm[(rl+8)*68 + nd*8 + c2 + 1]*sb1) * inv1;
            *(uint32_t*)(g_ao + r0g + nd*8 + c2) = pkh(v0, v1);
            *(uint32_t*)(g_ao + r1g + nd*8 + c2) = pkh(v2, v3);
        }
    }
}

/* ------------------------------------------------------------------ */
extern "C" void kernel_launch(void* const* d_in, const int* in_sizes, int n_in,
                              void* d_out, int out_size) {
    const float* x  = (const float*)d_in[0];
    const int*   cu = (const int*)  d_in[1];
    const float* Wq = (const float*)d_in[2];
    const float* Wk = (const float*)d_in[3];
    const float* Wv = (const float*)d_in[4];
    const float* Wo = (const float*)d_in[5];
    float* out = (float*)d_out;

    cudaFuncSetAttribute(attn_kernel,
                         cudaFuncAttributeMaxDynamicSharedMemorySize, ATTN_SMEM);
    cudaFuncSetAttribute(hmma_gemm_wo,
                         cudaFuncAttributeMaxDynamicSharedMemorySize, GEMM_SMEM);
    cudaFuncSetAttribute(hmma_gemm_qkv,
                         cudaFuncAttributeMaxDynamicSharedMemorySize, GEMM_SMEM);

    /* prep */
    rope_table_kernel<<<(SEQ*(HD/2) + 255)/256, 256>>>();
    convx_kernel<<<(NTOK*D_MODEL/4 + 255)/256, 256>>>(x, NTOK*D_MODEL/4);
    tconv_qkv_kernel<<<dim3(QKVDIM/32, D_MODEL/32), dim3(32,8)>>>(Wq, Wk, Wv);
    tconv_wo_kernel<<<dim3(D_MODEL/32, QDIM/32), dim3(32,8)>>>(Wo);

    /* merged QKV projection with fused rope+fp16 epilogue */
    hmma_gemm_qkv<<<dim3(QKVDIM/128, NTOK/128), 128, GEMM_SMEM>>>();

    /* attention */
    attn_kernel<<<dim3(SEQ/64, N_HEADS, BATCH), 256, ATTN_SMEM>>>(cu);

    /* output projection */
    hmma_gemm_wo<<<dim3(D_MODEL/128, NTOK/128), 128, GEMM_SMEM>>>(out);
}

// round 15
// speedup vs baseline: 2.3584x; 1.0255x over previous
#include <cuda_runtime.h>
#include <cuda_bf16.h>
#include <cuda_fp16.h>
#include <math.h>
#include <stdint.h>

#define D_MODEL 2048
#define N_HEADS 32
#define N_KV    8
#define HD      64
#define SEQ     2048
#define BATCH   2
#define NTOK    (BATCH*SEQ)      /* 4096 */
#define QDIM    (N_HEADS*HD)     /* 2048 */
#define KVDIM   (N_KV*HD)        /* 512  */
#define QKVDIM  (QDIM + 2*KVDIM) /* 3072 */
#define ROPE_BASE 500000.0f
#define SCALE_L2E 0.1803368801111204f   /* 0.125 * log2(e) */

/* ---------------- static device scratch ---------------- */
__device__ float g_cos[SEQ*(HD/2)];
__device__ float g_sin[SEQ*(HD/2)];

/* GEMM operands: single fp16 */
__device__ __half g_x  [NTOK*D_MODEL];
__device__ __half g_wb [QKVDIM*D_MODEL];   /* packed Wq|Wk|Wv, [N,K] */
__device__ __half g_wo [D_MODEL*QDIM];
__device__ __half g_ao [NTOK*QDIM];        /* attention out */

/* attention operands (all single fp16; q unscaled) */
__device__ __half g_qf [NTOK*QDIM];
__device__ __half g_kf [NTOK*KVDIM];
__device__ __half g_vf [NTOK*KVDIM];

/* ---------------- PTX helpers ---------------- */
__device__ __forceinline__ uint32_t smem_u32(const void* p) {
    uint32_t a;
    asm("{ .reg .u64 t; cvta.to.shared.u64 t, %1; cvt.u32.u64 %0, t; }" : "=r"(a) : "l"(p));
    return a;
}
__device__ __forceinline__ void cp16(uint32_t saddr, const void* g) {
    asm volatile("cp.async.cg.shared.global [%0], [%1], 16;" :: "r"(saddr), "l"(g));
}
__device__ __forceinline__ void cp_commit() { asm volatile("cp.async.commit_group;" ::: "memory"); }
__device__ __forceinline__ void cp_wait0()  { asm volatile("cp.async.wait_group 0;"  ::: "memory"); }
__device__ __forceinline__ void cp_wait1()  { asm volatile("cp.async.wait_group 1;"  ::: "memory"); }

__device__ __forceinline__ void ldmx4(uint32_t* r, uint32_t addr) {
    asm volatile("ldmatrix.sync.aligned.m8n8.x4.shared.b16 {%0,%1,%2,%3}, [%4];"
                 : "=r"(r[0]), "=r"(r[1]), "=r"(r[2]), "=r"(r[3]) : "r"(addr));
}
__device__ __forceinline__ void ldmx4t(uint32_t* r, uint32_t addr) {
    asm volatile("ldmatrix.sync.aligned.m8n8.x4.trans.shared.b16 {%0,%1,%2,%3}, [%4];"
                 : "=r"(r[0]), "=r"(r[1]), "=r"(r[2]), "=r"(r[3]) : "r"(addr));
}
__device__ __forceinline__ void mma16816h(float* d, const uint32_t* a, const uint32_t* b) {
    asm volatile(
        "mma.sync.aligned.m16n8k16.row.col.f32.f16.f16.f32 "
        "{%0,%1,%2,%3}, {%4,%5,%6,%7}, {%8,%9}, {%0,%1,%2,%3};"
        : "+f"(d[0]), "+f"(d[1]), "+f"(d[2]), "+f"(d[3])
        : "r"(a[0]), "r"(a[1]), "r"(a[2]), "r"(a[3]), "r"(b[0]), "r"(b[1]));
}
__device__ __forceinline__ float ex2(float x) {
    float y; asm("ex2.approx.f32 %0, %1;" : "=f"(y) : "f"(x)); return y;
}
__device__ __forceinline__ uint32_t pkh(float a, float b) {
    __half2 t = __floats2half2_rn(a, b);
    return *(uint32_t*)&t;
}

/* ---------------- prep kernels ---------------- */
__global__ __launch_bounds__(256) void convx_kernel(const float* __restrict__ src, int n4) {
    int i = blockIdx.x * blockDim.x + threadIdx.x;
    if (i >= n4) return;
    float4 v = ((const float4*)src)[i];
    __half h[4] = { __float2half_rn(v.x), __float2half_rn(v.y),
                    __float2half_rn(v.z), __float2half_rn(v.w) };
    ((uint2*)g_x)[i] = *(uint2*)h;
}

__global__ __launch_bounds__(256) void tconv_qkv_kernel(const float* __restrict__ Wq,
                                                        const float* __restrict__ Wk,
                                                        const float* __restrict__ Wv) {
    __shared__ float t[32][33];
    int np = blockIdx.x * 32;
    int k0 = blockIdx.y * 32;
    const float* W;
    int N, off;
    if (np < QDIM)              { W = Wq; N = QDIM;  off = 0; }
    else if (np < QDIM + KVDIM) { W = Wk; N = KVDIM; off = QDIM; }
    else                        { W = Wv; N = KVDIM; off = QDIM + KVDIM; }
    int n0 = np - off;
    int tx = threadIdx.x, ty = threadIdx.y;
#pragma unroll
    for (int i = 0; i < 32; i += 8)
        t[ty + i][tx] = W[(size_t)(k0 + ty + i) * N + n0 + tx];
    __syncthreads();
#pragma unroll
    for (int i = 0; i < 32; i += 8)
        g_wb[(size_t)(np + ty + i) * D_MODEL + k0 + tx] = __float2half_rn(t[tx][ty + i]);
}

__global__ __launch_bounds__(256) void tconv_wo_kernel(const float* __restrict__ W) {
    __shared__ float t[32][33];
    int n0 = blockIdx.x * 32, k0 = blockIdx.y * 32;
    int tx = threadIdx.x, ty = threadIdx.y;
#pragma unroll
    for (int i = 0; i < 32; i += 8)
        t[ty + i][tx] = W[(size_t)(k0 + ty + i) * D_MODEL + n0 + tx];
    __syncthreads();
#pragma unroll
    for (int i = 0; i < 32; i += 8)
        g_wo[(size_t)(n0 + ty + i) * QDIM + k0 + tx] = __float2half_rn(t[tx][ty + i]);
}

/* ---------------- RoPE table (fp32) ---------------- */
__global__ void rope_table_kernel() {
    int i = blockIdx.x * blockDim.x + threadIdx.x;
    if (i >= SEQ * (HD/2)) return;
    int t = i >> 5;
    int j = i & 31;
    float ex = (float)j * (1.0f / 32.0f);
    float inv = powf(ROPE_BASE, -ex);
    float ang = (float)t * inv;
    float s, c;
    sincosf(ang, &s, &c);
    g_cos[i] = c;
    g_sin[i] = s;
}

/* ---------------- single-fp16 GEMM mainloop macro ---------------- */
#define TILE_B   10240
#define STAGE_B  (2*TILE_B)
#define GEMM_SMEM (2*STAGE_B)     /* 40960 */

#define GEMM_MAIN(Ap, Bp, Kdim)                                                   \
    extern __shared__ char smem[];                                                \
    uint32_t sb = smem_u32(smem);                                                 \
    int tid = threadIdx.x, lane = tid & 31, wid = tid >> 5;                       \
    int wm = wid & 1, wn = wid >> 1;                                              \
    int bm = blockIdx.y * 128, bn = blockIdx.x * 128;                             \
    int lr = tid >> 2;                                                            \
    int lc = tid & 3;                                                             \
    const __half* gA1 = (Ap) + (size_t)(bm + lr) * (Kdim) + lc * 8;               \
    const __half* gB1 = (Bp) + (size_t)(bn + lr) * (Kdim) + lc * 8;               \
    size_t rstep = (size_t)32 * (Kdim);                                           \
    uint32_t soff = lr * 80 + lc * 16;                                            \
    float acc[4][8][4];                                                           \
    _Pragma("unroll")                                                             \
    for (int i = 0; i < 4; i++)                                                   \
        _Pragma("unroll")                                                         \
        for (int j = 0; j < 8; j++)                                               \
            _Pragma("unroll")                                                     \
            for (int t = 0; t < 4; t++) acc[i][j][t] = 0.f;                       \
    int nkt = (Kdim) >> 5;                                                        \
    {                                                                             \
        _Pragma("unroll")                                                         \
        for (int r = 0; r < 4; r++) {                                             \
            uint32_t so = sb + soff + r * 2560;                                   \
            cp16(so,          gA1 + r * rstep);                                   \
            cp16(so + TILE_B, gB1 + r * rstep);                                   \
        }                                                                         \
    }                                                                             \
    cp_commit(); cp_wait0(); __syncthreads();                                     \
    uint32_t aBase = 2 * ((uint32_t)(wm * 64 + (lane & 15)) * 40 + ((lane >> 4) << 3)); \
    uint32_t bBase = 2 * ((uint32_t)(wn * 64 + (lane & 7) + ((lane >> 4) << 3)) * 40 + (lane & 8)); \
    for (int kt = 0; kt < nkt; kt++) {                                            \
        if (kt + 1 < nkt) {                                                       \
            int koff = (kt + 1) << 5;                                             \
            uint32_t st = sb + ((kt + 1) & 1) * STAGE_B;                          \
            _Pragma("unroll")                                                     \
            for (int r = 0; r < 4; r++) {                                         \
                uint32_t so = st + soff + r * 2560;                               \
                cp16(so,          gA1 + r * rstep + koff);                        \
                cp16(so + TILE_B, gB1 + r * rstep + koff);                        \
            }                                                                     \
        }                                                                         \
        cp_commit();                                                              \
        uint32_t base = sb + (kt & 1) * STAGE_B;                                  \
        _Pragma("unroll")                                                         \
        for (int kb = 0; kb < 32; kb += 16) {                                     \
            uint32_t af[4][4], bf[4][4];                                          \
            _Pragma("unroll")                                                     \
            for (int mt = 0; mt < 4; mt++)                                        \
                ldmx4(af[mt], base + aBase + 2 * (mt * 16 * 40 + kb));            \
            _Pragma("unroll")                                                     \
            for (int g = 0; g < 4; g++)                                           \
                ldmx4(bf[g], base + TILE_B + bBase + 2 * (g * 16 * 40 + kb));     \
            _Pragma("unroll")                                                     \
            for (int mt = 0; mt < 4; mt++)                                        \
                _Pragma("unroll")                                                 \
                for (int nt = 0; nt < 8; nt++)                                    \
                    mma16816h(acc[mt][nt], af[mt], &bf[nt >> 1][(nt & 1) * 2]);   \
        }                                                                         \
        cp_wait0();                                                               \
        __syncthreads();                                                          \
    }

/* ---------------- Wo GEMM ---------------- */
__global__ __launch_bounds__(128, 2)
void hmma_gemm_wo(float* __restrict__ C) {
    GEMM_MAIN(g_ao, g_wo, QDIM)
    int er = lane >> 2, ec = (lane & 3) * 2;
#pragma unroll
    for (int mt = 0; mt < 4; mt++)
#pragma unroll
        for (int nt = 0; nt < 8; nt++) {
            int row = bm + wm * 64 + mt * 16 + er;
            int col = bn + wn * 64 + nt * 8 + ec;
            *(float2*)(C + (size_t)row * D_MODEL + col) =
                make_float2(acc[mt][nt][0], acc[mt][nt][1]);
            *(float2*)(C + (size_t)(row + 8) * D_MODEL + col) =
                make_float2(acc[mt][nt][2], acc[mt][nt][3]);
        }
}

/* ---------------- QKV GEMM with fused RoPE + fp16 epilogue -------------- */
__global__ __launch_bounds__(128, 2)
void hmma_gemm_qkv() {
    GEMM_MAIN(g_x, g_wb, D_MODEL)
    int er = lane >> 2, ec = (lane & 3) * 2;
    int head = (bn + wn * 64) >> 6;           /* 0..47 */
    if (head < N_HEADS + N_KV) {
        bool isq = head < N_HEADS;
        int dim  = isq ? QDIM : KVDIM;
        int hcol = (isq ? head : head - N_HEADS) * HD;
        __half* dst = isq ? g_qf : g_kf;
#pragma unroll
        for (int mt = 0; mt < 4; mt++) {
            int row = bm + wm * 64 + mt * 16 + er;
#pragma unroll
            for (int hr = 0; hr < 2; hr++) {
                int tok = row + hr * 8;
                int s = tok & (SEQ - 1);
                int e0 = hr * 2;
#pragma unroll
                for (int nt = 0; nt < 4; nt++) {
                    int j = nt * 8 + ec;
                    float c0 = g_cos[s*32 + j],   c1 = g_cos[s*32 + j + 1];
                    float n0 = g_sin[s*32 + j],   n1 = g_sin[s*32 + j + 1];
                    float x1a = acc[mt][nt][e0],     x1b = acc[mt][nt][e0+1];
                    float x2a = acc[mt][nt+4][e0],   x2b = acc[mt][nt+4][e0+1];
                    size_t o1 = (size_t)tok * dim + hcol + j;
                    *(uint32_t*)(dst + o1)      = pkh(x1a*c0 - x2a*n0, x1b*c1 - x2b*n1);
                    *(uint32_t*)(dst + o1 + 32) = pkh(x2a*c0 + x1a*n0, x2b*c1 + x1b*n1);
                }
            }
        }
    } else {
        int hcol = (head - N_HEADS - N_KV) * HD;
#pragma unroll
        for (int mt = 0; mt < 4; mt++) {
            int row = bm + wm * 64 + mt * 16 + er;
#pragma unroll
            for (int nt = 0; nt < 8; nt++) {
                int jj = nt * 8 + ec;
                *(uint32_t*)(g_vf + (size_t)row * KVDIM + hcol + jj) =
                    pkh(acc[mt][nt][0], acc[mt][nt][1]);
                *(uint32_t*)(g_vf + (size_t)(row + 8) * KVDIM + hcol + jj) =
                    pkh(acc[mt][nt][2], acc[mt][nt][3]);
            }
        }
    }
}

/* ---------------- fp16 flash attention, double-buffered KV --------------
 * stage = K(9216) | V(9216); two stages ping-pong.
 */
#define AST 18432
#define ATTN_SMEM (2*AST)

__global__ __launch_bounds__(256)
void attn_kernel(const int* __restrict__ cu) {
    extern __shared__ char smem[];
    uint32_t sb = smem_u32(smem);
    int qb = blockIdx.x, h = blockIdx.y, b = blockIdx.z;
    int kvh = h >> 2;
    int tid = threadIdx.x, lane = tid & 31, wid = tid >> 5;
    int wq = wid & 3, wk = wid >> 2;

    int b0 = min(max(cu[b*4+0], 0), SEQ);
    int b1 = min(max(cu[b*4+1], 0), SEQ);
    int b2 = min(max(cu[b*4+2], 0), SEQ);
    int b3 = min(max(cu[b*4+3], 0), SEQ);

    int p0 = qb * 64;
    int s_start = 0;
    if (b0 <= p0) s_start = b0;
    if (b1 <= p0) s_start = max(s_start, b1);
    if (b2 <= p0) s_start = max(s_start, b2);
    if (b3 <= p0) s_start = max(s_start, b3);
    int kb0 = s_start >> 6;

    /* stage Q (64 x 64 fp16) into stage0, extract fragments */
#pragma unroll
    for (int i = 0; i < 2; i++) {
        int rem = tid + i * 256;
        int row = rem >> 3, c = rem & 7;
        cp16(sb + row*144 + c*16,
             g_qf + (size_t)(b*SEQ + p0 + row) * QDIM + h*HD + c*8);
    }
    cp_commit(); cp_wait0(); __syncthreads();

    uint32_t qh[4][4];
#pragma unroll
    for (int kt = 0; kt < 4; kt++) {
        uint32_t off = (uint32_t)(wq*16 + (lane & 15)) * 144 + (kt*16 + ((lane >> 4) << 3)) * 2;
        ldmx4(qh[kt], sb + off);
    }
    __syncthreads();   /* Q fragments extracted; smem reusable */

    int qp0 = p0 + wq*16 + (lane >> 2);
    int qp1 = qp0 + 8;
    int qsg0 = (b0 <= qp0) + (b1 <= qp0) + (b2 <= qp0) + (b3 <= qp0);
    int qsg1 = (b0 <= qp1) + (b1 <= qp1) + (b2 <= qp1) + (b3 <= qp1);

    float m0 = -INFINITY, m1 = -INFINITY, l0 = 0.f, l1 = 0.f;
    float o[8][4];
#pragma unroll
    for (int nd = 0; nd < 8; nd++)
#pragma unroll
        for (int j = 0; j < 4; j++) o[nd][j] = 0.f;

    int colb = wk*32 + (lane & 3)*2;

#define LOADKV(stb, kb_)                                                          \
    do {                                                                          \
        _Pragma("unroll")                                                         \
        for (int i_ = 0; i_ < 4; i_++) {                                          \
            int arr_ = i_ >> 1;                                                   \
            int rem_ = tid + (i_ & 1) * 256;                                      \
            int row_ = rem_ >> 3, c_ = rem_ & 7;                                  \
            const __half* src_ = arr_ ? g_vf : g_kf;                              \
            cp16((stb) + arr_*9216 + row_*144 + c_*16,                            \
                 src_ + (size_t)(b*SEQ + (kb_)*64 + row_) * KVDIM + kvh*HD + c_*8);\
        }                                                                         \
    } while (0)

    LOADKV(sb + (kb0 & 1) * AST, kb0);
    cp_commit();

    for (int kb = kb0; kb <= qb; kb++) {
        if (kb < qb) {
            LOADKV(sb + ((kb + 1) & 1) * AST, kb + 1);
            cp_commit();
            cp_wait1();
        } else {
            cp_wait0();
        }
        __syncthreads();
        uint32_t st = sb + (kb & 1) * AST;

        /* S = Q K^T */
        float s[4][4];
#pragma unroll
        for (int nt = 0; nt < 4; nt++)
#pragma unroll
            for (int j = 0; j < 4; j++) s[nt][j] = 0.f;

#pragma unroll
        for (int kt = 0; kt < 4; kt++) {
            uint32_t khf[2][4];
#pragma unroll
            for (int np = 0; np < 2; np++) {
                int mq = lane >> 3, r = lane & 7;
                uint32_t off = (uint32_t)(wk*32 + np*16 + ((mq & 2) ? 8 : 0) + r) * 144
                             + (kt*16 + ((mq & 1) ? 8 : 0)) * 2;
                ldmx4(khf[np], st + off);
            }
#pragma unroll
            for (int nt = 0; nt < 4; nt++)
                mma16816h(s[nt], qh[kt], &khf[nt >> 1][(nt & 1) * 2]);
        }

#pragma unroll
        for (int nt = 0; nt < 4; nt++)
#pragma unroll
            for (int j = 0; j < 4; j++) s[nt][j] *= SCALE_L2E;

#pragma unroll
        for (int nt = 0; nt < 4; nt++)
#pragma unroll
            for (int e = 0; e < 2; e++) {
                int kp = kb*64 + colb + nt*8 + e;
                int sk = (b0 <= kp) + (b1 <= kp) + (b2 <= kp) + (b3 <= kp);
                if (kp > qp0 || sk != qsg0) s[nt][e]     = -INFINITY;
                if (kp > qp1 || sk != qsg1) s[nt][2 + e] = -INFINITY;
            }

        float rm0 = -INFINITY, rm1 = -INFINITY;
#pragma unroll
        for (int nt = 0; nt < 4; nt++) {
            rm0 = fmaxf(rm0, fmaxf(s[nt][0], s[nt][1]));
            rm1 = fmaxf(rm1, fmaxf(s[nt][2], s[nt][3]));
        }
        rm0 = fmaxf(rm0, __shfl_xor_sync(0xffffffffu, rm0, 1));
        rm0 = fmaxf(rm0, __shfl_xor_sync(0xffffffffu, rm0, 2));
        rm1 = fmaxf(rm1, __shfl_xor_sync(0xffffffffu, rm1, 1));
        rm1 = fmaxf(rm1, __shfl_xor_sync(0xffffffffu, rm1, 2));
        float mn0 = fmaxf(m0, rm0), mn1 = fmaxf(m1, rm1);
        bool lv0 = mn0 > -INFINITY, lv1 = mn1 > -INFINITY;
        float sc0 = lv0 ? ((m0 > -INFINITY) ? ex2(m0 - mn0) : 0.f) : 1.f;
        float sc1 = lv1 ? ((m1 > -INFINITY) ? ex2(m1 - mn1) : 0.f) : 1.f;

        float p[4][4];
        float rs0 = 0.f, rs1 = 0.f;
#pragma unroll
        for (int nt = 0; nt < 4; nt++) {
#pragma unroll
            for (int e = 0; e < 2; e++) {
                float v0 = lv0 ? ex2(s[nt][e]     - mn0) : 0.f;
                float v1 = lv1 ? ex2(s[nt][2 + e] - mn1) : 0.f;
                p[nt][e] = v0;     rs0 += v0;
                p[nt][2+e] = v1;   rs1 += v1;
            }
        }
        rs0 += __shfl_xor_sync(0xffffffffu, rs0, 1);
        rs0 += __shfl_xor_sync(0xffffffffu, rs0, 2);
        rs1 += __shfl_xor_sync(0xffffffffu, rs1, 1);
        rs1 += __shfl_xor_sync(0xffffffffu, rs1, 2);
        l0 = l0 * sc0 + rs0;  m0 = mn0;
        l1 = l1 * sc1 + rs1;  m1 = mn1;
#pragma unroll
        for (int nd = 0; nd < 8; nd++) {
            o[nd][0] *= sc0; o[nd][1] *= sc0;
            o[nd][2] *= sc1; o[nd][3] *= sc1;
        }

        /* O += P V */
#pragma unroll
        for (int kt2 = 0; kt2 < 2; kt2++) {
            uint32_t pah[4] = { pkh(p[2*kt2][0],   p[2*kt2][1]),
                                pkh(p[2*kt2][2],   p[2*kt2][3]),
                                pkh(p[2*kt2+1][0], p[2*kt2+1][1]),
                                pkh(p[2*kt2+1][2], p[2*kt2+1][3]) };
#pragma unroll
            for (int ndp = 0; ndp < 4; ndp++) {
                int mq = lane >> 3, r = lane & 7;
                uint32_t off = (uint32_t)(wk*32 + kt2*16 + ((mq & 1) ? 8 : 0) + r) * 144
                             + (ndp*16 + ((mq & 2) ? 8 : 0)) * 2;
                uint32_t vh4[4];
                ldmx4t(vh4, st + 9216 + off);
#pragma unroll
                for (int q2 = 0; q2 < 2; q2++)
                    mma16816h(o[ndp*2 + q2], pah, &vh4[q2*2]);
            }
        }
        __syncthreads();   /* stage consumed before it is re-targeted */
    }
#undef LOADKV

    /* merge kv-halves via smem */
    float* Osm = (float*)smem;
    float* msm = (float*)(smem + 17408);
    float* lsm = (float*)(smem + 17664);
    int rl = wq*16 + (lane >> 2);
    int c2 = (lane & 3)*2;
    if (wk == 1) {
#pragma unroll
        for (int nd = 0; nd < 8; nd++) {
            *(float2*)&Osm[rl*68 + nd*8 + c2]     = make_float2(o[nd][0], o[nd][1]);
            *(float2*)&Osm[(rl+8)*68 + nd*8 + c2] = make_float2(o[nd][2], o[nd][3]);
        }
        if ((lane & 3) == 0) {
            msm[rl] = m0; msm[rl+8] = m1;
            lsm[rl] = l0; lsm[rl+8] = l1;
        }
    }
    __syncthreads();
    if (wk == 0) {
        float pm0 = msm[rl], pm1 = msm[rl+8];
        float pl0 = lsm[rl], pl1 = lsm[rl+8];
        float M0 = fmaxf(m0, pm0), M1 = fmaxf(m1, pm1);
        float sa0 = (m0  > -INFINITY) ? ex2(m0  - M0) : 0.f;
        float sb0 = (pm0 > -INFINITY) ? ex2(pm0 - M0) : 0.f;
        float sa1 = (m1  > -INFINITY) ? ex2(m1  - M1) : 0.f;
        float sb1 = (pm1 > -INFINITY) ? ex2(pm1 - M1) : 0.f;
        float inv0 = 1.f / (l0*sa0 + pl0*sb0);
        float inv1 = 1.f / (l1*sa1 + pl1*sb1);
        size_t r0g = (size_t)(b*SEQ + p0 + rl) * QDIM + h*HD;
        size_t r1g = (size_t)(b*SEQ + p0 + rl + 8) * QDIM + h*HD;
#pragma unroll
        for (int nd = 0; nd < 8; nd++) {
            float v0 = (o[nd][0]*sa0 + Osm[rl*68 + nd*8 + c2]*sb0) * inv0;
            float v1 = (o[nd][1]*sa0 + Osm[rl*68 + nd*8 + c2 + 1]*sb0) * inv0;
            float v2 = (o[nd][2]*sa1 + Osm[(rl+8)*68 + nd*8 + c2]*sb1) * inv1;
            float v3 = (o[nd][3]*sa1 + Osm[(rl+8)*68 + nd*8 + c2 + 1]*sb1) * inv1;
            *(uint32_t*)(g_ao + r0g + nd*8 + c2) = pkh(v0, v1);
            *(uint32_t*)(g_ao + r1g + nd*8 + c2) = pkh(v2, v3);
        }
    }
}

/* ------------------------------------------------------------------ */
extern "C" void kernel_launch(void* const* d_in, const int* in_sizes, int n_in,
                              void* d_out, int out_size) {
    const float* x  = (const float*)d_in[0];
    const int*   cu = (const int*)  d_in[1];
    const float* Wq = (const float*)d_in[2];
    const float* Wk = (const float*)d_in[3];
    const float* Wv = (const float*)d_in[4];
    const float* Wo = (const float*)d_in[5];
    float* out = (float*)d_out;

    cudaFuncSetAttribute(attn_kernel,
                         cudaFuncAttributeMaxDynamicSharedMemorySize, ATTN_SMEM);
    cudaFuncSetAttribute(hmma_gemm_wo,
                         cudaFuncAttributeMaxDynamicSharedMemorySize, GEMM_SMEM);
    cudaFuncSetAttribute(hmma_gemm_qkv,
                         cudaFuncAttributeMaxDynamicSharedMemorySize, GEMM_SMEM);

    /* prep */
    rope_table_kernel<<<(SEQ*(HD/2) + 255)/256, 256>>>();
    convx_kernel<<<(NTOK*D_MODEL/4 + 255)/256, 256>>>(x, NTOK*D_MODEL/4);
    tconv_qkv_kernel<<<dim3(QKVDIM/32, D_MODEL/32), dim3(32,8)>>>(Wq, Wk, Wv);
    tconv_wo_kernel<<<dim3(D_MODEL/32, QDIM/32), dim3(32,8)>>>(Wo);

    /* merged QKV projection with fused rope+fp16 epilogue */
    hmma_gemm_qkv<<<dim3(QKVDIM/128, NTOK/128), 128, GEMM_SMEM>>>();

    /* attention */
    attn_kernel<<<dim3(SEQ/64, N_HEADS, BATCH), 256, ATTN_SMEM>>>(cu);

    /* output projection */
    hmma_gemm_wo<<<dim3(D_MODEL/128, NTOK/128), 128, GEMM_SMEM>>>(out);
}